// round 2
// baseline (speedup 1.0000x reference)
#include <cuda_runtime.h>
#include <math.h>
#include <stdint.h>

#define NLAYER 24
#define NHEAD  16
#define DMODEL 1024
#define HDIM   64
#define VOCAB  50257
#define BATCH  2
#define SEQ    1024
#define BTOK   (BATCH*SEQ)      // 2048
#define FFDIM  4096
#define D3     (3*DMODEL)       // 3072

// -------- scratch (device globals; no allocation allowed) --------
__device__ float g_x  [BTOK*DMODEL];   // residual stream
__device__ float g_h  [BTOK*DMODEL];   // LN output
__device__ float g_qkv[BTOK*D3];       // qkv
__device__ float g_y  [BTOK*DMODEL];   // attention output
__device__ float g_ff [BTOK*FFDIM];    // MLP hidden

// ---------------------------------------------------------------
__device__ __forceinline__ float gelu_f(float x){
    float x3 = x*x*x;
    return 0.5f*x*(1.f + tanhf(0.7978845608028654f*(x + 0.044715f*x3)));
}

// -------- embedding: x = wte[idx] + wpe[t] ---------------------
__global__ __launch_bounds__(256) void embed_kernel(
    const int* __restrict__ idx, const float* __restrict__ wte,
    const float* __restrict__ wpe, float* __restrict__ x)
{
    int i = blockIdx.x*256 + threadIdx.x;          // float4 index
    int tok = i >> 8;                              // 256 float4 per row (D=1024)
    int c   = i & 255;
    int t   = tok & (SEQ-1);
    int id  = idx[tok];
    float4 a = ((const float4*)(wte + (size_t)id*DMODEL))[c];
    float4 p = ((const float4*)(wpe + (size_t)t*DMODEL))[c];
    a.x += p.x; a.y += p.y; a.z += p.z; a.w += p.w;
    ((float4*)x)[i] = a;
}

// -------- layernorm (one block per row, D=1024) ----------------
__global__ __launch_bounds__(256) void ln_kernel(
    const float* __restrict__ x, const float* __restrict__ w,
    const float* __restrict__ b, float* __restrict__ out)
{
    int row = blockIdx.x, tid = threadIdx.x;
    const float4* xr = (const float4*)(x + (size_t)row*DMODEL);
    float4 v = xr[tid];
    float s  = v.x+v.y+v.z+v.w;
    float sq = v.x*v.x+v.y*v.y+v.z*v.z+v.w*v.w;
    #pragma unroll
    for (int off=16; off>0; off>>=1){
        s  += __shfl_xor_sync(0xffffffffu, s,  off);
        sq += __shfl_xor_sync(0xffffffffu, sq, off);
    }
    __shared__ float ss[8], sqs[8];
    if ((tid&31)==0){ ss[tid>>5]=s; sqs[tid>>5]=sq; }
    __syncthreads();
    float st=0.f, sqt=0.f;
    #pragma unroll
    for (int i=0;i<8;i++){ st+=ss[i]; sqt+=sqs[i]; }
    float mean = st*(1.f/DMODEL);
    float var  = sqt*(1.f/DMODEL) - mean*mean;
    float inv  = rsqrtf(var + 1e-5f);
    float4 wv = ((const float4*)w)[tid];
    float4 bv = ((const float4*)b)[tid];
    float4 o;
    o.x = (v.x-mean)*inv*wv.x + bv.x;
    o.y = (v.y-mean)*inv*wv.y + bv.y;
    o.z = (v.z-mean)*inv*wv.z + bv.z;
    o.w = (v.w-mean)*inv*wv.w + bv.w;
    ((float4*)(out + (size_t)row*DMODEL))[tid] = o;
}

// -------- generic tiled fp32 GEMM 128x128x16 -------------------
// C[M,N] = act(A[M,K] @ B + bias) + res
// transB==0: B row-major [K,N];  transB==1: B row-major [N,K] (C = A @ B^T)
__global__ __launch_bounds__(256) void gemm_kernel(
    const float* __restrict__ A, const float* __restrict__ B,
    const float* __restrict__ bias, const float* __restrict__ res,
    float* __restrict__ C, int M, int N, int K, int transB, int act)
{
    __shared__ float As[16][132];
    __shared__ float Bs[16][128];
    const int bn = blockIdx.x*128, bm = blockIdx.y*128;
    const int tid = threadIdx.x;
    const int tx = tid & 15, ty = tid >> 4;
    float acc[8][8];
    #pragma unroll
    for (int i=0;i<8;i++)
        #pragma unroll
        for (int j=0;j<8;j++) acc[i][j]=0.f;

    const int ar = tid >> 2;         // 0..63
    const int ac = (tid & 3) << 2;   // 0,4,8,12

    for (int k0 = 0; k0 < K; k0 += 16) {
        // A tile (transposed store into [k][m])
        #pragma unroll
        for (int rr=0; rr<128; rr+=64) {
            float4 v = *(const float4*)(A + (size_t)(bm+ar+rr)*K + k0 + ac);
            As[ac+0][ar+rr]=v.x; As[ac+1][ar+rr]=v.y;
            As[ac+2][ar+rr]=v.z; As[ac+3][ar+rr]=v.w;
        }
        if (!transB) {
            int br = tid >> 5;            // 0..7
            int bc = (tid & 31) << 2;     // 0..124
            #pragma unroll
            for (int rr=0; rr<16; rr+=8) {
                float4 v = *(const float4*)(B + (size_t)(k0+br+rr)*N + bn + bc);
                *(float4*)&Bs[br+rr][bc] = v;
            }
        } else {
            #pragma unroll
            for (int rr=0; rr<128; rr+=64) {
                int gn = bn + ar + rr;
                float4 v = make_float4(0.f,0.f,0.f,0.f);
                if (gn < N) v = *(const float4*)(B + (size_t)gn*K + k0 + ac);
                Bs[ac+0][ar+rr]=v.x; Bs[ac+1][ar+rr]=v.y;
                Bs[ac+2][ar+rr]=v.z; Bs[ac+3][ar+rr]=v.w;
            }
        }
        __syncthreads();
        #pragma unroll
        for (int k=0;k<16;k++){
            float a[8], b[8];
            *(float4*)&a[0] = *(const float4*)&As[k][ty<<2];
            *(float4*)&a[4] = *(const float4*)&As[k][64 + (ty<<2)];
            *(float4*)&b[0] = *(const float4*)&Bs[k][tx<<2];
            *(float4*)&b[4] = *(const float4*)&Bs[k][64 + (tx<<2)];
            #pragma unroll
            for (int i=0;i<8;i++)
                #pragma unroll
                for (int j=0;j<8;j++)
                    acc[i][j] += a[i]*b[j];
        }
        __syncthreads();
    }
    #pragma unroll
    for (int i=0;i<8;i++){
        int m = bm + ((i<4) ? (ty<<2)+i : 64 + (ty<<2) + i-4);
        const float* resrow = res ? res + (size_t)m*N : nullptr;
        float*       crow   = C + (size_t)m*N;
        #pragma unroll
        for (int j=0;j<8;j++){
            int n = bn + ((j<4) ? (tx<<2)+j : 64 + (tx<<2) + j-4);
            if (n < N){
                float v = acc[i][j];
                if (bias) v += bias[n];
                if (act)  v = gelu_f(v);
                if (resrow) v += resrow[n];
                crow[n] = v;
            }
        }
    }
}

// -------- fused causal flash attention -------------------------
// grid (T/64, H, B), block 256.  Q tile 64, KV tile 32, HD=64.
__global__ __launch_bounds__(256) void attn_kernel(
    const float* __restrict__ qkv, float* __restrict__ y)
{
    __shared__ float Qs[64][65];
    __shared__ float Ks[32][65];
    __shared__ float Vs[32][65];
    __shared__ float Ps[64][33];
    const int qb = blockIdx.x, h = blockIdx.y, b = blockIdx.z;
    const int tid = threadIdx.x, tx = tid & 15, ty = tid >> 4;
    const int q0 = qb*64;
    const float* base = qkv + (size_t)b*SEQ*D3;

    // load Q tile (pre-scaled by 1/sqrt(HD))
    #pragma unroll
    for (int p=0;p<4;p++){
        int idx = tid + 256*p;
        int r = idx >> 4, c = (idx & 15) << 2;
        float4 v = *(const float4*)(base + (size_t)(q0+r)*D3 + h*HDIM + c);
        Qs[r][c+0]=v.x*0.125f; Qs[r][c+1]=v.y*0.125f;
        Qs[r][c+2]=v.z*0.125f; Qs[r][c+3]=v.w*0.125f;
    }

    float o[4][4], m[4], l[4];
    #pragma unroll
    for (int i=0;i<4;i++){
        m[i]=-1e30f; l[i]=0.f;
        #pragma unroll
        for (int j=0;j<4;j++) o[i][j]=0.f;
    }

    const int ntiles = 2*qb + 2;
    for (int kt=0; kt<ntiles; kt++){
        int ks = kt*32;
        __syncthreads();
        #pragma unroll
        for (int p=0;p<2;p++){
            int idx = tid + 256*p;
            int r = idx >> 4, c = (idx & 15) << 2;   // r in 0..31
            float4 kv = *(const float4*)(base + (size_t)(ks+r)*D3 + DMODEL   + h*HDIM + c);
            float4 vv = *(const float4*)(base + (size_t)(ks+r)*D3 + 2*DMODEL + h*HDIM + c);
            Ks[r][c+0]=kv.x; Ks[r][c+1]=kv.y; Ks[r][c+2]=kv.z; Ks[r][c+3]=kv.w;
            Vs[r][c+0]=vv.x; Vs[r][c+1]=vv.y; Vs[r][c+2]=vv.z; Vs[r][c+3]=vv.w;
        }
        __syncthreads();

        float s[4][2];
        #pragma unroll
        for (int i=0;i<4;i++){ s[i][0]=0.f; s[i][1]=0.f; }
        #pragma unroll 8
        for (int d=0; d<HDIM; d++){
            float a0 = Qs[ty][d],    a1 = Qs[ty+16][d];
            float a2 = Qs[ty+32][d], a3 = Qs[ty+48][d];
            float b0 = Ks[tx][d],    b1 = Ks[tx+16][d];
            s[0][0]+=a0*b0; s[0][1]+=a0*b1;
            s[1][0]+=a1*b0; s[1][1]+=a1*b1;
            s[2][0]+=a2*b0; s[2][1]+=a2*b1;
            s[3][0]+=a3*b0; s[3][1]+=a3*b1;
        }
        // causal mask
        #pragma unroll
        for (int i=0;i<4;i++){
            int qg = q0 + ty + 16*i;
            #pragma unroll
            for (int j=0;j<2;j++){
                int kg = ks + tx + 16*j;
                if (kg > qg) s[i][j] = -1e30f;
            }
        }
        // streaming softmax update
        #pragma unroll
        for (int i=0;i<4;i++){
            float pm = fmaxf(s[i][0], s[i][1]);
            #pragma unroll
            for (int off=8; off>0; off>>=1)
                pm = fmaxf(pm, __shfl_xor_sync(0xffffffffu, pm, off));
            float mnew  = fmaxf(m[i], pm);
            float alpha = __expf(m[i] - mnew);
            float p0 = __expf(s[i][0]-mnew);
            float p1 = __expf(s[i][1]-mnew);
            float rsum = p0 + p1;
            #pragma unroll
            for (int off=8; off>0; off>>=1)
                rsum += __shfl_xor_sync(0xffffffffu, rsum, off);
            l[i] = l[i]*alpha + rsum;
            m[i] = mnew;
            #pragma unroll
            for (int j=0;j<4;j++) o[i][j]*=alpha;
            Ps[ty+16*i][tx]    = p0;
            Ps[ty+16*i][tx+16] = p1;
        }
        __syncthreads();
        #pragma unroll 4
        for (int kk=0; kk<32; kk++){
            float p0=Ps[ty][kk],    p1=Ps[ty+16][kk];
            float p2=Ps[ty+32][kk], p3=Ps[ty+48][kk];
            float v0=Vs[kk][tx],    v1=Vs[kk][tx+16];
            float v2=Vs[kk][tx+32], v3=Vs[kk][tx+48];
            o[0][0]+=p0*v0; o[0][1]+=p0*v1; o[0][2]+=p0*v2; o[0][3]+=p0*v3;
            o[1][0]+=p1*v0; o[1][1]+=p1*v1; o[1][2]+=p1*v2; o[1][3]+=p1*v3;
            o[2][0]+=p2*v0; o[2][1]+=p2*v1; o[2][2]+=p2*v2; o[2][3]+=p2*v3;
            o[3][0]+=p3*v0; o[3][1]+=p3*v1; o[3][2]+=p3*v2; o[3][3]+=p3*v3;
        }
    }
    // finalize + write
    #pragma unroll
    for (int i=0;i<4;i++){
        float inv = 1.f/l[i];
        size_t row = (size_t)(b*SEQ + q0 + ty + 16*i);
        #pragma unroll
        for (int j=0;j<4;j++)
            y[row*DMODEL + h*HDIM + tx + 16*j] = o[i][j]*inv;
    }
}

// ---------------------------------------------------------------
extern "C" void kernel_launch(void* const* d_in, const int* in_sizes, int n_in,
                              void* d_out, int out_size)
{
    (void)in_sizes; (void)n_in; (void)out_size;
    const int*   idx        = (const int*)  d_in[0];
    const float* wte        = (const float*)d_in[1];
    const float* wpe        = (const float*)d_in[2];
    const float* ln1_w      = (const float*)d_in[3];
    const float* ln1_b      = (const float*)d_in[4];
    const float* attn_w     = (const float*)d_in[5];
    const float* attn_b     = (const float*)d_in[6];
    const float* attnproj_w = (const float*)d_in[7];
    const float* attnproj_b = (const float*)d_in[8];
    const float* ln2_w      = (const float*)d_in[9];
    const float* ln2_b      = (const float*)d_in[10];
    const float* fc_w       = (const float*)d_in[11];
    const float* fc_b       = (const float*)d_in[12];
    const float* proj_w     = (const float*)d_in[13];
    const float* proj_b     = (const float*)d_in[14];
    const float* lnf_w      = (const float*)d_in[15];
    const float* lnf_b      = (const float*)d_in[16];
    float* out = (float*)d_out;

    float *x, *h, *qkv, *y, *ff;
    cudaGetSymbolAddress((void**)&x,   g_x);
    cudaGetSymbolAddress((void**)&h,   g_h);
    cudaGetSymbolAddress((void**)&qkv, g_qkv);
    cudaGetSymbolAddress((void**)&y,   g_y);
    cudaGetSymbolAddress((void**)&ff,  g_ff);

    // embedding
    embed_kernel<<<BTOK*DMODEL/4/256, 256>>>(idx, wte, wpe, x);

    for (int l = 0; l < NLAYER; l++) {
        // ln1
        ln_kernel<<<BTOK, 256>>>(x, ln1_w + (size_t)l*DMODEL, ln1_b + (size_t)l*DMODEL, h);
        // qkv = h @ attn_w + attn_b
        gemm_kernel<<<dim3(D3/128, BTOK/128), 256>>>(
            h, attn_w + (size_t)l*DMODEL*D3, attn_b + (size_t)l*D3,
            nullptr, qkv, BTOK, D3, DMODEL, 0, 0);
        // attention
        attn_kernel<<<dim3(SEQ/64, NHEAD, BATCH), 256>>>(qkv, y);
        // x = x + y @ attnproj_w + attnproj_b
        gemm_kernel<<<dim3(DMODEL/128, BTOK/128), 256>>>(
            y, attnproj_w + (size_t)l*DMODEL*DMODEL, attnproj_b + (size_t)l*DMODEL,
            x, x, BTOK, DMODEL, DMODEL, 0, 0);
        // ln2
        ln_kernel<<<BTOK, 256>>>(x, ln2_w + (size_t)l*DMODEL, ln2_b + (size_t)l*DMODEL, h);
        // ff = gelu(h @ fc_w + fc_b)
        gemm_kernel<<<dim3(FFDIM/128, BTOK/128), 256>>>(
            h, fc_w + (size_t)l*DMODEL*FFDIM, fc_b + (size_t)l*FFDIM,
            nullptr, ff, BTOK, FFDIM, DMODEL, 0, 1);
        // x = x + ff @ proj_w + proj_b
        gemm_kernel<<<dim3(DMODEL/128, BTOK/128), 256>>>(
            ff, proj_w + (size_t)l*FFDIM*DMODEL, proj_b + (size_t)l*DMODEL,
            x, x, BTOK, DMODEL, FFDIM, 0, 0);
    }

    // final LN + tied LM head: logits = lnf(x) @ wte^T
    ln_kernel<<<BTOK, 256>>>(x, lnf_w, lnf_b, h);
    gemm_kernel<<<dim3((VOCAB + 127)/128, BTOK/128), 256>>>(
        h, wte, nullptr, nullptr, out, BTOK, VOCAB, DMODEL, 1, 0);
}

// round 3
// speedup vs baseline: 1.0086x; 1.0086x over previous
#include <cuda_runtime.h>
#include <math.h>
#include <stdint.h>

#define NLAYER 24
#define NHEAD  16
#define DMODEL 1024
#define HDIM   64
#define VOCAB  50257
#define BATCH  2
#define SEQ    1024
#define BTOK   (BATCH*SEQ)      // 2048
#define FFDIM  4096
#define D3     (3*DMODEL)       // 3072

// -------- scratch (device globals; no allocation allowed) --------
__device__ float g_x  [BTOK*DMODEL];   // residual stream
__device__ float g_h  [BTOK*DMODEL];   // LN output
__device__ float g_qkv[BTOK*D3];       // qkv
__device__ float g_y  [BTOK*DMODEL];   // attention output
__device__ float g_ff [BTOK*FFDIM];    // MLP hidden

// ---------------------------------------------------------------
__device__ __forceinline__ float gelu_f(float x){
    float x3 = x*x*x;
    return 0.5f*x*(1.f + tanhf(0.7978845608028654f*(x + 0.044715f*x3)));
}

// -------- embedding: x = wte[idx] + wpe[t] ---------------------
__global__ __launch_bounds__(256) void embed_kernel(
    const int* __restrict__ idx, const float* __restrict__ wte,
    const float* __restrict__ wpe, float* __restrict__ x)
{
    int i = blockIdx.x*256 + threadIdx.x;          // float4 index
    int tok = i >> 8;                              // 256 float4 per row (D=1024)
    int c   = i & 255;
    int t   = tok & (SEQ-1);
    int id  = idx[tok];
    float4 a = ((const float4*)(wte + (size_t)id*DMODEL))[c];
    float4 p = ((const float4*)(wpe + (size_t)t*DMODEL))[c];
    a.x += p.x; a.y += p.y; a.z += p.z; a.w += p.w;
    ((float4*)x)[i] = a;
}

// -------- layernorm (one block per row, D=1024) ----------------
__global__ __launch_bounds__(256) void ln_kernel(
    const float* __restrict__ x, const float* __restrict__ w,
    const float* __restrict__ b, float* __restrict__ out)
{
    int row = blockIdx.x, tid = threadIdx.x;
    const float4* xr = (const float4*)(x + (size_t)row*DMODEL);
    float4 v = xr[tid];
    float s  = v.x+v.y+v.z+v.w;
    float sq = v.x*v.x+v.y*v.y+v.z*v.z+v.w*v.w;
    #pragma unroll
    for (int off=16; off>0; off>>=1){
        s  += __shfl_xor_sync(0xffffffffu, s,  off);
        sq += __shfl_xor_sync(0xffffffffu, sq, off);
    }
    __shared__ float ss[8], sqs[8];
    if ((tid&31)==0){ ss[tid>>5]=s; sqs[tid>>5]=sq; }
    __syncthreads();
    float st=0.f, sqt=0.f;
    #pragma unroll
    for (int i=0;i<8;i++){ st+=ss[i]; sqt+=sqs[i]; }
    float mean = st*(1.f/DMODEL);
    float var  = sqt*(1.f/DMODEL) - mean*mean;
    float inv  = rsqrtf(var + 1e-5f);
    float4 wv = ((const float4*)w)[tid];
    float4 bv = ((const float4*)b)[tid];
    float4 o;
    o.x = (v.x-mean)*inv*wv.x + bv.x;
    o.y = (v.y-mean)*inv*wv.y + bv.y;
    o.z = (v.z-mean)*inv*wv.z + bv.z;
    o.w = (v.w-mean)*inv*wv.w + bv.w;
    ((float4*)(out + (size_t)row*DMODEL))[tid] = o;
}

// -------- generic tiled fp32 GEMM 128x128x16 -------------------
// C[M,N] = act(A[M,K] @ B + bias) + res
// transB==0: B row-major [K,N];  transB==1: B row-major [N,K] (C = A @ B^T)
__global__ __launch_bounds__(256) void gemm_kernel(
    const float* __restrict__ A, const float* __restrict__ B,
    const float* __restrict__ bias, const float* __restrict__ res,
    float* __restrict__ C, int M, int N, int K, int transB, int act)
{
    __shared__ float As[16][132];
    __shared__ float Bs[16][128];
    const int bn = blockIdx.x*128, bm = blockIdx.y*128;
    const int tid = threadIdx.x;
    const int tx = tid & 15, ty = tid >> 4;
    float acc[8][8];
    #pragma unroll
    for (int i=0;i<8;i++)
        #pragma unroll
        for (int j=0;j<8;j++) acc[i][j]=0.f;

    const int ar = tid >> 2;         // 0..63
    const int ac = (tid & 3) << 2;   // 0,4,8,12

    for (int k0 = 0; k0 < K; k0 += 16) {
        // A tile (transposed store into [k][m])
        #pragma unroll
        for (int rr=0; rr<128; rr+=64) {
            float4 v = *(const float4*)(A + (size_t)(bm+ar+rr)*K + k0 + ac);
            As[ac+0][ar+rr]=v.x; As[ac+1][ar+rr]=v.y;
            As[ac+2][ar+rr]=v.z; As[ac+3][ar+rr]=v.w;
        }
        if (!transB) {
            int br = tid >> 5;            // 0..7
            int bc = (tid & 31) << 2;     // 0..124
            #pragma unroll
            for (int rr=0; rr<16; rr+=8) {
                float4 v = *(const float4*)(B + (size_t)(k0+br+rr)*N + bn + bc);
                *(float4*)&Bs[br+rr][bc] = v;
            }
        } else {
            #pragma unroll
            for (int rr=0; rr<128; rr+=64) {
                int gn = bn + ar + rr;
                float4 v = make_float4(0.f,0.f,0.f,0.f);
                if (gn < N) v = *(const float4*)(B + (size_t)gn*K + k0 + ac);
                Bs[ac+0][ar+rr]=v.x; Bs[ac+1][ar+rr]=v.y;
                Bs[ac+2][ar+rr]=v.z; Bs[ac+3][ar+rr]=v.w;
            }
        }
        __syncthreads();
        #pragma unroll
        for (int k=0;k<16;k++){
            float a[8], b[8];
            *(float4*)&a[0] = *(const float4*)&As[k][ty<<2];
            *(float4*)&a[4] = *(const float4*)&As[k][64 + (ty<<2)];
            *(float4*)&b[0] = *(const float4*)&Bs[k][tx<<2];
            *(float4*)&b[4] = *(const float4*)&Bs[k][64 + (tx<<2)];
            #pragma unroll
            for (int i=0;i<8;i++)
                #pragma unroll
                for (int j=0;j<8;j++)
                    acc[i][j] += a[i]*b[j];
        }
        __syncthreads();
    }
    #pragma unroll
    for (int i=0;i<8;i++){
        int m = bm + ((i<4) ? (ty<<2)+i : 64 + (ty<<2) + i-4);
        const float* resrow = res ? res + (size_t)m*N : nullptr;
        float*       crow   = C + (size_t)m*N;
        #pragma unroll
        for (int j=0;j<8;j++){
            int n = bn + ((j<4) ? (tx<<2)+j : 64 + (tx<<2) + j-4);
            if (n < N){
                float v = acc[i][j];
                if (bias) v += bias[n];
                if (act)  v = gelu_f(v);
                if (resrow) v += resrow[n];
                crow[n] = v;
            }
        }
    }
}

// -------- fused causal flash attention -------------------------
// grid (T/64, H, B), block 256.  Q tile 64, KV tile 32, HD=64.
__global__ __launch_bounds__(256) void attn_kernel(
    const float* __restrict__ qkv, float* __restrict__ y)
{
    __shared__ float Qs[64][65];
    __shared__ float Ks[32][65];
    __shared__ float Vs[32][65];
    __shared__ float Ps[64][33];
    const int qb = blockIdx.x, h = blockIdx.y, b = blockIdx.z;
    const int tid = threadIdx.x, tx = tid & 15, ty = tid >> 4;
    const int q0 = qb*64;
    const float* base = qkv + (size_t)b*SEQ*D3;

    // load Q tile (pre-scaled by 1/sqrt(HD))
    #pragma unroll
    for (int p=0;p<4;p++){
        int idx = tid + 256*p;
        int r = idx >> 4, c = (idx & 15) << 2;
        float4 v = *(const float4*)(base + (size_t)(q0+r)*D3 + h*HDIM + c);
        Qs[r][c+0]=v.x*0.125f; Qs[r][c+1]=v.y*0.125f;
        Qs[r][c+2]=v.z*0.125f; Qs[r][c+3]=v.w*0.125f;
    }

    float o[4][4], m[4], l[4];
    #pragma unroll
    for (int i=0;i<4;i++){
        m[i]=-1e30f; l[i]=0.f;
        #pragma unroll
        for (int j=0;j<4;j++) o[i][j]=0.f;
    }

    const int ntiles = 2*qb + 2;
    for (int kt=0; kt<ntiles; kt++){
        int ks = kt*32;
        __syncthreads();
        #pragma unroll
        for (int p=0;p<2;p++){
            int idx = tid + 256*p;
            int r = idx >> 4, c = (idx & 15) << 2;   // r in 0..31
            float4 kv = *(const float4*)(base + (size_t)(ks+r)*D3 + DMODEL   + h*HDIM + c);
            float4 vv = *(const float4*)(base + (size_t)(ks+r)*D3 + 2*DMODEL + h*HDIM + c);
            Ks[r][c+0]=kv.x; Ks[r][c+1]=kv.y; Ks[r][c+2]=kv.z; Ks[r][c+3]=kv.w;
            Vs[r][c+0]=vv.x; Vs[r][c+1]=vv.y; Vs[r][c+2]=vv.z; Vs[r][c+3]=vv.w;
        }
        __syncthreads();

        float s[4][2];
        #pragma unroll
        for (int i=0;i<4;i++){ s[i][0]=0.f; s[i][1]=0.f; }
        #pragma unroll 8
        for (int d=0; d<HDIM; d++){
            float a0 = Qs[ty][d],    a1 = Qs[ty+16][d];
            float a2 = Qs[ty+32][d], a3 = Qs[ty+48][d];
            float b0 = Ks[tx][d],    b1 = Ks[tx+16][d];
            s[0][0]+=a0*b0; s[0][1]+=a0*b1;
            s[1][0]+=a1*b0; s[1][1]+=a1*b1;
            s[2][0]+=a2*b0; s[2][1]+=a2*b1;
            s[3][0]+=a3*b0; s[3][1]+=a3*b1;
        }
        // causal mask
        #pragma unroll
        for (int i=0;i<4;i++){
            int qg = q0 + ty + 16*i;
            #pragma unroll
            for (int j=0;j<2;j++){
                int kg = ks + tx + 16*j;
                if (kg > qg) s[i][j] = -1e30f;
            }
        }
        // streaming softmax update
        #pragma unroll
        for (int i=0;i<4;i++){
            float pm = fmaxf(s[i][0], s[i][1]);
            #pragma unroll
            for (int off=8; off>0; off>>=1)
                pm = fmaxf(pm, __shfl_xor_sync(0xffffffffu, pm, off));
            float mnew  = fmaxf(m[i], pm);
            float alpha = __expf(m[i] - mnew);
            float p0 = __expf(s[i][0]-mnew);
            float p1 = __expf(s[i][1]-mnew);
            float rsum = p0 + p1;
            #pragma unroll
            for (int off=8; off>0; off>>=1)
                rsum += __shfl_xor_sync(0xffffffffu, rsum, off);
            l[i] = l[i]*alpha + rsum;
            m[i] = mnew;
            #pragma unroll
            for (int j=0;j<4;j++) o[i][j]*=alpha;
            Ps[ty+16*i][tx]    = p0;
            Ps[ty+16*i][tx+16] = p1;
        }
        __syncthreads();
        #pragma unroll 4
        for (int kk=0; kk<32; kk++){
            float p0=Ps[ty][kk],    p1=Ps[ty+16][kk];
            float p2=Ps[ty+32][kk], p3=Ps[ty+48][kk];
            float v0=Vs[kk][tx],    v1=Vs[kk][tx+16];
            float v2=Vs[kk][tx+32], v3=Vs[kk][tx+48];
            o[0][0]+=p0*v0; o[0][1]+=p0*v1; o[0][2]+=p0*v2; o[0][3]+=p0*v3;
            o[1][0]+=p1*v0; o[1][1]+=p1*v1; o[1][2]+=p1*v2; o[1][3]+=p1*v3;
            o[2][0]+=p2*v0; o[2][1]+=p2*v1; o[2][2]+=p2*v2; o[2][3]+=p2*v3;
            o[3][0]+=p3*v0; o[3][1]+=p3*v1; o[3][2]+=p3*v2; o[3][3]+=p3*v3;
        }
    }
    // finalize + write
    #pragma unroll
    for (int i=0;i<4;i++){
        float inv = 1.f/l[i];
        size_t row = (size_t)(b*SEQ + q0 + ty + 16*i);
        #pragma unroll
        for (int j=0;j<4;j++)
            y[row*DMODEL + h*HDIM + tx + 16*j] = o[i][j]*inv;
    }
}

// ---------------------------------------------------------------
extern "C" void kernel_launch(void* const* d_in, const int* in_sizes, int n_in,
                              void* d_out, int out_size)
{
    (void)in_sizes; (void)n_in; (void)out_size;
    const int*   idx        = (const int*)  d_in[0];
    const float* wte        = (const float*)d_in[1];
    const float* wpe        = (const float*)d_in[2];
    const float* ln1_w      = (const float*)d_in[3];
    const float* ln1_b      = (const float*)d_in[4];
    const float* attn_w     = (const float*)d_in[5];
    const float* attn_b     = (const float*)d_in[6];
    const float* attnproj_w = (const float*)d_in[7];
    const float* attnproj_b = (const float*)d_in[8];
    const float* ln2_w      = (const float*)d_in[9];
    const float* ln2_b      = (const float*)d_in[10];
    const float* fc_w       = (const float*)d_in[11];
    const float* fc_b       = (const float*)d_in[12];
    const float* proj_w     = (const float*)d_in[13];
    const float* proj_b     = (const float*)d_in[14];
    const float* lnf_w      = (const float*)d_in[15];
    const float* lnf_b      = (const float*)d_in[16];
    float* out = (float*)d_out;

    float *x, *h, *qkv, *y, *ff;
    cudaGetSymbolAddress((void**)&x,   g_x);
    cudaGetSymbolAddress((void**)&h,   g_h);
    cudaGetSymbolAddress((void**)&qkv, g_qkv);
    cudaGetSymbolAddress((void**)&y,   g_y);
    cudaGetSymbolAddress((void**)&ff,  g_ff);

    // embedding
    embed_kernel<<<BTOK*DMODEL/4/256, 256>>>(idx, wte, wpe, x);

    for (int l = 0; l < NLAYER; l++) {
        // ln1
        ln_kernel<<<BTOK, 256>>>(x, ln1_w + (size_t)l*DMODEL, ln1_b + (size_t)l*DMODEL, h);
        // qkv = h @ attn_w + attn_b
        gemm_kernel<<<dim3(D3/128, BTOK/128), 256>>>(
            h, attn_w + (size_t)l*DMODEL*D3, attn_b + (size_t)l*D3,
            nullptr, qkv, BTOK, D3, DMODEL, 0, 0);
        // attention
        attn_kernel<<<dim3(SEQ/64, NHEAD, BATCH), 256>>>(qkv, y);
        // x = x + y @ attnproj_w + attnproj_b
        gemm_kernel<<<dim3(DMODEL/128, BTOK/128), 256>>>(
            y, attnproj_w + (size_t)l*DMODEL*DMODEL, attnproj_b + (size_t)l*DMODEL,
            x, x, BTOK, DMODEL, DMODEL, 0, 0);
        // ln2
        ln_kernel<<<BTOK, 256>>>(x, ln2_w + (size_t)l*DMODEL, ln2_b + (size_t)l*DMODEL, h);
        // ff = gelu(h @ fc_w + fc_b)
        gemm_kernel<<<dim3(FFDIM/128, BTOK/128), 256>>>(
            h, fc_w + (size_t)l*DMODEL*FFDIM, fc_b + (size_t)l*FFDIM,
            nullptr, ff, BTOK, FFDIM, DMODEL, 0, 1);
        // x = x + ff @ proj_w + proj_b
        gemm_kernel<<<dim3(DMODEL/128, BTOK/128), 256>>>(
            ff, proj_w + (size_t)l*FFDIM*DMODEL, proj_b + (size_t)l*DMODEL,
            x, x, BTOK, DMODEL, FFDIM, 0, 0);
    }

    // final LN + tied LM head: logits = lnf(x) @ wte^T
    ln_kernel<<<BTOK, 256>>>(x, lnf_w, lnf_b, h);
    gemm_kernel<<<dim3((VOCAB + 127)/128, BTOK/128), 256>>>(
        h, wte, nullptr, nullptr, out, BTOK, VOCAB, DMODEL, 1, 0);
}

// round 5
// speedup vs baseline: 1.6393x; 1.6253x over previous
#include <cuda_runtime.h>
#include <cuda_bf16.h>
#include <math.h>
#include <stdint.h>

#define NLAYER 24
#define NHEAD  16
#define DMODEL 1024
#define HDIM   64
#define VOCAB  50257
#define BATCH  2
#define SEQ    1024
#define BTOK   (BATCH*SEQ)
#define FFDIM  4096
#define D3     (3*DMODEL)

__device__ float g_x  [BTOK*DMODEL];
__device__ float g_qkv[BTOK*D3];
__device__ __nv_bfloat16 g_h_hi [BTOK*DMODEL], g_h_lo [BTOK*DMODEL];
__device__ __nv_bfloat16 g_y_hi [BTOK*DMODEL], g_y_lo [BTOK*DMODEL];
__device__ __nv_bfloat16 g_ff_hi[BTOK*FFDIM],  g_ff_lo[BTOK*FFDIM];
__device__ __nv_bfloat16 g_wq_hi[(size_t)NLAYER*DMODEL*D3],     g_wq_lo[(size_t)NLAYER*DMODEL*D3];
__device__ __nv_bfloat16 g_wa_hi[(size_t)NLAYER*DMODEL*DMODEL], g_wa_lo[(size_t)NLAYER*DMODEL*DMODEL];
__device__ __nv_bfloat16 g_wf_hi[(size_t)NLAYER*DMODEL*FFDIM],  g_wf_lo[(size_t)NLAYER*DMODEL*FFDIM];
__device__ __nv_bfloat16 g_wp_hi[(size_t)NLAYER*FFDIM*DMODEL],  g_wp_lo[(size_t)NLAYER*FFDIM*DMODEL];
__device__ __nv_bfloat16 g_we_hi[(size_t)VOCAB*DMODEL],         g_we_lo[(size_t)VOCAB*DMODEL];

__device__ __forceinline__ uint32_t smem_u32(const void* p){
    uint32_t a;
    asm("{ .reg .u64 t; cvta.to.shared.u64 t, %1; cvt.u32.u64 %0, t; }" : "=r"(a) : "l"(p));
    return a;
}
#define LDSM4(r0,r1,r2,r3,a) asm volatile("ldmatrix.sync.aligned.m8n8.x4.shared.b16 {%0,%1,%2,%3},[%4];":"=r"(r0),"=r"(r1),"=r"(r2),"=r"(r3):"r"(a))
#define LDSM2(r0,r1,a)       asm volatile("ldmatrix.sync.aligned.m8n8.x2.shared.b16 {%0,%1},[%2];":"=r"(r0),"=r"(r1):"r"(a))
#define MMA16816(c,a,b) asm volatile( \
    "mma.sync.aligned.m16n8k16.row.col.f32.bf16.bf16.f32 {%0,%1,%2,%3},{%4,%5,%6,%7},{%8,%9},{%0,%1,%2,%3};" \
    :"+f"((c)[0]),"+f"((c)[1]),"+f"((c)[2]),"+f"((c)[3]) \
    :"r"((a)[0]),"r"((a)[1]),"r"((a)[2]),"r"((a)[3]),"r"((b)[0]),"r"((b)[1]))

__device__ __forceinline__ float gelu_f(float x){
    float x3=x*x*x;
    return 0.5f*x*(1.f+tanhf(0.7978845608028654f*(x+0.044715f*x3)));
}
__device__ __forceinline__ void split2(float v, __nv_bfloat16&h, __nv_bfloat16&l){
    h=__float2bfloat16(v); l=__float2bfloat16(v-__bfloat162float(h));
}
__device__ __forceinline__ uint32_t pack2(__nv_bfloat16 a, __nv_bfloat16 b){
    return ((uint32_t)__bfloat16_as_ushort(b)<<16)|__bfloat16_as_ushort(a);
}

__global__ __launch_bounds__(256) void embed_kernel(
    const int* __restrict__ idx, const float* __restrict__ wte,
    const float* __restrict__ wpe, float* __restrict__ x)
{
    int i=blockIdx.x*256+threadIdx.x, tok=i>>8, c=i&255, t=tok&(SEQ-1);
    int id=idx[tok];
    float4 a=((const float4*)(wte+(size_t)id*DMODEL))[c];
    float4 p=((const float4*)(wpe+(size_t)t*DMODEL))[c];
    a.x+=p.x; a.y+=p.y; a.z+=p.z; a.w+=p.w;
    ((float4*)x)[i]=a;
}

__global__ __launch_bounds__(256) void ln_kernel(
    const float* __restrict__ x, const float* __restrict__ w, const float* __restrict__ b,
    __nv_bfloat16* __restrict__ ohi, __nv_bfloat16* __restrict__ olo)
{
    int row=blockIdx.x, tid=threadIdx.x;
    float4 v=((const float4*)(x+(size_t)row*DMODEL))[tid];
    float s=v.x+v.y+v.z+v.w, sq=v.x*v.x+v.y*v.y+v.z*v.z+v.w*v.w;
    #pragma unroll
    for(int o=16;o>0;o>>=1){ s+=__shfl_xor_sync(~0u,s,o); sq+=__shfl_xor_sync(~0u,sq,o); }
    __shared__ float ss[8],sqs[8];
    if((tid&31)==0){ ss[tid>>5]=s; sqs[tid>>5]=sq; }
    __syncthreads();
    float st=0,sqt=0;
    #pragma unroll
    for(int i=0;i<8;i++){ st+=ss[i]; sqt+=sqs[i]; }
    float mean=st*(1.f/DMODEL), var=sqt*(1.f/DMODEL)-mean*mean, inv=rsqrtf(var+1e-5f);
    float4 wv=((const float4*)w)[tid], bv=((const float4*)b)[tid];
    float o0=(v.x-mean)*inv*wv.x+bv.x, o1=(v.y-mean)*inv*wv.y+bv.y;
    float o2=(v.z-mean)*inv*wv.z+bv.z, o3=(v.w-mean)*inv*wv.w+bv.w;
    __nv_bfloat16 h0,h1,h2,h3,l0,l1,l2,l3;
    split2(o0,h0,l0); split2(o1,h1,l1); split2(o2,h2,l2); split2(o3,h3,l3);
    size_t base=(size_t)row*DMODEL+tid*4;
    *(uint2*)(ohi+base)=make_uint2(pack2(h0,h1),pack2(h2,h3));
    *(uint2*)(olo+base)=make_uint2(pack2(l0,l1),pack2(l2,l3));
}

// W[K][N] (layer l) -> hi/lo [N][K]
__global__ void wsplit_t(const float* __restrict__ W, __nv_bfloat16* __restrict__ hi,
                         __nv_bfloat16* __restrict__ lo, int K, int N)
{
    __shared__ float t[32][33];
    int l=blockIdx.z;
    const float* Wl=W+(size_t)l*K*N;
    __nv_bfloat16* hil=hi+(size_t)l*K*N;
    __nv_bfloat16* lol=lo+(size_t)l*K*N;
    int n0=blockIdx.x*32, k0=blockIdx.y*32, tx=threadIdx.x, ty=threadIdx.y;
    #pragma unroll
    for(int i=0;i<4;i++) t[ty+8*i][tx]=Wl[(size_t)(k0+ty+8*i)*N+n0+tx];
    __syncthreads();
    #pragma unroll
    for(int i=0;i<4;i++){
        float v=t[tx][ty+8*i];
        __nv_bfloat16 h,lw; split2(v,h,lw);
        size_t o=(size_t)(n0+ty+8*i)*K+k0+tx;
        hil[o]=h; lol[o]=lw;
    }
}

__global__ __launch_bounds__(256) void wte_split(
    const float* __restrict__ w, __nv_bfloat16* __restrict__ hi, __nv_bfloat16* __restrict__ lo)
{
    size_t base=(size_t)blockIdx.x*DMODEL+threadIdx.x*4;
    float4 v=*(const float4*)(w+base);
    __nv_bfloat16 h,l;
    split2(v.x,h,l); hi[base]=h;   lo[base]=l;
    split2(v.y,h,l); hi[base+1]=h; lo[base+1]=l;
    split2(v.z,h,l); hi[base+2]=h; lo[base+2]=l;
    split2(v.w,h,l); hi[base+3]=h; lo[base+3]=l;
}

// ---- mma.sync bf16x3 GEMM: C[128-tile] = A[M,K] * B[N,K]^T --------------
// act 0: +bias->f32  1: +bias+res->f32  2: +bias,gelu->split bf16  3: plain guarded ->f32
#define AST 40
#define BUFB (128*AST*2)
__global__ __launch_bounds__(256) void gemm_mma(
    const __nv_bfloat16* __restrict__ Ahi, const __nv_bfloat16* __restrict__ Alo,
    const __nv_bfloat16* __restrict__ Bhi, const __nv_bfloat16* __restrict__ Blo,
    const float* __restrict__ bias, const float* __restrict__ res,
    float* __restrict__ Cf, __nv_bfloat16* __restrict__ Chi, __nv_bfloat16* __restrict__ Clo,
    int N, int K, int act)
{
    __shared__ __nv_bfloat16 As[2][128*AST];
    __shared__ __nv_bfloat16 Bs[2][128*AST];
    const int tid=threadIdx.x, wid=tid>>5, lane=tid&31;
    const int bn=blockIdx.x*128, bm=blockIdx.y*128;
    const int wm=(wid&3)*32, wn=(wid>>2)*64;
    const int row=tid>>2, ch=tid&3;

    float acc[2][8][4];
    #pragma unroll
    for(int i=0;i<2;i++)
        #pragma unroll
        for(int j=0;j<8;j++)
            #pragma unroll
            for(int k=0;k<4;k++) acc[i][j][k]=0.f;

    const uint32_t a_base = smem_u32(&As[0][0]) + (uint32_t)(((wm+(lane&15))*AST + (lane>>4)*8)*2);
    const uint32_t b_base = smem_u32(&Bs[0][0]) + (uint32_t)(((wn+(lane&7))*AST + ((lane>>3)&1)*8)*2);
    const uint32_t sa = smem_u32(&As[0][0]) + (uint32_t)((row*AST+ch*8)*2);
    const uint32_t sbp= smem_u32(&Bs[0][0]) + (uint32_t)((row*AST+ch*8)*2);

    const int KS=K>>5, S=3*KS;
    uint4 pa0,pa1,pb0,pb1;

    // load stage 0 into buffer 0
    {
        const __nv_bfloat16* Ap=Ahi; const __nv_bfloat16* Bp=Bhi;
        pa0=*(const uint4*)(Ap+(size_t)(bm+row)*K+ch*8);
        pa1=*(const uint4*)(Ap+(size_t)(bm+row+64)*K+ch*8);
        int g0=bn+row, g1=bn+row+64;
        pb0 = (g0<N)? *(const uint4*)(Bp+(size_t)g0*K+ch*8) : make_uint4(0,0,0,0);
        pb1 = (g1<N)? *(const uint4*)(Bp+(size_t)g1*K+ch*8) : make_uint4(0,0,0,0);
        *(uint4*)(As[0]+row*AST+ch*8)=pa0;
        *(uint4*)(As[0]+(row+64)*AST+ch*8)=pa1;
        *(uint4*)(Bs[0]+row*AST+ch*8)=pb0;
        *(uint4*)(Bs[0]+(row+64)*AST+ch*8)=pb1;
    }
    __syncthreads();

    for(int s=0;s<S;s++){
        const int buf=s&1;
        if(s+1<S){
            int sn=s+1, pass=sn/KS, slab=sn-pass*KS;
            const __nv_bfloat16* Ap=(pass==2)?Alo:Ahi;
            const __nv_bfloat16* Bp=(pass==1)?Blo:Bhi;
            size_t kk=(size_t)slab<<5;
            pa0=*(const uint4*)(Ap+(size_t)(bm+row)*K+kk+ch*8);
            pa1=*(const uint4*)(Ap+(size_t)(bm+row+64)*K+kk+ch*8);
            int g0=bn+row, g1=bn+row+64;
            pb0 = (g0<N)? *(const uint4*)(Bp+(size_t)g0*K+kk+ch*8) : make_uint4(0,0,0,0);
            pb1 = (g1<N)? *(const uint4*)(Bp+(size_t)g1*K+kk+ch*8) : make_uint4(0,0,0,0);
        }
        #pragma unroll
        for(int ks=0;ks<2;ks++){
            uint32_t a[2][4];
            #pragma unroll
            for(int mt=0;mt<2;mt++){
                uint32_t ad = a_base + buf*BUFB + mt*(16*AST*2) + ks*32;
                LDSM4(a[mt][0],a[mt][1],a[mt][2],a[mt][3], ad);
            }
            uint32_t b[8][2];
            #pragma unroll
            for(int nt=0;nt<8;nt++){
                uint32_t bd = b_base + buf*BUFB + nt*(8*AST*2) + ks*32;
                LDSM2(b[nt][0],b[nt][1], bd);
            }
            #pragma unroll
            for(int mt=0;mt<2;mt++)
                #pragma unroll
                for(int nt=0;nt<8;nt++)
                    MMA16816(acc[mt][nt], a[mt], b[nt]);
        }
        if(s+1<S){
            const uint32_t ob=(buf^1)*BUFB;
            *(uint4*)(As[0]+ (ob>>1) + row*AST+ch*8)=pa0;        // ob bytes -> elements
            *(uint4*)(As[0]+ (ob>>1) + (row+64)*AST+ch*8)=pa1;
            *(uint4*)(Bs[0]+ (ob>>1) + row*AST+ch*8)=pb0;
            *(uint4*)(Bs[0]+ (ob>>1) + (row+64)*AST+ch*8)=pb1;
            __syncthreads();
        }
    }

    // epilogue
    const int g=lane>>2, ct=lane&3;
    #pragma unroll
    for(int mt=0;mt<2;mt++){
        #pragma unroll
        for(int nt=0;nt<8;nt++){
            int r0=bm+wm+mt*16+g, r1=r0+8;
            int col=bn+wn+nt*8+ct*2;
            float c0=acc[mt][nt][0], c1=acc[mt][nt][1];
            float c2=acc[mt][nt][2], c3=acc[mt][nt][3];
            if(act==3){
                if(col<N)   Cf[(size_t)r0*N+col]=c0;
                if(col+1<N) Cf[(size_t)r0*N+col+1]=c1;
                if(col<N)   Cf[(size_t)r1*N+col]=c2;
                if(col+1<N) Cf[(size_t)r1*N+col+1]=c3;
            } else {
                float b0=bias[col], b1=bias[col+1];
                c0+=b0; c1+=b1; c2+=b0; c3+=b1;
                if(act==1){
                    float2 q0=*(const float2*)(res+(size_t)r0*N+col);
                    float2 q1=*(const float2*)(res+(size_t)r1*N+col);
                    c0+=q0.x; c1+=q0.y; c2+=q1.x; c3+=q1.y;
                    *(float2*)(Cf+(size_t)r0*N+col)=make_float2(c0,c1);
                    *(float2*)(Cf+(size_t)r1*N+col)=make_float2(c2,c3);
                } else if(act==0){
                    *(float2*)(Cf+(size_t)r0*N+col)=make_float2(c0,c1);
                    *(float2*)(Cf+(size_t)r1*N+col)=make_float2(c2,c3);
                } else { // act==2 gelu -> split bf16
                    c0=gelu_f(c0); c1=gelu_f(c1); c2=gelu_f(c2); c3=gelu_f(c3);
                    __nv_bfloat16 h0,h1,h2,h3,l0,l1,l2,l3;
                    split2(c0,h0,l0); split2(c1,h1,l1); split2(c2,h2,l2); split2(c3,h3,l3);
                    *(uint32_t*)(Chi+(size_t)r0*N+col)=pack2(h0,h1);
                    *(uint32_t*)(Clo+(size_t)r0*N+col)=pack2(l0,l1);
                    *(uint32_t*)(Chi+(size_t)r1*N+col)=pack2(h2,h3);
                    *(uint32_t*)(Clo+(size_t)r1*N+col)=pack2(l2,l3);
                }
            }
        }
    }
}

// flash attention (fp32), outputs split bf16
__global__ __launch_bounds__(256) void attn_kernel(
    const float* __restrict__ qkv, __nv_bfloat16* __restrict__ yhi, __nv_bfloat16* __restrict__ ylo)
{
    __shared__ float Qs[64][65], Ks[32][65], Vs[32][65], Ps[64][33];
    const int qb=blockIdx.x, h=blockIdx.y, b=blockIdx.z;
    const int tid=threadIdx.x, tx=tid&15, ty=tid>>4, q0=qb*64;
    const float* base=qkv+(size_t)b*SEQ*D3;
    #pragma unroll
    for(int p=0;p<4;p++){
        int idx=tid+256*p, r=idx>>4, c=(idx&15)<<2;
        float4 v=*(const float4*)(base+(size_t)(q0+r)*D3+h*HDIM+c);
        Qs[r][c]=v.x*0.125f; Qs[r][c+1]=v.y*0.125f; Qs[r][c+2]=v.z*0.125f; Qs[r][c+3]=v.w*0.125f;
    }
    float o[4][4], m[4], l[4];
    #pragma unroll
    for(int i=0;i<4;i++){ m[i]=-1e30f; l[i]=0.f;
        #pragma unroll
        for(int j=0;j<4;j++) o[i][j]=0.f; }
    const int nt=2*qb+2;
    for(int kt=0;kt<nt;kt++){
        int ks=kt*32;
        __syncthreads();
        #pragma unroll
        for(int p=0;p<2;p++){
            int idx=tid+256*p, r=idx>>4, c=(idx&15)<<2;
            float4 kv=*(const float4*)(base+(size_t)(ks+r)*D3+DMODEL+h*HDIM+c);
            float4 vv=*(const float4*)(base+(size_t)(ks+r)*D3+2*DMODEL+h*HDIM+c);
            Ks[r][c]=kv.x; Ks[r][c+1]=kv.y; Ks[r][c+2]=kv.z; Ks[r][c+3]=kv.w;
            Vs[r][c]=vv.x; Vs[r][c+1]=vv.y; Vs[r][c+2]=vv.z; Vs[r][c+3]=vv.w;
        }
        __syncthreads();
        float s[4][2];
        #pragma unroll
        for(int i=0;i<4;i++){ s[i][0]=0.f; s[i][1]=0.f; }
        #pragma unroll 8
        for(int d=0;d<HDIM;d++){
            float a0=Qs[ty][d],a1=Qs[ty+16][d],a2=Qs[ty+32][d],a3=Qs[ty+48][d];
            float b0=Ks[tx][d],b1=Ks[tx+16][d];
            s[0][0]+=a0*b0; s[0][1]+=a0*b1; s[1][0]+=a1*b0; s[1][1]+=a1*b1;
            s[2][0]+=a2*b0; s[2][1]+=a2*b1; s[3][0]+=a3*b0; s[3][1]+=a3*b1;
        }
        #pragma unroll
        for(int i=0;i<4;i++){
            int qg=q0+ty+16*i;
            if(ks+tx>qg) s[i][0]=-1e30f;
            if(ks+tx+16>qg) s[i][1]=-1e30f;
        }
        #pragma unroll
        for(int i=0;i<4;i++){
            float pm=fmaxf(s[i][0],s[i][1]);
            #pragma unroll
            for(int off=8;off>0;off>>=1) pm=fmaxf(pm,__shfl_xor_sync(~0u,pm,off));
            float mn=fmaxf(m[i],pm), al=__expf(m[i]-mn);
            float p0=__expf(s[i][0]-mn), p1=__expf(s[i][1]-mn);
            float rs=p0+p1;
            #pragma unroll
            for(int off=8;off>0;off>>=1) rs+=__shfl_xor_sync(~0u,rs,off);
            l[i]=l[i]*al+rs; m[i]=mn;
            #pragma unroll
            for(int j=0;j<4;j++) o[i][j]*=al;
            Ps[ty+16*i][tx]=p0; Ps[ty+16*i][tx+16]=p1;
        }
        __syncthreads();
        #pragma unroll 4
        for(int kk=0;kk<32;kk++){
            float p0=Ps[ty][kk],p1=Ps[ty+16][kk],p2=Ps[ty+32][kk],p3=Ps[ty+48][kk];
            float v0=Vs[kk][tx],v1=Vs[kk][tx+16],v2=Vs[kk][tx+32],v3=Vs[kk][tx+48];
            o[0][0]+=p0*v0; o[0][1]+=p0*v1; o[0][2]+=p0*v2; o[0][3]+=p0*v3;
            o[1][0]+=p1*v0; o[1][1]+=p1*v1; o[1][2]+=p1*v2; o[1][3]+=p1*v3;
            o[2][0]+=p2*v0; o[2][1]+=p2*v1; o[2][2]+=p2*v2; o[2][3]+=p2*v3;
            o[3][0]+=p3*v0; o[3][1]+=p3*v1; o[3][2]+=p3*v2; o[3][3]+=p3*v3;
        }
    }
    #pragma unroll
    for(int i=0;i<4;i++){
        float inv=1.f/l[i];
        size_t row=(size_t)(b*SEQ+q0+ty+16*i);
        #pragma unroll
        for(int j=0;j<4;j++){
            float val=o[i][j]*inv;
            __nv_bfloat16 hv,lv; split2(val,hv,lv);
            size_t off=row*DMODEL+h*HDIM+tx+16*j;
            yhi[off]=hv; ylo[off]=lv;
        }
    }
}

extern "C" void kernel_launch(void* const* d_in, const int* in_sizes, int n_in,
                              void* d_out, int out_size)
{
    (void)in_sizes;(void)n_in;(void)out_size;
    const int*   idx   =(const int*)  d_in[0];
    const float* wte   =(const float*)d_in[1];
    const float* wpe   =(const float*)d_in[2];
    const float* ln1_w =(const float*)d_in[3];
    const float* ln1_b =(const float*)d_in[4];
    const float* aw    =(const float*)d_in[5];
    const float* ab    =(const float*)d_in[6];
    const float* pw    =(const float*)d_in[7];
    const float* pb    =(const float*)d_in[8];
    const float* ln2_w =(const float*)d_in[9];
    const float* ln2_b =(const float*)d_in[10];
    const float* fw    =(const float*)d_in[11];
    const float* fb    =(const float*)d_in[12];
    const float* ow    =(const float*)d_in[13];
    const float* ob    =(const float*)d_in[14];
    const float* lnf_w =(const float*)d_in[15];
    const float* lnf_b =(const float*)d_in[16];
    float* out=(float*)d_out;

    float *x,*qkv;
    __nv_bfloat16 *hhi,*hlo,*yhi,*ylo,*ffhi,*fflo;
    __nv_bfloat16 *wqh,*wql,*wah,*wal,*wfh,*wfl,*wph,*wpl,*weh,*wel;
    cudaGetSymbolAddress((void**)&x,g_x);       cudaGetSymbolAddress((void**)&qkv,g_qkv);
    cudaGetSymbolAddress((void**)&hhi,g_h_hi);  cudaGetSymbolAddress((void**)&hlo,g_h_lo);
    cudaGetSymbolAddress((void**)&yhi,g_y_hi);  cudaGetSymbolAddress((void**)&ylo,g_y_lo);
    cudaGetSymbolAddress((void**)&ffhi,g_ff_hi);cudaGetSymbolAddress((void**)&fflo,g_ff_lo);
    cudaGetSymbolAddress((void**)&wqh,g_wq_hi); cudaGetSymbolAddress((void**)&wql,g_wq_lo);
    cudaGetSymbolAddress((void**)&wah,g_wa_hi); cudaGetSymbolAddress((void**)&wal,g_wa_lo);
    cudaGetSymbolAddress((void**)&wfh,g_wf_hi); cudaGetSymbolAddress((void**)&wfl,g_wf_lo);
    cudaGetSymbolAddress((void**)&wph,g_wp_hi); cudaGetSymbolAddress((void**)&wpl,g_wp_lo);
    cudaGetSymbolAddress((void**)&weh,g_we_hi); cudaGetSymbolAddress((void**)&wel,g_we_lo);

    dim3 wb(32,8);
    wsplit_t<<<dim3(D3/32,   DMODEL/32, NLAYER), wb>>>(aw, wqh, wql, DMODEL, D3);
    wsplit_t<<<dim3(DMODEL/32,DMODEL/32,NLAYER), wb>>>(pw, wah, wal, DMODEL, DMODEL);
    wsplit_t<<<dim3(FFDIM/32, DMODEL/32,NLAYER), wb>>>(fw, wfh, wfl, DMODEL, FFDIM);
    wsplit_t<<<dim3(DMODEL/32,FFDIM/32, NLAYER), wb>>>(ow, wph, wpl, FFDIM, DMODEL);
    wte_split<<<VOCAB,256>>>(wte, weh, wel);

    embed_kernel<<<BTOK*DMODEL/1024,256>>>(idx, wte, wpe, x);

    for(int l=0;l<NLAYER;l++){
        ln_kernel<<<BTOK,256>>>(x, ln1_w+(size_t)l*DMODEL, ln1_b+(size_t)l*DMODEL, hhi, hlo);
        gemm_mma<<<dim3(D3/128,BTOK/128),256>>>(
            hhi,hlo, wqh+(size_t)l*DMODEL*D3, wql+(size_t)l*DMODEL*D3,
            ab+(size_t)l*D3, nullptr, qkv, nullptr,nullptr, D3, DMODEL, 0);
        attn_kernel<<<dim3(SEQ/64,NHEAD,BATCH),256>>>(qkv, yhi, ylo);
        gemm_mma<<<dim3(DMODEL/128,BTOK/128),256>>>(
            yhi,ylo, wah+(size_t)l*DMODEL*DMODEL, wal+(size_t)l*DMODEL*DMODEL,
            pb+(size_t)l*DMODEL, x, x, nullptr,nullptr, DMODEL, DMODEL, 1);
        ln_kernel<<<BTOK,256>>>(x, ln2_w+(size_t)l*DMODEL, ln2_b+(size_t)l*DMODEL, hhi, hlo);
        gemm_mma<<<dim3(FFDIM/128,BTOK/128),256>>>(
            hhi,hlo, wfh+(size_t)l*DMODEL*FFDIM, wfl+(size_t)l*DMODEL*FFDIM,
            fb+(size_t)l*FFDIM, nullptr, nullptr, ffhi, fflo, FFDIM, DMODEL, 2);
        gemm_mma<<<dim3(DMODEL/128,BTOK/128),256>>>(
            ffhi,fflo, wph+(size_t)l*FFDIM*DMODEL, wpl+(size_t)l*FFDIM*DMODEL,
            ob+(size_t)l*DMODEL, x, x, nullptr,nullptr, DMODEL, FFDIM, 1);
    }
    ln_kernel<<<BTOK,256>>>(x, lnf_w, lnf_b, hhi, hlo);
    gemm_mma<<<dim3((VOCAB+127)/128,BTOK/128),256>>>(
        hhi,hlo, weh, wel, nullptr, nullptr, out, nullptr,nullptr, VOCAB, DMODEL, 3);
}

// round 8
// speedup vs baseline: 2.0349x; 1.2413x over previous
#include <cuda_runtime.h>
#include <cuda_bf16.h>
#include <math.h>
#include <stdint.h>

#define NLAYER 24
#define NHEAD  16
#define DMODEL 1024
#define HDIM   64
#define VOCAB  50257
#define BATCH  2
#define SEQ    1024
#define BTOK   (BATCH*SEQ)
#define FFDIM  4096
#define D3     (3*DMODEL)

__device__ float g_x  [BTOK*DMODEL];
__device__ float g_qkv[BTOK*D3];
__device__ __nv_bfloat16 g_h_hi [BTOK*DMODEL], g_h_lo [BTOK*DMODEL];
__device__ __nv_bfloat16 g_y_hi [BTOK*DMODEL], g_y_lo [BTOK*DMODEL];
__device__ __nv_bfloat16 g_ff_hi[BTOK*FFDIM],  g_ff_lo[BTOK*FFDIM];
__device__ __nv_bfloat16 g_wq_hi[(size_t)NLAYER*DMODEL*D3],     g_wq_lo[(size_t)NLAYER*DMODEL*D3];
__device__ __nv_bfloat16 g_wa_hi[(size_t)NLAYER*DMODEL*DMODEL], g_wa_lo[(size_t)NLAYER*DMODEL*DMODEL];
__device__ __nv_bfloat16 g_wf_hi[(size_t)NLAYER*DMODEL*FFDIM],  g_wf_lo[(size_t)NLAYER*DMODEL*FFDIM];
__device__ __nv_bfloat16 g_wp_hi[(size_t)NLAYER*FFDIM*DMODEL],  g_wp_lo[(size_t)NLAYER*FFDIM*DMODEL];
__device__ __nv_bfloat16 g_we_hi[(size_t)VOCAB*DMODEL],         g_we_lo[(size_t)VOCAB*DMODEL];

__device__ __forceinline__ uint32_t smem_u32(const void* p){
    uint32_t a;
    asm("{ .reg .u64 t; cvta.to.shared.u64 t, %1; cvt.u32.u64 %0, t; }" : "=r"(a) : "l"(p));
    return a;
}
#define LDSM4(r0,r1,r2,r3,a) asm volatile("ldmatrix.sync.aligned.m8n8.x4.shared.b16 {%0,%1,%2,%3},[%4];":"=r"(r0),"=r"(r1),"=r"(r2),"=r"(r3):"r"(a))
#define LDSM2(r0,r1,a)       asm volatile("ldmatrix.sync.aligned.m8n8.x2.shared.b16 {%0,%1},[%2];":"=r"(r0),"=r"(r1):"r"(a))
#define MMA16816(c,a,b) asm volatile( \
    "mma.sync.aligned.m16n8k16.row.col.f32.bf16.bf16.f32 {%0,%1,%2,%3},{%4,%5,%6,%7},{%8,%9},{%0,%1,%2,%3};" \
    :"+f"((c)[0]),"+f"((c)[1]),"+f"((c)[2]),"+f"((c)[3]) \
    :"r"((a)[0]),"r"((a)[1]),"r"((a)[2]),"r"((a)[3]),"r"((b)[0]),"r"((b)[1]))

__device__ __forceinline__ float gelu_f(float x){
    float x3=x*x*x;
    return 0.5f*x*(1.f+tanhf(0.7978845608028654f*(x+0.044715f*x3)));
}
__device__ __forceinline__ void split2(float v, __nv_bfloat16&h, __nv_bfloat16&l){
    h=__float2bfloat16(v); l=__float2bfloat16(v-__bfloat162float(h));
}
__device__ __forceinline__ uint32_t pack2(__nv_bfloat16 a, __nv_bfloat16 b){
    return ((uint32_t)__bfloat16_as_ushort(b)<<16)|__bfloat16_as_ushort(a);
}

__global__ __launch_bounds__(256) void embed_kernel(
    const int* __restrict__ idx, const float* __restrict__ wte,
    const float* __restrict__ wpe, float* __restrict__ x)
{
    int i=blockIdx.x*256+threadIdx.x, tok=i>>8, c=i&255, t=tok&(SEQ-1);
    int id=idx[tok];
    float4 a=((const float4*)(wte+(size_t)id*DMODEL))[c];
    float4 p=((const float4*)(wpe+(size_t)t*DMODEL))[c];
    a.x+=p.x; a.y+=p.y; a.z+=p.z; a.w+=p.w;
    ((float4*)x)[i]=a;
}

__global__ __launch_bounds__(256) void ln_kernel(
    const float* __restrict__ x, const float* __restrict__ w, const float* __restrict__ b,
    __nv_bfloat16* __restrict__ ohi, __nv_bfloat16* __restrict__ olo)
{
    int row=blockIdx.x, tid=threadIdx.x;
    float4 v=((const float4*)(x+(size_t)row*DMODEL))[tid];
    float s=v.x+v.y+v.z+v.w, sq=v.x*v.x+v.y*v.y+v.z*v.z+v.w*v.w;
    #pragma unroll
    for(int o=16;o>0;o>>=1){ s+=__shfl_xor_sync(~0u,s,o); sq+=__shfl_xor_sync(~0u,sq,o); }
    __shared__ float ss[8],sqs[8];
    if((tid&31)==0){ ss[tid>>5]=s; sqs[tid>>5]=sq; }
    __syncthreads();
    float st=0,sqt=0;
    #pragma unroll
    for(int i=0;i<8;i++){ st+=ss[i]; sqt+=sqs[i]; }
    float mean=st*(1.f/DMODEL), var=sqt*(1.f/DMODEL)-mean*mean, inv=rsqrtf(var+1e-5f);
    float4 wv=((const float4*)w)[tid], bv=((const float4*)b)[tid];
    float o0=(v.x-mean)*inv*wv.x+bv.x, o1=(v.y-mean)*inv*wv.y+bv.y;
    float o2=(v.z-mean)*inv*wv.z+bv.z, o3=(v.w-mean)*inv*wv.w+bv.w;
    __nv_bfloat16 h0,h1,h2,h3,l0,l1,l2,l3;
    split2(o0,h0,l0); split2(o1,h1,l1); split2(o2,h2,l2); split2(o3,h3,l3);
    size_t base=(size_t)row*DMODEL+tid*4;
    *(uint2*)(ohi+base)=make_uint2(pack2(h0,h1),pack2(h2,h3));
    *(uint2*)(olo+base)=make_uint2(pack2(l0,l1),pack2(l2,l3));
}

__global__ void wsplit_t(const float* __restrict__ W, __nv_bfloat16* __restrict__ hi,
                         __nv_bfloat16* __restrict__ lo, int K, int N)
{
    __shared__ float t[32][33];
    int l=blockIdx.z;
    const float* Wl=W+(size_t)l*K*N;
    __nv_bfloat16* hil=hi+(size_t)l*K*N;
    __nv_bfloat16* lol=lo+(size_t)l*K*N;
    int n0=blockIdx.x*32, k0=blockIdx.y*32, tx=threadIdx.x, ty=threadIdx.y;
    #pragma unroll
    for(int i=0;i<4;i++) t[ty+8*i][tx]=Wl[(size_t)(k0+ty+8*i)*N+n0+tx];
    __syncthreads();
    #pragma unroll
    for(int i=0;i<4;i++){
        float v=t[tx][ty+8*i];
        __nv_bfloat16 h,lw; split2(v,h,lw);
        size_t o=(size_t)(n0+ty+8*i)*K+k0+tx;
        hil[o]=h; lol[o]=lw;
    }
}

__global__ __launch_bounds__(256) void wte_split(
    const float* __restrict__ w, __nv_bfloat16* __restrict__ hi, __nv_bfloat16* __restrict__ lo)
{
    size_t base=(size_t)blockIdx.x*DMODEL+threadIdx.x*4;
    float4 v=*(const float4*)(w+base);
    __nv_bfloat16 h,l;
    split2(v.x,h,l); hi[base]=h;   lo[base]=l;
    split2(v.y,h,l); hi[base+1]=h; lo[base+1]=l;
    split2(v.z,h,l); hi[base+2]=h; lo[base+2]=l;
    split2(v.w,h,l); hi[base+3]=h; lo[base+3]=l;
}

// ---- mma.sync bf16x3 GEMM (unchanged from R5 WIN) ------------------------
#define AST 40
#define BUFB (128*AST*2)
__global__ __launch_bounds__(256) void gemm_mma(
    const __nv_bfloat16* __restrict__ Ahi, const __nv_bfloat16* __restrict__ Alo,
    const __nv_bfloat16* __restrict__ Bhi, const __nv_bfloat16* __restrict__ Blo,
    const float* __restrict__ bias, const float* __restrict__ res,
    float* __restrict__ Cf, __nv_bfloat16* __restrict__ Chi, __nv_bfloat16* __restrict__ Clo,
    int N, int K, int act)
{
    __shared__ __nv_bfloat16 As[2][128*AST];
    __shared__ __nv_bfloat16 Bs[2][128*AST];
    const int tid=threadIdx.x, wid=tid>>5, lane=tid&31;
    const int bn=blockIdx.x*128, bm=blockIdx.y*128;
    const int wm=(wid&3)*32, wn=(wid>>2)*64;
    const int row=tid>>2, ch=tid&3;

    float acc[2][8][4];
    #pragma unroll
    for(int i=0;i<2;i++)
        #pragma unroll
        for(int j=0;j<8;j++)
            #pragma unroll
            for(int k=0;k<4;k++) acc[i][j][k]=0.f;

    const uint32_t a_base = smem_u32(&As[0][0]) + (uint32_t)(((wm+(lane&15))*AST + (lane>>4)*8)*2);
    const uint32_t b_base = smem_u32(&Bs[0][0]) + (uint32_t)(((wn+(lane&7))*AST + ((lane>>3)&1)*8)*2);

    const int KS=K>>5, S=3*KS;
    uint4 pa0,pa1,pb0,pb1;
    {
        const __nv_bfloat16* Ap=Ahi; const __nv_bfloat16* Bp=Bhi;
        pa0=*(const uint4*)(Ap+(size_t)(bm+row)*K+ch*8);
        pa1=*(const uint4*)(Ap+(size_t)(bm+row+64)*K+ch*8);
        int g0=bn+row, g1=bn+row+64;
        pb0 = (g0<N)? *(const uint4*)(Bp+(size_t)g0*K+ch*8) : make_uint4(0,0,0,0);
        pb1 = (g1<N)? *(const uint4*)(Bp+(size_t)g1*K+ch*8) : make_uint4(0,0,0,0);
        *(uint4*)(As[0]+row*AST+ch*8)=pa0;
        *(uint4*)(As[0]+(row+64)*AST+ch*8)=pa1;
        *(uint4*)(Bs[0]+row*AST+ch*8)=pb0;
        *(uint4*)(Bs[0]+(row+64)*AST+ch*8)=pb1;
    }
    __syncthreads();

    for(int s=0;s<S;s++){
        const int buf=s&1;
        if(s+1<S){
            int sn=s+1, pass=sn/KS, slab=sn-pass*KS;
            const __nv_bfloat16* Ap=(pass==2)?Alo:Ahi;
            const __nv_bfloat16* Bp=(pass==1)?Blo:Bhi;
            size_t kk=(size_t)slab<<5;
            pa0=*(const uint4*)(Ap+(size_t)(bm+row)*K+kk+ch*8);
            pa1=*(const uint4*)(Ap+(size_t)(bm+row+64)*K+kk+ch*8);
            int g0=bn+row, g1=bn+row+64;
            pb0 = (g0<N)? *(const uint4*)(Bp+(size_t)g0*K+kk+ch*8) : make_uint4(0,0,0,0);
            pb1 = (g1<N)? *(const uint4*)(Bp+(size_t)g1*K+kk+ch*8) : make_uint4(0,0,0,0);
        }
        #pragma unroll
        for(int ks=0;ks<2;ks++){
            uint32_t a[2][4];
            #pragma unroll
            for(int mt=0;mt<2;mt++){
                uint32_t ad = a_base + buf*BUFB + mt*(16*AST*2) + ks*32;
                LDSM4(a[mt][0],a[mt][1],a[mt][2],a[mt][3], ad);
            }
            uint32_t b[8][2];
            #pragma unroll
            for(int nt=0;nt<8;nt++){
                uint32_t bd = b_base + buf*BUFB + nt*(8*AST*2) + ks*32;
                LDSM2(b[nt][0],b[nt][1], bd);
            }
            #pragma unroll
            for(int mt=0;mt<2;mt++)
                #pragma unroll
                for(int nt=0;nt<8;nt++)
                    MMA16816(acc[mt][nt], a[mt], b[nt]);
        }
        if(s+1<S){
            const uint32_t ob=(buf^1)*BUFB;
            *(uint4*)(As[0]+ (ob>>1) + row*AST+ch*8)=pa0;
            *(uint4*)(As[0]+ (ob>>1) + (row+64)*AST+ch*8)=pa1;
            *(uint4*)(Bs[0]+ (ob>>1) + row*AST+ch*8)=pb0;
            *(uint4*)(Bs[0]+ (ob>>1) + (row+64)*AST+ch*8)=pb1;
            __syncthreads();
        }
    }

    const int g=lane>>2, ct=lane&3;
    #pragma unroll
    for(int mt=0;mt<2;mt++){
        #pragma unroll
        for(int nt=0;nt<8;nt++){
            int r0=bm+wm+mt*16+g, r1=r0+8;
            int col=bn+wn+nt*8+ct*2;
            float c0=acc[mt][nt][0], c1=acc[mt][nt][1];
            float c2=acc[mt][nt][2], c3=acc[mt][nt][3];
            if(act==3){
                if(col<N)   Cf[(size_t)r0*N+col]=c0;
                if(col+1<N) Cf[(size_t)r0*N+col+1]=c1;
                if(col<N)   Cf[(size_t)r1*N+col]=c2;
                if(col+1<N) Cf[(size_t)r1*N+col+1]=c3;
            } else {
                float b0=bias[col], b1=bias[col+1];
                c0+=b0; c1+=b1; c2+=b0; c3+=b1;
                if(act==1){
                    float2 q0=*(const float2*)(res+(size_t)r0*N+col);
                    float2 q1=*(const float2*)(res+(size_t)r1*N+col);
                    c0+=q0.x; c1+=q0.y; c2+=q1.x; c3+=q1.y;
                    *(float2*)(Cf+(size_t)r0*N+col)=make_float2(c0,c1);
                    *(float2*)(Cf+(size_t)r1*N+col)=make_float2(c2,c3);
                } else if(act==0){
                    *(float2*)(Cf+(size_t)r0*N+col)=make_float2(c0,c1);
                    *(float2*)(Cf+(size_t)r1*N+col)=make_float2(c2,c3);
                } else {
                    c0=gelu_f(c0); c1=gelu_f(c1); c2=gelu_f(c2); c3=gelu_f(c3);
                    __nv_bfloat16 h0,h1,h2,h3,l0,l1,l2,l3;
                    split2(c0,h0,l0); split2(c1,h1,l1); split2(c2,h2,l2); split2(c3,h3,l3);
                    *(uint32_t*)(Chi+(size_t)r0*N+col)=pack2(h0,h1);
                    *(uint32_t*)(Clo+(size_t)r0*N+col)=pack2(l0,l1);
                    *(uint32_t*)(Chi+(size_t)r1*N+col)=pack2(h2,h3);
                    *(uint32_t*)(Clo+(size_t)r1*N+col)=pack2(l2,l3);
                }
            }
        }
    }
}

// ---- tensor-core flash attention (bf16x3 QK and PV, fp32 softmax) --------
// AT_STR=72 elements -> 144-byte row stride: 16B-aligned (ldmatrix requirement)
// and 8 rows land at distinct 16B offsets mod 128 (conflict-free).
#define AT_STR 72
#define AT_TILE (64*AT_STR)
#define AT_SMEM (6*AT_TILE*2)
__global__ __launch_bounds__(128) void attn_tc(
    const float* __restrict__ qkv, __nv_bfloat16* __restrict__ yhi, __nv_bfloat16* __restrict__ ylo)
{
    extern __shared__ __nv_bfloat16 sm[];
    __nv_bfloat16 *Qh=sm, *Kh=sm+2*AT_TILE, *Vh=sm+4*AT_TILE;
    const int qb=blockIdx.x, h=blockIdx.y, b=blockIdx.z;
    const int tid=threadIdx.x, wid=tid>>5, lane=tid&31;
    const int q0=qb*64;
    const float* base=qkv+(size_t)b*SEQ*D3;
    const uint32_t dLO = AT_TILE*2;   // bytes from hi to lo array

    #pragma unroll
    for(int i=0;i<8;i++){
        int idx=tid+128*i, r=idx>>4, c=(idx&15)*4;
        float4 v=*(const float4*)(base+(size_t)(q0+r)*D3+h*HDIM+c);
        float f[4]={v.x*0.125f,v.y*0.125f,v.z*0.125f,v.w*0.125f};
        #pragma unroll
        for(int j=0;j<4;j++){
            __nv_bfloat16 hh,ll; split2(f[j],hh,ll);
            Qh[r*AT_STR+c+j]=hh; Qh[AT_TILE+r*AT_STR+c+j]=ll;
        }
    }

    const int g=lane>>2, ct=lane&3;
    float o[8][4];
    #pragma unroll
    for(int nt=0;nt<8;nt++){ o[nt][0]=0.f;o[nt][1]=0.f;o[nt][2]=0.f;o[nt][3]=0.f; }
    float m0=-1e30f,m1=-1e30f,l0=0.f,l1=0.f;

    const uint32_t qa = smem_u32(Qh) + (uint32_t)(((wid*16+(lane&15))*AT_STR + (lane>>4)*8)*2);
    const uint32_t kb = smem_u32(Kh) + (uint32_t)(((lane&7)*AT_STR + ((lane>>3)&1)*8)*2);
    const uint32_t vb = smem_u32(Vh) + (uint32_t)(((lane&7)*AT_STR + ((lane>>3)&1)*8)*2);

    for(int kt=0;kt<=qb;kt++){
        __syncthreads();
        const int ks0=kt*64;
        #pragma unroll
        for(int i=0;i<8;i++){
            int idx=tid+128*i, r=idx>>4, c=(idx&15)*4;
            float4 kv=*(const float4*)(base+(size_t)(ks0+r)*D3+DMODEL+h*HDIM+c);
            float4 vv=*(const float4*)(base+(size_t)(ks0+r)*D3+2*DMODEL+h*HDIM+c);
            float kf[4]={kv.x,kv.y,kv.z,kv.w}, vf[4]={vv.x,vv.y,vv.z,vv.w};
            #pragma unroll
            for(int j=0;j<4;j++){
                __nv_bfloat16 hh,ll;
                split2(kf[j],hh,ll);
                Kh[r*AT_STR+c+j]=hh; Kh[AT_TILE+r*AT_STR+c+j]=ll;
                split2(vf[j],hh,ll);
                Vh[(c+j)*AT_STR+r]=hh; Vh[AT_TILE+(c+j)*AT_STR+r]=ll;
            }
        }
        __syncthreads();

        float S[8][4];
        #pragma unroll
        for(int nt=0;nt<8;nt++){ S[nt][0]=0.f;S[nt][1]=0.f;S[nt][2]=0.f;S[nt][3]=0.f; }
        #pragma unroll
        for(int pass=0;pass<3;pass++){
            const uint32_t ab = qa + ((pass==2)?dLO:0u);
            const uint32_t bb = kb + ((pass==1)?dLO:0u);
            #pragma unroll
            for(int ks=0;ks<4;ks++){
                uint32_t a[4];
                LDSM4(a[0],a[1],a[2],a[3], ab + ks*32);
                #pragma unroll
                for(int nt=0;nt<8;nt++){
                    uint32_t bf[2];
                    LDSM2(bf[0],bf[1], bb + nt*(8*AT_STR*2) + ks*32);
                    MMA16816(S[nt], a, bf);
                }
            }
        }
        if(kt==qb){
            const int r0=q0+wid*16+g, r1=r0+8;
            #pragma unroll
            for(int nt=0;nt<8;nt++){
                int c0=ks0+nt*8+ct*2;
                if(c0>r0)   S[nt][0]=-1e30f;
                if(c0+1>r0) S[nt][1]=-1e30f;
                if(c0>r1)   S[nt][2]=-1e30f;
                if(c0+1>r1) S[nt][3]=-1e30f;
            }
        }
        float rm0=-1e30f, rm1=-1e30f;
        #pragma unroll
        for(int nt=0;nt<8;nt++){
            rm0=fmaxf(rm0,fmaxf(S[nt][0],S[nt][1]));
            rm1=fmaxf(rm1,fmaxf(S[nt][2],S[nt][3]));
        }
        rm0=fmaxf(rm0,__shfl_xor_sync(~0u,rm0,1)); rm0=fmaxf(rm0,__shfl_xor_sync(~0u,rm0,2));
        rm1=fmaxf(rm1,__shfl_xor_sync(~0u,rm1,1)); rm1=fmaxf(rm1,__shfl_xor_sync(~0u,rm1,2));
        float mn0=fmaxf(m0,rm0), mn1=fmaxf(m1,rm1);
        float al0=__expf(m0-mn0), al1=__expf(m1-mn1);
        m0=mn0; m1=mn1;
        float rs0=0.f, rs1=0.f;
        uint32_t ph[4][4], pl[4][4];
        #pragma unroll
        for(int j=0;j<8;j++){
            float p0=__expf(S[j][0]-mn0), p1=__expf(S[j][1]-mn0);
            float p2=__expf(S[j][2]-mn1), p3=__expf(S[j][3]-mn1);
            rs0+=p0+p1; rs1+=p2+p3;
            __nv_bfloat16 h0,h1,h2,h3,q0b,q1b,q2b,q3b;
            split2(p0,h0,q0b); split2(p1,h1,q1b); split2(p2,h2,q2b); split2(p3,h3,q3b);
            ph[j>>1][(j&1)*2]  =pack2(h0,h1);
            ph[j>>1][(j&1)*2+1]=pack2(h2,h3);
            pl[j>>1][(j&1)*2]  =pack2(q0b,q1b);
            pl[j>>1][(j&1)*2+1]=pack2(q2b,q3b);
        }
        rs0+=__shfl_xor_sync(~0u,rs0,1); rs0+=__shfl_xor_sync(~0u,rs0,2);
        rs1+=__shfl_xor_sync(~0u,rs1,1); rs1+=__shfl_xor_sync(~0u,rs1,2);
        l0=l0*al0+rs0; l1=l1*al1+rs1;
        #pragma unroll
        for(int nt=0;nt<8;nt++){
            o[nt][0]*=al0; o[nt][1]*=al0; o[nt][2]*=al1; o[nt][3]*=al1;
        }
        #pragma unroll
        for(int pass=0;pass<3;pass++){
            const uint32_t vbb = vb + ((pass==1)?dLO:0u);
            #pragma unroll
            for(int kk=0;kk<4;kk++){
                const uint32_t* A = (pass==2)? pl[kk] : ph[kk];
                #pragma unroll
                for(int nt=0;nt<8;nt++){
                    uint32_t bf[2];
                    LDSM2(bf[0],bf[1], vbb + nt*(8*AT_STR*2) + kk*32);
                    MMA16816(o[nt], A, bf);
                }
            }
        }
    }
    const float i0=1.f/l0, i1=1.f/l1;
    const size_t r0=(size_t)(b*SEQ+q0+wid*16+g), r1=r0+8;
    #pragma unroll
    for(int nt=0;nt<8;nt++){
        int col=h*HDIM+nt*8+ct*2;
        __nv_bfloat16 ah,al2,bh,bl;
        split2(o[nt][0]*i0,ah,al2); split2(o[nt][1]*i0,bh,bl);
        *(uint32_t*)(yhi+r0*DMODEL+col)=pack2(ah,bh);
        *(uint32_t*)(ylo+r0*DMODEL+col)=pack2(al2,bl);
        split2(o[nt][2]*i1,ah,al2); split2(o[nt][3]*i1,bh,bl);
        *(uint32_t*)(yhi+r1*DMODEL+col)=pack2(ah,bh);
        *(uint32_t*)(ylo+r1*DMODEL+col)=pack2(al2,bl);
    }
}

extern "C" void kernel_launch(void* const* d_in, const int* in_sizes, int n_in,
                              void* d_out, int out_size)
{
    (void)in_sizes;(void)n_in;(void)out_size;
    const int*   idx   =(const int*)  d_in[0];
    const float* wte   =(const float*)d_in[1];
    const float* wpe   =(const float*)d_in[2];
    const float* ln1_w =(const float*)d_in[3];
    const float* ln1_b =(const float*)d_in[4];
    const float* aw    =(const float*)d_in[5];
    const float* ab    =(const float*)d_in[6];
    const float* pw    =(const float*)d_in[7];
    const float* pb    =(const float*)d_in[8];
    const float* ln2_w =(const float*)d_in[9];
    const float* ln2_b =(const float*)d_in[10];
    const float* fw    =(const float*)d_in[11];
    const float* fb    =(const float*)d_in[12];
    const float* ow    =(const float*)d_in[13];
    const float* ob    =(const float*)d_in[14];
    const float* lnf_w =(const float*)d_in[15];
    const float* lnf_b =(const float*)d_in[16];
    float* out=(float*)d_out;

    cudaFuncSetAttribute(attn_tc, cudaFuncAttributeMaxDynamicSharedMemorySize, AT_SMEM);

    float *x,*qkv;
    __nv_bfloat16 *hhi,*hlo,*yhi,*ylo,*ffhi,*fflo;
    __nv_bfloat16 *wqh,*wql,*wah,*wal,*wfh,*wfl,*wph,*wpl,*weh,*wel;
    cudaGetSymbolAddress((void**)&x,g_x);       cudaGetSymbolAddress((void**)&qkv,g_qkv);
    cudaGetSymbolAddress((void**)&hhi,g_h_hi);  cudaGetSymbolAddress((void**)&hlo,g_h_lo);
    cudaGetSymbolAddress((void**)&yhi,g_y_hi);  cudaGetSymbolAddress((void**)&ylo,g_y_lo);
    cudaGetSymbolAddress((void**)&ffhi,g_ff_hi);cudaGetSymbolAddress((void**)&fflo,g_ff_lo);
    cudaGetSymbolAddress((void**)&wqh,g_wq_hi); cudaGetSymbolAddress((void**)&wql,g_wq_lo);
    cudaGetSymbolAddress((void**)&wah,g_wa_hi); cudaGetSymbolAddress((void**)&wal,g_wa_lo);
    cudaGetSymbolAddress((void**)&wfh,g_wf_hi); cudaGetSymbolAddress((void**)&wfl,g_wf_lo);
    cudaGetSymbolAddress((void**)&wph,g_wp_hi); cudaGetSymbolAddress((void**)&wpl,g_wp_lo);
    cudaGetSymbolAddress((void**)&weh,g_we_hi); cudaGetSymbolAddress((void**)&wel,g_we_lo);

    dim3 wb(32,8);
    wsplit_t<<<dim3(D3/32,   DMODEL/32, NLAYER), wb>>>(aw, wqh, wql, DMODEL, D3);
    wsplit_t<<<dim3(DMODEL/32,DMODEL/32,NLAYER), wb>>>(pw, wah, wal, DMODEL, DMODEL);
    wsplit_t<<<dim3(FFDIM/32, DMODEL/32,NLAYER), wb>>>(fw, wfh, wfl, DMODEL, FFDIM);
    wsplit_t<<<dim3(DMODEL/32,FFDIM/32, NLAYER), wb>>>(ow, wph, wpl, FFDIM, DMODEL);
    wte_split<<<VOCAB,256>>>(wte, weh, wel);

    embed_kernel<<<BTOK*DMODEL/1024,256>>>(idx, wte, wpe, x);

    for(int l=0;l<NLAYER;l++){
        ln_kernel<<<BTOK,256>>>(x, ln1_w+(size_t)l*DMODEL, ln1_b+(size_t)l*DMODEL, hhi, hlo);
        gemm_mma<<<dim3(D3/128,BTOK/128),256>>>(
            hhi,hlo, wqh+(size_t)l*DMODEL*D3, wql+(size_t)l*DMODEL*D3,
            ab+(size_t)l*D3, nullptr, qkv, nullptr,nullptr, D3, DMODEL, 0);
        attn_tc<<<dim3(SEQ/64,NHEAD,BATCH),128,AT_SMEM>>>(qkv, yhi, ylo);
        gemm_mma<<<dim3(DMODEL/128,BTOK/128),256>>>(
            yhi,ylo, wah+(size_t)l*DMODEL*DMODEL, wal+(size_t)l*DMODEL*DMODEL,
            pb+(size_t)l*DMODEL, x, x, nullptr,nullptr, DMODEL, DMODEL, 1);
        ln_kernel<<<BTOK,256>>>(x, ln2_w+(size_t)l*DMODEL, ln2_b+(size_t)l*DMODEL, hhi, hlo);
        gemm_mma<<<dim3(FFDIM/128,BTOK/128),256>>>(
            hhi,hlo, wfh+(size_t)l*DMODEL*FFDIM, wfl+(size_t)l*DMODEL*FFDIM,
            fb+(size_t)l*FFDIM, nullptr, nullptr, ffhi, fflo, FFDIM, DMODEL, 2);
        gemm_mma<<<dim3(DMODEL/128,BTOK/128),256>>>(
            ffhi,fflo, wph+(size_t)l*FFDIM*DMODEL, wpl+(size_t)l*FFDIM*DMODEL,
            ob+(size_t)l*DMODEL, x, x, nullptr,nullptr, DMODEL, FFDIM, 1);
    }
    ln_kernel<<<BTOK,256>>>(x, lnf_w, lnf_b, hhi, hlo);
    gemm_mma<<<dim3((VOCAB+127)/128,BTOK/128),256>>>(
        hhi,hlo, weh, wel, nullptr, nullptr, out, nullptr,nullptr, VOCAB, DMODEL, 3);
}

// round 9
// speedup vs baseline: 2.5557x; 1.2559x over previous
#include <cuda_runtime.h>
#include <cuda_bf16.h>
#include <math.h>
#include <stdint.h>

#define NLAYER 24
#define NHEAD  16
#define DMODEL 1024
#define HDIM   64
#define VOCAB  50257
#define BATCH  2
#define SEQ    1024
#define BTOK   (BATCH*SEQ)
#define FFDIM  4096
#define D3     (3*DMODEL)

__device__ float g_x  [BTOK*DMODEL];
__device__ float g_qkv[BTOK*D3];
__device__ __nv_bfloat16 g_h_hi [BTOK*DMODEL], g_h_lo [BTOK*DMODEL];
__device__ __nv_bfloat16 g_y_hi [BTOK*DMODEL], g_y_lo [BTOK*DMODEL];
__device__ __nv_bfloat16 g_ff_hi[BTOK*FFDIM],  g_ff_lo[BTOK*FFDIM];
__device__ __nv_bfloat16 g_wq_hi[(size_t)NLAYER*DMODEL*D3],     g_wq_lo[(size_t)NLAYER*DMODEL*D3];
__device__ __nv_bfloat16 g_wa_hi[(size_t)NLAYER*DMODEL*DMODEL], g_wa_lo[(size_t)NLAYER*DMODEL*DMODEL];
__device__ __nv_bfloat16 g_wf_hi[(size_t)NLAYER*DMODEL*FFDIM],  g_wf_lo[(size_t)NLAYER*DMODEL*FFDIM];
__device__ __nv_bfloat16 g_wp_hi[(size_t)NLAYER*FFDIM*DMODEL],  g_wp_lo[(size_t)NLAYER*FFDIM*DMODEL];
__device__ __nv_bfloat16 g_we_hi[(size_t)VOCAB*DMODEL],         g_we_lo[(size_t)VOCAB*DMODEL];

__device__ __forceinline__ uint32_t smem_u32(const void* p){
    uint32_t a;
    asm("{ .reg .u64 t; cvta.to.shared.u64 t, %1; cvt.u32.u64 %0, t; }" : "=r"(a) : "l"(p));
    return a;
}
#define LDSM4(r0,r1,r2,r3,a) asm volatile("ldmatrix.sync.aligned.m8n8.x4.shared.b16 {%0,%1,%2,%3},[%4];":"=r"(r0),"=r"(r1),"=r"(r2),"=r"(r3):"r"(a))
#define LDSM2(r0,r1,a)       asm volatile("ldmatrix.sync.aligned.m8n8.x2.shared.b16 {%0,%1},[%2];":"=r"(r0),"=r"(r1):"r"(a))
#define MMA16816(c,a,b) asm volatile( \
    "mma.sync.aligned.m16n8k16.row.col.f32.bf16.bf16.f32 {%0,%1,%2,%3},{%4,%5,%6,%7},{%8,%9},{%0,%1,%2,%3};" \
    :"+f"((c)[0]),"+f"((c)[1]),"+f"((c)[2]),"+f"((c)[3]) \
    :"r"((a)[0]),"r"((a)[1]),"r"((a)[2]),"r"((a)[3]),"r"((b)[0]),"r"((b)[1]))
#define CPASYNC16(sa,gp) asm volatile("cp.async.cg.shared.global [%0],[%1],16;"::"r"(sa),"l"(gp))
#define CPCOMMIT() asm volatile("cp.async.commit_group;":::"memory")
#define CPWAIT0()  asm volatile("cp.async.wait_group 0;":::"memory")

__device__ __forceinline__ float gelu_f(float x){
    float x3=x*x*x;
    return 0.5f*x*(1.f+tanhf(0.7978845608028654f*(x+0.044715f*x3)));
}
__device__ __forceinline__ void split2(float v, __nv_bfloat16&h, __nv_bfloat16&l){
    h=__float2bfloat16(v); l=__float2bfloat16(v-__bfloat162float(h));
}
__device__ __forceinline__ uint32_t pack2(__nv_bfloat16 a, __nv_bfloat16 b){
    return ((uint32_t)__bfloat16_as_ushort(b)<<16)|__bfloat16_as_ushort(a);
}

__global__ __launch_bounds__(256) void embed_kernel(
    const int* __restrict__ idx, const float* __restrict__ wte,
    const float* __restrict__ wpe, float* __restrict__ x)
{
    int i=blockIdx.x*256+threadIdx.x, tok=i>>8, c=i&255, t=tok&(SEQ-1);
    int id=idx[tok];
    float4 a=((const float4*)(wte+(size_t)id*DMODEL))[c];
    float4 p=((const float4*)(wpe+(size_t)t*DMODEL))[c];
    a.x+=p.x; a.y+=p.y; a.z+=p.z; a.w+=p.w;
    ((float4*)x)[i]=a;
}

__global__ __launch_bounds__(256) void ln_kernel(
    const float* __restrict__ x, const float* __restrict__ w, const float* __restrict__ b,
    __nv_bfloat16* __restrict__ ohi, __nv_bfloat16* __restrict__ olo)
{
    int row=blockIdx.x, tid=threadIdx.x;
    float4 v=((const float4*)(x+(size_t)row*DMODEL))[tid];
    float s=v.x+v.y+v.z+v.w, sq=v.x*v.x+v.y*v.y+v.z*v.z+v.w*v.w;
    #pragma unroll
    for(int o=16;o>0;o>>=1){ s+=__shfl_xor_sync(~0u,s,o); sq+=__shfl_xor_sync(~0u,sq,o); }
    __shared__ float ss[8],sqs[8];
    if((tid&31)==0){ ss[tid>>5]=s; sqs[tid>>5]=sq; }
    __syncthreads();
    float st=0,sqt=0;
    #pragma unroll
    for(int i=0;i<8;i++){ st+=ss[i]; sqt+=sqs[i]; }
    float mean=st*(1.f/DMODEL), var=sqt*(1.f/DMODEL)-mean*mean, inv=rsqrtf(var+1e-5f);
    float4 wv=((const float4*)w)[tid], bv=((const float4*)b)[tid];
    float o0=(v.x-mean)*inv*wv.x+bv.x, o1=(v.y-mean)*inv*wv.y+bv.y;
    float o2=(v.z-mean)*inv*wv.z+bv.z, o3=(v.w-mean)*inv*wv.w+bv.w;
    __nv_bfloat16 h0,h1,h2,h3,l0,l1,l2,l3;
    split2(o0,h0,l0); split2(o1,h1,l1); split2(o2,h2,l2); split2(o3,h3,l3);
    size_t base=(size_t)row*DMODEL+tid*4;
    *(uint2*)(ohi+base)=make_uint2(pack2(h0,h1),pack2(h2,h3));
    *(uint2*)(olo+base)=make_uint2(pack2(l0,l1),pack2(l2,l3));
}

__global__ void wsplit_t(const float* __restrict__ W, __nv_bfloat16* __restrict__ hi,
                         __nv_bfloat16* __restrict__ lo, int K, int N)
{
    __shared__ float t[32][33];
    int l=blockIdx.z;
    const float* Wl=W+(size_t)l*K*N;
    __nv_bfloat16* hil=hi+(size_t)l*K*N;
    __nv_bfloat16* lol=lo+(size_t)l*K*N;
    int n0=blockIdx.x*32, k0=blockIdx.y*32, tx=threadIdx.x, ty=threadIdx.y;
    #pragma unroll
    for(int i=0;i<4;i++) t[ty+8*i][tx]=Wl[(size_t)(k0+ty+8*i)*N+n0+tx];
    __syncthreads();
    #pragma unroll
    for(int i=0;i<4;i++){
        float v=t[tx][ty+8*i];
        __nv_bfloat16 h,lw; split2(v,h,lw);
        size_t o=(size_t)(n0+ty+8*i)*K+k0+tx;
        hil[o]=h; lol[o]=lw;
    }
}

__global__ __launch_bounds__(256) void wte_split(
    const float* __restrict__ w, __nv_bfloat16* __restrict__ hi, __nv_bfloat16* __restrict__ lo)
{
    size_t base=(size_t)blockIdx.x*DMODEL+threadIdx.x*4;
    float4 v=*(const float4*)(w+base);
    __nv_bfloat16 h,l;
    split2(v.x,h,l); hi[base]=h;   lo[base]=l;
    split2(v.y,h,l); hi[base+1]=h; lo[base+1]=l;
    split2(v.z,h,l); hi[base+2]=h; lo[base+2]=l;
    split2(v.w,h,l); hi[base+3]=h; lo[base+3]=l;
}

// ---- fused 3-pass bf16x3 GEMM, single K-loop, cp.async pipeline ----------
// SMEM slab: 128 rows x 64 cols (cols 0..31 = hi chunk, 32..63 = lo), stride 72.
#define GST   72
#define GSLAB (128*GST)          // elements per operand buffer
#define GSLABB (GSLAB*2)         // bytes
#define GSMEM2 (4*GSLABB)        // A0,A1,B0,B1
__global__ __launch_bounds__(256) void gemm_mma(
    const __nv_bfloat16* __restrict__ Ahi, const __nv_bfloat16* __restrict__ Alo,
    const __nv_bfloat16* __restrict__ Bhi, const __nv_bfloat16* __restrict__ Blo,
    const float* __restrict__ bias, const float* __restrict__ res,
    float* __restrict__ Cf, __nv_bfloat16* __restrict__ Chi, __nv_bfloat16* __restrict__ Clo,
    int N, int K, int act)
{
    extern __shared__ __nv_bfloat16 sm2[];
    const uint32_t smA = smem_u32(sm2);
    const uint32_t smB = smA + 2*GSLABB;
    const int tid=threadIdx.x, wid=tid>>5, lane=tid&31;
    const int bn=blockIdx.x*128, bm=blockIdx.y*128;
    const int wm=(wid&3)*32, wn=(wid>>2)*64;
    const int row2=tid>>2, ch=tid&3;

    float acc[2][8][4];
    #pragma unroll
    for(int i=0;i<2;i++)
        #pragma unroll
        for(int j=0;j<8;j++)
            #pragma unroll
            for(int k=0;k<4;k++) acc[i][j][k]=0.f;

    const uint32_t a_base = smA + (uint32_t)(((wm+(lane&15))*GST + (lane>>4)*8)*2);
    const uint32_t b_base = smB + (uint32_t)(((wn+(lane&7))*GST + ((lane>>3)&1)*8)*2);
    const int KS = K>>5;

    // stage loader (chunk c -> buffer buf)
    auto load_stage=[&](int c,int buf){
        const size_t gk=(size_t)c*32 + ch*8;
        #pragma unroll
        for(int half=0;half<2;half++){
            int r=row2+half*64;
            uint32_t sa = smA + buf*GSLABB + (uint32_t)((r*GST+ch*8)*2);
            CPASYNC16(sa,    Ahi+(size_t)(bm+r)*K+gk);
            CPASYNC16(sa+64, Alo+(size_t)(bm+r)*K+gk);
            int gn=bn+r; size_t gs=(gn<N)?(size_t)gn:0;
            uint32_t sb = smB + buf*GSLABB + (uint32_t)((r*GST+ch*8)*2);
            CPASYNC16(sb,    Bhi+gs*K+gk);
            CPASYNC16(sb+64, Blo+gs*K+gk);
        }
    };

    load_stage(0,0); CPCOMMIT(); CPWAIT0();
    __syncthreads();

    for(int c=0;c<KS;c++){
        const int buf=c&1;
        if(c+1<KS){ load_stage(c+1,buf^1); CPCOMMIT(); }
        const uint32_t ab=a_base+buf*GSLABB, bb=b_base+buf*GSLABB;
        #pragma unroll
        for(int ks=0;ks<2;ks++){
            uint32_t Ah[2][4],Al[2][4],Bh[8][2],Bl[8][2];
            #pragma unroll
            for(int mt=0;mt<2;mt++){
                uint32_t ad=ab+mt*(16*GST*2)+ks*32;
                LDSM4(Ah[mt][0],Ah[mt][1],Ah[mt][2],Ah[mt][3], ad);
                LDSM4(Al[mt][0],Al[mt][1],Al[mt][2],Al[mt][3], ad+64);
            }
            #pragma unroll
            for(int nt=0;nt<8;nt++){
                uint32_t bd=bb+nt*(8*GST*2)+ks*32;
                LDSM2(Bh[nt][0],Bh[nt][1], bd);
                LDSM2(Bl[nt][0],Bl[nt][1], bd+64);
            }
            #pragma unroll
            for(int mt=0;mt<2;mt++)
                #pragma unroll
                for(int nt=0;nt<8;nt++)
                    MMA16816(acc[mt][nt], Ah[mt], Bh[nt]);
            #pragma unroll
            for(int mt=0;mt<2;mt++)
                #pragma unroll
                for(int nt=0;nt<8;nt++)
                    MMA16816(acc[mt][nt], Ah[mt], Bl[nt]);
            #pragma unroll
            for(int mt=0;mt<2;mt++)
                #pragma unroll
                for(int nt=0;nt<8;nt++)
                    MMA16816(acc[mt][nt], Al[mt], Bh[nt]);
        }
        if(c+1<KS) CPWAIT0();
        __syncthreads();
    }

    const int g=lane>>2, ct=lane&3;
    #pragma unroll
    for(int mt=0;mt<2;mt++){
        #pragma unroll
        for(int nt=0;nt<8;nt++){
            int r0=bm+wm+mt*16+g, r1=r0+8;
            int col=bn+wn+nt*8+ct*2;
            float c0=acc[mt][nt][0], c1=acc[mt][nt][1];
            float c2=acc[mt][nt][2], c3=acc[mt][nt][3];
            if(act==3){
                if(col<N)   Cf[(size_t)r0*N+col]=c0;
                if(col+1<N) Cf[(size_t)r0*N+col+1]=c1;
                if(col<N)   Cf[(size_t)r1*N+col]=c2;
                if(col+1<N) Cf[(size_t)r1*N+col+1]=c3;
            } else {
                float b0=bias[col], b1=bias[col+1];
                c0+=b0; c1+=b1; c2+=b0; c3+=b1;
                if(act==1){
                    float2 q0=*(const float2*)(res+(size_t)r0*N+col);
                    float2 q1=*(const float2*)(res+(size_t)r1*N+col);
                    c0+=q0.x; c1+=q0.y; c2+=q1.x; c3+=q1.y;
                    *(float2*)(Cf+(size_t)r0*N+col)=make_float2(c0,c1);
                    *(float2*)(Cf+(size_t)r1*N+col)=make_float2(c2,c3);
                } else if(act==0){
                    *(float2*)(Cf+(size_t)r0*N+col)=make_float2(c0,c1);
                    *(float2*)(Cf+(size_t)r1*N+col)=make_float2(c2,c3);
                } else {
                    c0=gelu_f(c0); c1=gelu_f(c1); c2=gelu_f(c2); c3=gelu_f(c3);
                    __nv_bfloat16 h0,h1,h2,h3,l0,l1,l2,l3;
                    split2(c0,h0,l0); split2(c1,h1,l1); split2(c2,h2,l2); split2(c3,h3,l3);
                    *(uint32_t*)(Chi+(size_t)r0*N+col)=pack2(h0,h1);
                    *(uint32_t*)(Clo+(size_t)r0*N+col)=pack2(l0,l1);
                    *(uint32_t*)(Chi+(size_t)r1*N+col)=pack2(h2,h3);
                    *(uint32_t*)(Clo+(size_t)r1*N+col)=pack2(l2,l3);
                }
            }
        }
    }
}

// ---- tensor-core flash attention (unchanged from R8 WIN) -----------------
#define AT_STR 72
#define AT_TILE (64*AT_STR)
#define AT_SMEM (6*AT_TILE*2)
__global__ __launch_bounds__(128) void attn_tc(
    const float* __restrict__ qkv, __nv_bfloat16* __restrict__ yhi, __nv_bfloat16* __restrict__ ylo)
{
    extern __shared__ __nv_bfloat16 sm[];
    __nv_bfloat16 *Qh=sm, *Kh=sm+2*AT_TILE, *Vh=sm+4*AT_TILE;
    const int qb=blockIdx.x, h=blockIdx.y, b=blockIdx.z;
    const int tid=threadIdx.x, wid=tid>>5, lane=tid&31;
    const int q0=qb*64;
    const float* base=qkv+(size_t)b*SEQ*D3;
    const uint32_t dLO = AT_TILE*2;

    #pragma unroll
    for(int i=0;i<8;i++){
        int idx=tid+128*i, r=idx>>4, c=(idx&15)*4;
        float4 v=*(const float4*)(base+(size_t)(q0+r)*D3+h*HDIM+c);
        float f[4]={v.x*0.125f,v.y*0.125f,v.z*0.125f,v.w*0.125f};
        #pragma unroll
        for(int j=0;j<4;j++){
            __nv_bfloat16 hh,ll; split2(f[j],hh,ll);
            Qh[r*AT_STR+c+j]=hh; Qh[AT_TILE+r*AT_STR+c+j]=ll;
        }
    }

    const int g=lane>>2, ct=lane&3;
    float o[8][4];
    #pragma unroll
    for(int nt=0;nt<8;nt++){ o[nt][0]=0.f;o[nt][1]=0.f;o[nt][2]=0.f;o[nt][3]=0.f; }
    float m0=-1e30f,m1=-1e30f,l0=0.f,l1=0.f;

    const uint32_t qa = smem_u32(Qh) + (uint32_t)(((wid*16+(lane&15))*AT_STR + (lane>>4)*8)*2);
    const uint32_t kb = smem_u32(Kh) + (uint32_t)(((lane&7)*AT_STR + ((lane>>3)&1)*8)*2);
    const uint32_t vb = smem_u32(Vh) + (uint32_t)(((lane&7)*AT_STR + ((lane>>3)&1)*8)*2);

    for(int kt=0;kt<=qb;kt++){
        __syncthreads();
        const int ks0=kt*64;
        #pragma unroll
        for(int i=0;i<8;i++){
            int idx=tid+128*i, r=idx>>4, c=(idx&15)*4;
            float4 kv=*(const float4*)(base+(size_t)(ks0+r)*D3+DMODEL+h*HDIM+c);
            float4 vv=*(const float4*)(base+(size_t)(ks0+r)*D3+2*DMODEL+h*HDIM+c);
            float kf[4]={kv.x,kv.y,kv.z,kv.w}, vf[4]={vv.x,vv.y,vv.z,vv.w};
            #pragma unroll
            for(int j=0;j<4;j++){
                __nv_bfloat16 hh,ll;
                split2(kf[j],hh,ll);
                Kh[r*AT_STR+c+j]=hh; Kh[AT_TILE+r*AT_STR+c+j]=ll;
                split2(vf[j],hh,ll);
                Vh[(c+j)*AT_STR+r]=hh; Vh[AT_TILE+(c+j)*AT_STR+r]=ll;
            }
        }
        __syncthreads();

        float S[8][4];
        #pragma unroll
        for(int nt=0;nt<8;nt++){ S[nt][0]=0.f;S[nt][1]=0.f;S[nt][2]=0.f;S[nt][3]=0.f; }
        #pragma unroll
        for(int pass=0;pass<3;pass++){
            const uint32_t ab = qa + ((pass==2)?dLO:0u);
            const uint32_t bb = kb + ((pass==1)?dLO:0u);
            #pragma unroll
            for(int ks=0;ks<4;ks++){
                uint32_t a[4];
                LDSM4(a[0],a[1],a[2],a[3], ab + ks*32);
                #pragma unroll
                for(int nt=0;nt<8;nt++){
                    uint32_t bf[2];
                    LDSM2(bf[0],bf[1], bb + nt*(8*AT_STR*2) + ks*32);
                    MMA16816(S[nt], a, bf);
                }
            }
        }
        if(kt==qb){
            const int r0=q0+wid*16+g, r1=r0+8;
            #pragma unroll
            for(int nt=0;nt<8;nt++){
                int c0=ks0+nt*8+ct*2;
                if(c0>r0)   S[nt][0]=-1e30f;
                if(c0+1>r0) S[nt][1]=-1e30f;
                if(c0>r1)   S[nt][2]=-1e30f;
                if(c0+1>r1) S[nt][3]=-1e30f;
            }
        }
        float rm0=-1e30f, rm1=-1e30f;
        #pragma unroll
        for(int nt=0;nt<8;nt++){
            rm0=fmaxf(rm0,fmaxf(S[nt][0],S[nt][1]));
            rm1=fmaxf(rm1,fmaxf(S[nt][2],S[nt][3]));
        }
        rm0=fmaxf(rm0,__shfl_xor_sync(~0u,rm0,1)); rm0=fmaxf(rm0,__shfl_xor_sync(~0u,rm0,2));
        rm1=fmaxf(rm1,__shfl_xor_sync(~0u,rm1,1)); rm1=fmaxf(rm1,__shfl_xor_sync(~0u,rm1,2));
        float mn0=fmaxf(m0,rm0), mn1=fmaxf(m1,rm1);
        float al0=__expf(m0-mn0), al1=__expf(m1-mn1);
        m0=mn0; m1=mn1;
        float rs0=0.f, rs1=0.f;
        uint32_t ph[4][4], pl[4][4];
        #pragma unroll
        for(int j=0;j<8;j++){
            float p0=__expf(S[j][0]-mn0), p1=__expf(S[j][1]-mn0);
            float p2=__expf(S[j][2]-mn1), p3=__expf(S[j][3]-mn1);
            rs0+=p0+p1; rs1+=p2+p3;
            __nv_bfloat16 h0,h1,h2,h3,q0b,q1b,q2b,q3b;
            split2(p0,h0,q0b); split2(p1,h1,q1b); split2(p2,h2,q2b); split2(p3,h3,q3b);
            ph[j>>1][(j&1)*2]  =pack2(h0,h1);
            ph[j>>1][(j&1)*2+1]=pack2(h2,h3);
            pl[j>>1][(j&1)*2]  =pack2(q0b,q1b);
            pl[j>>1][(j&1)*2+1]=pack2(q2b,q3b);
        }
        rs0+=__shfl_xor_sync(~0u,rs0,1); rs0+=__shfl_xor_sync(~0u,rs0,2);
        rs1+=__shfl_xor_sync(~0u,rs1,1); rs1+=__shfl_xor_sync(~0u,rs1,2);
        l0=l0*al0+rs0; l1=l1*al1+rs1;
        #pragma unroll
        for(int nt=0;nt<8;nt++){
            o[nt][0]*=al0; o[nt][1]*=al0; o[nt][2]*=al1; o[nt][3]*=al1;
        }
        #pragma unroll
        for(int pass=0;pass<3;pass++){
            const uint32_t vbb = vb + ((pass==1)?dLO:0u);
            #pragma unroll
            for(int kk=0;kk<4;kk++){
                const uint32_t* A = (pass==2)? pl[kk] : ph[kk];
                #pragma unroll
                for(int nt=0;nt<8;nt++){
                    uint32_t bf[2];
                    LDSM2(bf[0],bf[1], vbb + nt*(8*AT_STR*2) + kk*32);
                    MMA16816(o[nt], A, bf);
                }
            }
        }
    }
    const float i0=1.f/l0, i1=1.f/l1;
    const size_t r0=(size_t)(b*SEQ+q0+wid*16+g), r1=r0+8;
    #pragma unroll
    for(int nt=0;nt<8;nt++){
        int col=h*HDIM+nt*8+ct*2;
        __nv_bfloat16 ah,al2,bh,bl;
        split2(o[nt][0]*i0,ah,al2); split2(o[nt][1]*i0,bh,bl);
        *(uint32_t*)(yhi+r0*DMODEL+col)=pack2(ah,bh);
        *(uint32_t*)(ylo+r0*DMODEL+col)=pack2(al2,bl);
        split2(o[nt][2]*i1,ah,al2); split2(o[nt][3]*i1,bh,bl);
        *(uint32_t*)(yhi+r1*DMODEL+col)=pack2(ah,bh);
        *(uint32_t*)(ylo+r1*DMODEL+col)=pack2(al2,bl);
    }
}

extern "C" void kernel_launch(void* const* d_in, const int* in_sizes, int n_in,
                              void* d_out, int out_size)
{
    (void)in_sizes;(void)n_in;(void)out_size;
    const int*   idx   =(const int*)  d_in[0];
    const float* wte   =(const float*)d_in[1];
    const float* wpe   =(const float*)d_in[2];
    const float* ln1_w =(const float*)d_in[3];
    const float* ln1_b =(const float*)d_in[4];
    const float* aw    =(const float*)d_in[5];
    const float* ab    =(const float*)d_in[6];
    const float* pw    =(const float*)d_in[7];
    const float* pb    =(const float*)d_in[8];
    const float* ln2_w =(const float*)d_in[9];
    const float* ln2_b =(const float*)d_in[10];
    const float* fw    =(const float*)d_in[11];
    const float* fb    =(const float*)d_in[12];
    const float* ow    =(const float*)d_in[13];
    const float* ob    =(const float*)d_in[14];
    const float* lnf_w =(const float*)d_in[15];
    const float* lnf_b =(const float*)d_in[16];
    float* out=(float*)d_out;

    cudaFuncSetAttribute(attn_tc,  cudaFuncAttributeMaxDynamicSharedMemorySize, AT_SMEM);
    cudaFuncSetAttribute(gemm_mma, cudaFuncAttributeMaxDynamicSharedMemorySize, GSMEM2);

    float *x,*qkv;
    __nv_bfloat16 *hhi,*hlo,*yhi,*ylo,*ffhi,*fflo;
    __nv_bfloat16 *wqh,*wql,*wah,*wal,*wfh,*wfl,*wph,*wpl,*weh,*wel;
    cudaGetSymbolAddress((void**)&x,g_x);       cudaGetSymbolAddress((void**)&qkv,g_qkv);
    cudaGetSymbolAddress((void**)&hhi,g_h_hi);  cudaGetSymbolAddress((void**)&hlo,g_h_lo);
    cudaGetSymbolAddress((void**)&yhi,g_y_hi);  cudaGetSymbolAddress((void**)&ylo,g_y_lo);
    cudaGetSymbolAddress((void**)&ffhi,g_ff_hi);cudaGetSymbolAddress((void**)&fflo,g_ff_lo);
    cudaGetSymbolAddress((void**)&wqh,g_wq_hi); cudaGetSymbolAddress((void**)&wql,g_wq_lo);
    cudaGetSymbolAddress((void**)&wah,g_wa_hi); cudaGetSymbolAddress((void**)&wal,g_wa_lo);
    cudaGetSymbolAddress((void**)&wfh,g_wf_hi); cudaGetSymbolAddress((void**)&wfl,g_wf_lo);
    cudaGetSymbolAddress((void**)&wph,g_wp_hi); cudaGetSymbolAddress((void**)&wpl,g_wp_lo);
    cudaGetSymbolAddress((void**)&weh,g_we_hi); cudaGetSymbolAddress((void**)&wel,g_we_lo);

    dim3 wb(32,8);
    wsplit_t<<<dim3(D3/32,   DMODEL/32, NLAYER), wb>>>(aw, wqh, wql, DMODEL, D3);
    wsplit_t<<<dim3(DMODEL/32,DMODEL/32,NLAYER), wb>>>(pw, wah, wal, DMODEL, DMODEL);
    wsplit_t<<<dim3(FFDIM/32, DMODEL/32,NLAYER), wb>>>(fw, wfh, wfl, DMODEL, FFDIM);
    wsplit_t<<<dim3(DMODEL/32,FFDIM/32, NLAYER), wb>>>(ow, wph, wpl, FFDIM, DMODEL);
    wte_split<<<VOCAB,256>>>(wte, weh, wel);

    embed_kernel<<<BTOK*DMODEL/1024,256>>>(idx, wte, wpe, x);

    for(int l=0;l<NLAYER;l++){
        ln_kernel<<<BTOK,256>>>(x, ln1_w+(size_t)l*DMODEL, ln1_b+(size_t)l*DMODEL, hhi, hlo);
        gemm_mma<<<dim3(D3/128,BTOK/128),256,GSMEM2>>>(
            hhi,hlo, wqh+(size_t)l*DMODEL*D3, wql+(size_t)l*DMODEL*D3,
            ab+(size_t)l*D3, nullptr, qkv, nullptr,nullptr, D3, DMODEL, 0);
        attn_tc<<<dim3(SEQ/64,NHEAD,BATCH),128,AT_SMEM>>>(qkv, yhi, ylo);
        gemm_mma<<<dim3(DMODEL/128,BTOK/128),256,GSMEM2>>>(
            yhi,ylo, wah+(size_t)l*DMODEL*DMODEL, wal+(size_t)l*DMODEL*DMODEL,
            pb+(size_t)l*DMODEL, x, x, nullptr,nullptr, DMODEL, DMODEL, 1);
        ln_kernel<<<BTOK,256>>>(x, ln2_w+(size_t)l*DMODEL, ln2_b+(size_t)l*DMODEL, hhi, hlo);
        gemm_mma<<<dim3(FFDIM/128,BTOK/128),256,GSMEM2>>>(
            hhi,hlo, wfh+(size_t)l*DMODEL*FFDIM, wfl+(size_t)l*DMODEL*FFDIM,
            fb+(size_t)l*FFDIM, nullptr, nullptr, ffhi, fflo, FFDIM, DMODEL, 2);
        gemm_mma<<<dim3(DMODEL/128,BTOK/128),256,GSMEM2>>>(
            ffhi,fflo, wph+(size_t)l*FFDIM*DMODEL, wpl+(size_t)l*FFDIM*DMODEL,
            ob+(size_t)l*DMODEL, x, x, nullptr,nullptr, DMODEL, FFDIM, 1);
    }
    ln_kernel<<<BTOK,256>>>(x, lnf_w, lnf_b, hhi, hlo);
    gemm_mma<<<dim3((VOCAB+127)/128,BTOK/128),256,GSMEM2>>>(
        hhi,hlo, weh, wel, nullptr, nullptr, out, nullptr,nullptr, VOCAB, DMODEL, 3);
}

// round 10
// speedup vs baseline: 2.6230x; 1.0263x over previous
#include <cuda_runtime.h>
#include <cuda_bf16.h>
#include <math.h>
#include <stdint.h>

#define NLAYER 24
#define NHEAD  16
#define DMODEL 1024
#define HDIM   64
#define VOCAB  50257
#define BATCH  2
#define SEQ    1024
#define BTOK   (BATCH*SEQ)
#define FFDIM  4096
#define D3     (3*DMODEL)

__device__ float g_x  [BTOK*DMODEL];
__device__ float g_qkv[BTOK*D3];
__device__ __nv_bfloat16 g_h_hi [BTOK*DMODEL], g_h_lo [BTOK*DMODEL];
__device__ __nv_bfloat16 g_y_hi [BTOK*DMODEL], g_y_lo [BTOK*DMODEL];
__device__ __nv_bfloat16 g_ff_hi[BTOK*FFDIM],  g_ff_lo[BTOK*FFDIM];
__device__ __nv_bfloat16 g_wq_hi[(size_t)NLAYER*DMODEL*D3],     g_wq_lo[(size_t)NLAYER*DMODEL*D3];
__device__ __nv_bfloat16 g_wa_hi[(size_t)NLAYER*DMODEL*DMODEL], g_wa_lo[(size_t)NLAYER*DMODEL*DMODEL];
__device__ __nv_bfloat16 g_wf_hi[(size_t)NLAYER*DMODEL*FFDIM],  g_wf_lo[(size_t)NLAYER*DMODEL*FFDIM];
__device__ __nv_bfloat16 g_wp_hi[(size_t)NLAYER*FFDIM*DMODEL],  g_wp_lo[(size_t)NLAYER*FFDIM*DMODEL];
__device__ __nv_bfloat16 g_we_hi[(size_t)VOCAB*DMODEL],         g_we_lo[(size_t)VOCAB*DMODEL];

__device__ __forceinline__ uint32_t smem_u32(const void* p){
    uint32_t a;
    asm("{ .reg .u64 t; cvta.to.shared.u64 t, %1; cvt.u32.u64 %0, t; }" : "=r"(a) : "l"(p));
    return a;
}
#define LDSM4(r0,r1,r2,r3,a) asm volatile("ldmatrix.sync.aligned.m8n8.x4.shared.b16 {%0,%1,%2,%3},[%4];":"=r"(r0),"=r"(r1),"=r"(r2),"=r"(r3):"r"(a))
#define LDSM2(r0,r1,a)       asm volatile("ldmatrix.sync.aligned.m8n8.x2.shared.b16 {%0,%1},[%2];":"=r"(r0),"=r"(r1):"r"(a))
#define MMA16816(c,a,b) asm volatile( \
    "mma.sync.aligned.m16n8k16.row.col.f32.bf16.bf16.f32 {%0,%1,%2,%3},{%4,%5,%6,%7},{%8,%9},{%0,%1,%2,%3};" \
    :"+f"((c)[0]),"+f"((c)[1]),"+f"((c)[2]),"+f"((c)[3]) \
    :"r"((a)[0]),"r"((a)[1]),"r"((a)[2]),"r"((a)[3]),"r"((b)[0]),"r"((b)[1]))
#define CPASYNC16(sa,gp) asm volatile("cp.async.cg.shared.global [%0],[%1],16;"::"r"(sa),"l"(gp))
#define CPCOMMIT() asm volatile("cp.async.commit_group;":::"memory")
#define CPWAIT0()  asm volatile("cp.async.wait_group 0;":::"memory")

__device__ __forceinline__ float gelu_f(float x){
    float x3=x*x*x;
    return 0.5f*x*(1.f+tanhf(0.7978845608028654f*(x+0.044715f*x3)));
}
__device__ __forceinline__ void split2(float v, __nv_bfloat16&h, __nv_bfloat16&l){
    h=__float2bfloat16(v); l=__float2bfloat16(v-__bfloat162float(h));
}
__device__ __forceinline__ uint32_t pack2(__nv_bfloat16 a, __nv_bfloat16 b){
    return ((uint32_t)__bfloat16_as_ushort(b)<<16)|__bfloat16_as_ushort(a);
}

__global__ __launch_bounds__(256) void embed_kernel(
    const int* __restrict__ idx, const float* __restrict__ wte,
    const float* __restrict__ wpe, float* __restrict__ x)
{
    int i=blockIdx.x*256+threadIdx.x, tok=i>>8, c=i&255, t=tok&(SEQ-1);
    int id=idx[tok];
    float4 a=((const float4*)(wte+(size_t)id*DMODEL))[c];
    float4 p=((const float4*)(wpe+(size_t)t*DMODEL))[c];
    a.x+=p.x; a.y+=p.y; a.z+=p.z; a.w+=p.w;
    ((float4*)x)[i]=a;
}

__global__ __launch_bounds__(256) void ln_kernel(
    const float* __restrict__ x, const float* __restrict__ w, const float* __restrict__ b,
    __nv_bfloat16* __restrict__ ohi, __nv_bfloat16* __restrict__ olo)
{
    int row=blockIdx.x, tid=threadIdx.x;
    float4 v=((const float4*)(x+(size_t)row*DMODEL))[tid];
    float s=v.x+v.y+v.z+v.w, sq=v.x*v.x+v.y*v.y+v.z*v.z+v.w*v.w;
    #pragma unroll
    for(int o=16;o>0;o>>=1){ s+=__shfl_xor_sync(~0u,s,o); sq+=__shfl_xor_sync(~0u,sq,o); }
    __shared__ float ss[8],sqs[8];
    if((tid&31)==0){ ss[tid>>5]=s; sqs[tid>>5]=sq; }
    __syncthreads();
    float st=0,sqt=0;
    #pragma unroll
    for(int i=0;i<8;i++){ st+=ss[i]; sqt+=sqs[i]; }
    float mean=st*(1.f/DMODEL), var=sqt*(1.f/DMODEL)-mean*mean, inv=rsqrtf(var+1e-5f);
    float4 wv=((const float4*)w)[tid], bv=((const float4*)b)[tid];
    float o0=(v.x-mean)*inv*wv.x+bv.x, o1=(v.y-mean)*inv*wv.y+bv.y;
    float o2=(v.z-mean)*inv*wv.z+bv.z, o3=(v.w-mean)*inv*wv.w+bv.w;
    __nv_bfloat16 h0,h1,h2,h3,l0,l1,l2,l3;
    split2(o0,h0,l0); split2(o1,h1,l1); split2(o2,h2,l2); split2(o3,h3,l3);
    size_t base=(size_t)row*DMODEL+tid*4;
    *(uint2*)(ohi+base)=make_uint2(pack2(h0,h1),pack2(h2,h3));
    *(uint2*)(olo+base)=make_uint2(pack2(l0,l1),pack2(l2,l3));
}

__global__ void wsplit_t(const float* __restrict__ W, __nv_bfloat16* __restrict__ hi,
                         __nv_bfloat16* __restrict__ lo, int K, int N)
{
    __shared__ float t[32][33];
    int l=blockIdx.z;
    const float* Wl=W+(size_t)l*K*N;
    __nv_bfloat16* hil=hi+(size_t)l*K*N;
    __nv_bfloat16* lol=lo+(size_t)l*K*N;
    int n0=blockIdx.x*32, k0=blockIdx.y*32, tx=threadIdx.x, ty=threadIdx.y;
    #pragma unroll
    for(int i=0;i<4;i++) t[ty+8*i][tx]=Wl[(size_t)(k0+ty+8*i)*N+n0+tx];
    __syncthreads();
    #pragma unroll
    for(int i=0;i<4;i++){
        float v=t[tx][ty+8*i];
        __nv_bfloat16 h,lw; split2(v,h,lw);
        size_t o=(size_t)(n0+ty+8*i)*K+k0+tx;
        hil[o]=h; lol[o]=lw;
    }
}

__global__ __launch_bounds__(256) void wte_split(
    const float* __restrict__ w, __nv_bfloat16* __restrict__ hi, __nv_bfloat16* __restrict__ lo)
{
    size_t base=(size_t)blockIdx.x*DMODEL+threadIdx.x*4;
    float4 v=*(const float4*)(w+base);
    __nv_bfloat16 h,l;
    split2(v.x,h,l); hi[base]=h;   lo[base]=l;
    split2(v.y,h,l); hi[base+1]=h; lo[base+1]=l;
    split2(v.z,h,l); hi[base+2]=h; lo[base+2]=l;
    split2(v.w,h,l); hi[base+3]=h; lo[base+3]=l;
}

// ---- fused bf16x3 GEMM, single K-loop, cp.async, x4 B-frag loads ---------
// grid: (M/128, N-tiles)  -> bm on x (fastest) so weight tiles stream once.
#define GST   72
#define GSLAB (128*GST)
#define GSLABB (GSLAB*2)
#define GSMEM2 (4*GSLABB)
__global__ __launch_bounds__(256) void gemm_mma(
    const __nv_bfloat16* __restrict__ Ahi, const __nv_bfloat16* __restrict__ Alo,
    const __nv_bfloat16* __restrict__ Bhi, const __nv_bfloat16* __restrict__ Blo,
    const float* __restrict__ bias, const float* __restrict__ res,
    float* __restrict__ Cf, __nv_bfloat16* __restrict__ Chi, __nv_bfloat16* __restrict__ Clo,
    int N, int K, int act)
{
    extern __shared__ __nv_bfloat16 sm2[];
    const uint32_t smA = smem_u32(sm2);
    const uint32_t smB = smA + 2*GSLABB;
    const int tid=threadIdx.x, wid=tid>>5, lane=tid&31;
    const int bm=blockIdx.x*128, bn=blockIdx.y*128;
    const int wm=(wid&3)*32, wn=(wid>>2)*64;
    const int row2=tid>>2, ch=tid&3;

    float acc[2][8][4];
    #pragma unroll
    for(int i=0;i<2;i++)
        #pragma unroll
        for(int j=0;j<8;j++)
            #pragma unroll
            for(int k=0;k<4;k++) acc[i][j][k]=0.f;

    const uint32_t a_base = smA + (uint32_t)(((wm+(lane&15))*GST + (lane>>4)*8)*2);
    // x4 B base: lane>>4 selects n-subtile (+8 rows), (lane>>3)&1 selects k-chunk
    const uint32_t b4_base = smB + (uint32_t)(((wn+(lane&7)+((lane>>4)&1)*8)*GST + ((lane>>3)&1)*8)*2);
    const int KS = K>>5;

    auto load_stage=[&](int c,int buf){
        const size_t gk=(size_t)c*32 + ch*8;
        #pragma unroll
        for(int half=0;half<2;half++){
            int r=row2+half*64;
            uint32_t sa = smA + buf*GSLABB + (uint32_t)((r*GST+ch*8)*2);
            CPASYNC16(sa,    Ahi+(size_t)(bm+r)*K+gk);
            CPASYNC16(sa+64, Alo+(size_t)(bm+r)*K+gk);
            int gn=bn+r; size_t gs=(gn<N)?(size_t)gn:0;
            uint32_t sb = smB + buf*GSLABB + (uint32_t)((r*GST+ch*8)*2);
            CPASYNC16(sb,    Bhi+gs*K+gk);
            CPASYNC16(sb+64, Blo+gs*K+gk);
        }
    };

    load_stage(0,0); CPCOMMIT(); CPWAIT0();
    __syncthreads();

    for(int c=0;c<KS;c++){
        const int buf=c&1;
        if(c+1<KS){ load_stage(c+1,buf^1); CPCOMMIT(); }
        const uint32_t ab=a_base+buf*GSLABB, bb=b4_base+buf*GSLABB;
        #pragma unroll
        for(int ks=0;ks<2;ks++){
            uint32_t Ah[2][4],Al[2][4],Bh[8][2],Bl[8][2];
            #pragma unroll
            for(int mt=0;mt<2;mt++){
                uint32_t ad=ab+mt*(16*GST*2)+ks*32;
                LDSM4(Ah[mt][0],Ah[mt][1],Ah[mt][2],Ah[mt][3], ad);
                LDSM4(Al[mt][0],Al[mt][1],Al[mt][2],Al[mt][3], ad+64);
            }
            #pragma unroll
            for(int np=0;np<4;np++){
                uint32_t bd=bb+np*(16*GST*2)+ks*32;
                LDSM4(Bh[2*np][0],Bh[2*np][1],Bh[2*np+1][0],Bh[2*np+1][1], bd);
                LDSM4(Bl[2*np][0],Bl[2*np][1],Bl[2*np+1][0],Bl[2*np+1][1], bd+64);
            }
            #pragma unroll
            for(int mt=0;mt<2;mt++)
                #pragma unroll
                for(int nt=0;nt<8;nt++)
                    MMA16816(acc[mt][nt], Ah[mt], Bh[nt]);
            #pragma unroll
            for(int mt=0;mt<2;mt++)
                #pragma unroll
                for(int nt=0;nt<8;nt++)
                    MMA16816(acc[mt][nt], Ah[mt], Bl[nt]);
            #pragma unroll
            for(int mt=0;mt<2;mt++)
                #pragma unroll
                for(int nt=0;nt<8;nt++)
                    MMA16816(acc[mt][nt], Al[mt], Bh[nt]);
        }
        if(c+1<KS) CPWAIT0();
        __syncthreads();
    }

    const int g=lane>>2, ct=lane&3;
    #pragma unroll
    for(int mt=0;mt<2;mt++){
        #pragma unroll
        for(int nt=0;nt<8;nt++){
            int r0=bm+wm+mt*16+g, r1=r0+8;
            int col=bn+wn+nt*8+ct*2;
            float c0=acc[mt][nt][0], c1=acc[mt][nt][1];
            float c2=acc[mt][nt][2], c3=acc[mt][nt][3];
            if(act==3){
                if(col<N)   Cf[(size_t)r0*N+col]=c0;
                if(col+1<N) Cf[(size_t)r0*N+col+1]=c1;
                if(col<N)   Cf[(size_t)r1*N+col]=c2;
                if(col+1<N) Cf[(size_t)r1*N+col+1]=c3;
            } else {
                float b0=bias[col], b1=bias[col+1];
                c0+=b0; c1+=b1; c2+=b0; c3+=b1;
                if(act==1){
                    float2 q0=*(const float2*)(res+(size_t)r0*N+col);
                    float2 q1=*(const float2*)(res+(size_t)r1*N+col);
                    c0+=q0.x; c1+=q0.y; c2+=q1.x; c3+=q1.y;
                    *(float2*)(Cf+(size_t)r0*N+col)=make_float2(c0,c1);
                    *(float2*)(Cf+(size_t)r1*N+col)=make_float2(c2,c3);
                } else if(act==0){
                    *(float2*)(Cf+(size_t)r0*N+col)=make_float2(c0,c1);
                    *(float2*)(Cf+(size_t)r1*N+col)=make_float2(c2,c3);
                } else {
                    c0=gelu_f(c0); c1=gelu_f(c1); c2=gelu_f(c2); c3=gelu_f(c3);
                    __nv_bfloat16 h0,h1,h2,h3,l0,l1,l2,l3;
                    split2(c0,h0,l0); split2(c1,h1,l1); split2(c2,h2,l2); split2(c3,h3,l3);
                    *(uint32_t*)(Chi+(size_t)r0*N+col)=pack2(h0,h1);
                    *(uint32_t*)(Clo+(size_t)r0*N+col)=pack2(l0,l1);
                    *(uint32_t*)(Chi+(size_t)r1*N+col)=pack2(h2,h3);
                    *(uint32_t*)(Clo+(size_t)r1*N+col)=pack2(l2,l3);
                }
            }
        }
    }
}

// ---- tensor-core flash attention, fused 3-pass fragment reuse ------------
#define AT_STR 72
#define AT_TILE (64*AT_STR)
#define AT_SMEM (6*AT_TILE*2)
__global__ __launch_bounds__(128) void attn_tc(
    const float* __restrict__ qkv, __nv_bfloat16* __restrict__ yhi, __nv_bfloat16* __restrict__ ylo)
{
    extern __shared__ __nv_bfloat16 sm[];
    __nv_bfloat16 *Qh=sm, *Kh=sm+2*AT_TILE, *Vh=sm+4*AT_TILE;
    const int qb=blockIdx.x, h=blockIdx.y, b=blockIdx.z;
    const int tid=threadIdx.x, wid=tid>>5, lane=tid&31;
    const int q0=qb*64;
    const float* base=qkv+(size_t)b*SEQ*D3;
    const uint32_t dLO = AT_TILE*2;

    #pragma unroll
    for(int i=0;i<8;i++){
        int idx=tid+128*i, r=idx>>4, c=(idx&15)*4;
        float4 v=*(const float4*)(base+(size_t)(q0+r)*D3+h*HDIM+c);
        float f[4]={v.x*0.125f,v.y*0.125f,v.z*0.125f,v.w*0.125f};
        #pragma unroll
        for(int j=0;j<4;j++){
            __nv_bfloat16 hh,ll; split2(f[j],hh,ll);
            Qh[r*AT_STR+c+j]=hh; Qh[AT_TILE+r*AT_STR+c+j]=ll;
        }
    }

    const int g=lane>>2, ct=lane&3;
    float o[8][4];
    #pragma unroll
    for(int nt=0;nt<8;nt++){ o[nt][0]=0.f;o[nt][1]=0.f;o[nt][2]=0.f;o[nt][3]=0.f; }
    float m0=-1e30f,m1=-1e30f,l0=0.f,l1=0.f;

    const uint32_t qa  = smem_u32(Qh) + (uint32_t)(((wid*16+(lane&15))*AT_STR + (lane>>4)*8)*2);
    const uint32_t kb4 = smem_u32(Kh) + (uint32_t)((((lane&7)+((lane>>4)&1)*8)*AT_STR + ((lane>>3)&1)*8)*2);
    const uint32_t vb4 = smem_u32(Vh) + (uint32_t)((((lane&7)+((lane>>4)&1)*8)*AT_STR + ((lane>>3)&1)*8)*2);

    for(int kt=0;kt<=qb;kt++){
        __syncthreads();
        const int ks0=kt*64;
        #pragma unroll
        for(int i=0;i<8;i++){
            int idx=tid+128*i, r=idx>>4, c=(idx&15)*4;
            float4 kv=*(const float4*)(base+(size_t)(ks0+r)*D3+DMODEL+h*HDIM+c);
            float4 vv=*(const float4*)(base+(size_t)(ks0+r)*D3+2*DMODEL+h*HDIM+c);
            float kf[4]={kv.x,kv.y,kv.z,kv.w}, vf[4]={vv.x,vv.y,vv.z,vv.w};
            #pragma unroll
            for(int j=0;j<4;j++){
                __nv_bfloat16 hh,ll;
                split2(kf[j],hh,ll);
                Kh[r*AT_STR+c+j]=hh; Kh[AT_TILE+r*AT_STR+c+j]=ll;
                split2(vf[j],hh,ll);
                Vh[(c+j)*AT_STR+r]=hh; Vh[AT_TILE+(c+j)*AT_STR+r]=ll;
            }
        }
        __syncthreads();

        float S[8][4];
        #pragma unroll
        for(int nt=0;nt<8;nt++){ S[nt][0]=0.f;S[nt][1]=0.f;S[nt][2]=0.f;S[nt][3]=0.f; }
        // QK^T fused: per k16-step load Ah,Al + Kh,Kl frags once
        #pragma unroll
        for(int ks=0;ks<4;ks++){
            uint32_t Aq[4],Alq[4],KhF[8][2],KlF[8][2];
            LDSM4(Aq[0],Aq[1],Aq[2],Aq[3],   qa + ks*32);
            LDSM4(Alq[0],Alq[1],Alq[2],Alq[3], qa + dLO + ks*32);
            #pragma unroll
            for(int np=0;np<4;np++){
                uint32_t kd = kb4 + np*(16*AT_STR*2) + ks*32;
                LDSM4(KhF[2*np][0],KhF[2*np][1],KhF[2*np+1][0],KhF[2*np+1][1], kd);
                LDSM4(KlF[2*np][0],KlF[2*np][1],KlF[2*np+1][0],KlF[2*np+1][1], kd+dLO);
            }
            #pragma unroll
            for(int nt=0;nt<8;nt++) MMA16816(S[nt], Aq, KhF[nt]);
            #pragma unroll
            for(int nt=0;nt<8;nt++) MMA16816(S[nt], Aq, KlF[nt]);
            #pragma unroll
            for(int nt=0;nt<8;nt++) MMA16816(S[nt], Alq, KhF[nt]);
        }
        if(kt==qb){
            const int r0=q0+wid*16+g, r1=r0+8;
            #pragma unroll
            for(int nt=0;nt<8;nt++){
                int c0=ks0+nt*8+ct*2;
                if(c0>r0)   S[nt][0]=-1e30f;
                if(c0+1>r0) S[nt][1]=-1e30f;
                if(c0>r1)   S[nt][2]=-1e30f;
                if(c0+1>r1) S[nt][3]=-1e30f;
            }
        }
        float rm0=-1e30f, rm1=-1e30f;
        #pragma unroll
        for(int nt=0;nt<8;nt++){
            rm0=fmaxf(rm0,fmaxf(S[nt][0],S[nt][1]));
            rm1=fmaxf(rm1,fmaxf(S[nt][2],S[nt][3]));
        }
        rm0=fmaxf(rm0,__shfl_xor_sync(~0u,rm0,1)); rm0=fmaxf(rm0,__shfl_xor_sync(~0u,rm0,2));
        rm1=fmaxf(rm1,__shfl_xor_sync(~0u,rm1,1)); rm1=fmaxf(rm1,__shfl_xor_sync(~0u,rm1,2));
        float mn0=fmaxf(m0,rm0), mn1=fmaxf(m1,rm1);
        float al0=__expf(m0-mn0), al1=__expf(m1-mn1);
        m0=mn0; m1=mn1;
        float rs0=0.f, rs1=0.f;
        uint32_t ph[4][4], pl[4][4];
        #pragma unroll
        for(int j=0;j<8;j++){
            float p0=__expf(S[j][0]-mn0), p1=__expf(S[j][1]-mn0);
            float p2=__expf(S[j][2]-mn1), p3=__expf(S[j][3]-mn1);
            rs0+=p0+p1; rs1+=p2+p3;
            __nv_bfloat16 h0,h1,h2,h3,q0b,q1b,q2b,q3b;
            split2(p0,h0,q0b); split2(p1,h1,q1b); split2(p2,h2,q2b); split2(p3,h3,q3b);
            ph[j>>1][(j&1)*2]  =pack2(h0,h1);
            ph[j>>1][(j&1)*2+1]=pack2(h2,h3);
            pl[j>>1][(j&1)*2]  =pack2(q0b,q1b);
            pl[j>>1][(j&1)*2+1]=pack2(q2b,q3b);
        }
        rs0+=__shfl_xor_sync(~0u,rs0,1); rs0+=__shfl_xor_sync(~0u,rs0,2);
        rs1+=__shfl_xor_sync(~0u,rs1,1); rs1+=__shfl_xor_sync(~0u,rs1,2);
        l0=l0*al0+rs0; l1=l1*al1+rs1;
        #pragma unroll
        for(int nt=0;nt<8;nt++){
            o[nt][0]*=al0; o[nt][1]*=al0; o[nt][2]*=al1; o[nt][3]*=al1;
        }
        // P @ V fused: per kk load Vh,Vl frags once; terms ph·Vh, ph·Vl, pl·Vh
        #pragma unroll
        for(int kk=0;kk<4;kk++){
            uint32_t VhF[8][2],VlF[8][2];
            #pragma unroll
            for(int np=0;np<4;np++){
                uint32_t vd = vb4 + np*(16*AT_STR*2) + kk*32;
                LDSM4(VhF[2*np][0],VhF[2*np][1],VhF[2*np+1][0],VhF[2*np+1][1], vd);
                LDSM4(VlF[2*np][0],VlF[2*np][1],VlF[2*np+1][0],VlF[2*np+1][1], vd+dLO);
            }
            #pragma unroll
            for(int nt=0;nt<8;nt++) MMA16816(o[nt], ph[kk], VhF[nt]);
            #pragma unroll
            for(int nt=0;nt<8;nt++) MMA16816(o[nt], ph[kk], VlF[nt]);
            #pragma unroll
            for(int nt=0;nt<8;nt++) MMA16816(o[nt], pl[kk], VhF[nt]);
        }
    }
    const float i0=1.f/l0, i1=1.f/l1;
    const size_t r0=(size_t)(b*SEQ+q0+wid*16+g), r1=r0+8;
    #pragma unroll
    for(int nt=0;nt<8;nt++){
        int col=h*HDIM+nt*8+ct*2;
        __nv_bfloat16 ah,al2,bh,bl;
        split2(o[nt][0]*i0,ah,al2); split2(o[nt][1]*i0,bh,bl);
        *(uint32_t*)(yhi+r0*DMODEL+col)=pack2(ah,bh);
        *(uint32_t*)(ylo+r0*DMODEL+col)=pack2(al2,bl);
        split2(o[nt][2]*i1,ah,al2); split2(o[nt][3]*i1,bh,bl);
        *(uint32_t*)(yhi+r1*DMODEL+col)=pack2(ah,bh);
        *(uint32_t*)(ylo+r1*DMODEL+col)=pack2(al2,bl);
    }
}

extern "C" void kernel_launch(void* const* d_in, const int* in_sizes, int n_in,
                              void* d_out, int out_size)
{
    (void)in_sizes;(void)n_in;(void)out_size;
    const int*   idx   =(const int*)  d_in[0];
    const float* wte   =(const float*)d_in[1];
    const float* wpe   =(const float*)d_in[2];
    const float* ln1_w =(const float*)d_in[3];
    const float* ln1_b =(const float*)d_in[4];
    const float* aw    =(const float*)d_in[5];
    const float* ab    =(const float*)d_in[6];
    const float* pw    =(const float*)d_in[7];
    const float* pb    =(const float*)d_in[8];
    const float* ln2_w =(const float*)d_in[9];
    const float* ln2_b =(const float*)d_in[10];
    const float* fw    =(const float*)d_in[11];
    const float* fb    =(const float*)d_in[12];
    const float* ow    =(const float*)d_in[13];
    const float* ob    =(const float*)d_in[14];
    const float* lnf_w =(const float*)d_in[15];
    const float* lnf_b =(const float*)d_in[16];
    float* out=(float*)d_out;

    cudaFuncSetAttribute(attn_tc,  cudaFuncAttributeMaxDynamicSharedMemorySize, AT_SMEM);
    cudaFuncSetAttribute(gemm_mma, cudaFuncAttributeMaxDynamicSharedMemorySize, GSMEM2);

    float *x,*qkv;
    __nv_bfloat16 *hhi,*hlo,*yhi,*ylo,*ffhi,*fflo;
    __nv_bfloat16 *wqh,*wql,*wah,*wal,*wfh,*wfl,*wph,*wpl,*weh,*wel;
    cudaGetSymbolAddress((void**)&x,g_x);       cudaGetSymbolAddress((void**)&qkv,g_qkv);
    cudaGetSymbolAddress((void**)&hhi,g_h_hi);  cudaGetSymbolAddress((void**)&hlo,g_h_lo);
    cudaGetSymbolAddress((void**)&yhi,g_y_hi);  cudaGetSymbolAddress((void**)&ylo,g_y_lo);
    cudaGetSymbolAddress((void**)&ffhi,g_ff_hi);cudaGetSymbolAddress((void**)&fflo,g_ff_lo);
    cudaGetSymbolAddress((void**)&wqh,g_wq_hi); cudaGetSymbolAddress((void**)&wql,g_wq_lo);
    cudaGetSymbolAddress((void**)&wah,g_wa_hi); cudaGetSymbolAddress((void**)&wal,g_wa_lo);
    cudaGetSymbolAddress((void**)&wfh,g_wf_hi); cudaGetSymbolAddress((void**)&wfl,g_wf_lo);
    cudaGetSymbolAddress((void**)&wph,g_wp_hi); cudaGetSymbolAddress((void**)&wpl,g_wp_lo);
    cudaGetSymbolAddress((void**)&weh,g_we_hi); cudaGetSymbolAddress((void**)&wel,g_we_lo);

    dim3 wb(32,8);
    wsplit_t<<<dim3(D3/32,   DMODEL/32, NLAYER), wb>>>(aw, wqh, wql, DMODEL, D3);
    wsplit_t<<<dim3(DMODEL/32,DMODEL/32,NLAYER), wb>>>(pw, wah, wal, DMODEL, DMODEL);
    wsplit_t<<<dim3(FFDIM/32, DMODEL/32,NLAYER), wb>>>(fw, wfh, wfl, DMODEL, FFDIM);
    wsplit_t<<<dim3(DMODEL/32,FFDIM/32, NLAYER), wb>>>(ow, wph, wpl, FFDIM, DMODEL);
    wte_split<<<VOCAB,256>>>(wte, weh, wel);

    embed_kernel<<<BTOK*DMODEL/1024,256>>>(idx, wte, wpe, x);

    for(int l=0;l<NLAYER;l++){
        ln_kernel<<<BTOK,256>>>(x, ln1_w+(size_t)l*DMODEL, ln1_b+(size_t)l*DMODEL, hhi, hlo);
        gemm_mma<<<dim3(BTOK/128,D3/128),256,GSMEM2>>>(
            hhi,hlo, wqh+(size_t)l*DMODEL*D3, wql+(size_t)l*DMODEL*D3,
            ab+(size_t)l*D3, nullptr, qkv, nullptr,nullptr, D3, DMODEL, 0);
        attn_tc<<<dim3(SEQ/64,NHEAD,BATCH),128,AT_SMEM>>>(qkv, yhi, ylo);
        gemm_mma<<<dim3(BTOK/128,DMODEL/128),256,GSMEM2>>>(
            yhi,ylo, wah+(size_t)l*DMODEL*DMODEL, wal+(size_t)l*DMODEL*DMODEL,
            pb+(size_t)l*DMODEL, x, x, nullptr,nullptr, DMODEL, DMODEL, 1);
        ln_kernel<<<BTOK,256>>>(x, ln2_w+(size_t)l*DMODEL, ln2_b+(size_t)l*DMODEL, hhi, hlo);
        gemm_mma<<<dim3(BTOK/128,FFDIM/128),256,GSMEM2>>>(
            hhi,hlo, wfh+(size_t)l*DMODEL*FFDIM, wfl+(size_t)l*DMODEL*FFDIM,
            fb+(size_t)l*FFDIM, nullptr, nullptr, ffhi, fflo, FFDIM, DMODEL, 2);
        gemm_mma<<<dim3(BTOK/128,DMODEL/128),256,GSMEM2>>>(
            ffhi,fflo, wph+(size_t)l*FFDIM*DMODEL, wpl+(size_t)l*FFDIM*DMODEL,
            ob+(size_t)l*DMODEL, x, x, nullptr,nullptr, DMODEL, FFDIM, 1);
    }
    ln_kernel<<<BTOK,256>>>(x, lnf_w, lnf_b, hhi, hlo);
    gemm_mma<<<dim3(BTOK/128,(VOCAB+127)/128),256,GSMEM2>>>(
        hhi,hlo, weh, wel, nullptr, nullptr, out, nullptr,nullptr, VOCAB, DMODEL, 3);
}

// round 11
// speedup vs baseline: 3.3383x; 1.2727x over previous
#include <cuda_runtime.h>
#include <cuda_bf16.h>
#include <cuda_fp16.h>
#include <math.h>
#include <stdint.h>

#define NLAYER 24
#define NHEAD  16
#define DMODEL 1024
#define HDIM   64
#define VOCAB  50257
#define BATCH  2
#define SEQ    1024
#define BTOK   (BATCH*SEQ)
#define FFDIM  4096
#define D3     (3*DMODEL)

__device__ float g_x  [BTOK*DMODEL];
__device__ float g_qkv[BTOK*D3];
__device__ __half g_h [BTOK*DMODEL];
__device__ __half g_y [BTOK*DMODEL];
__device__ __half g_ff[BTOK*FFDIM];
__device__ __half g_wq_hi[(size_t)NLAYER*DMODEL*D3],     g_wq_lo[(size_t)NLAYER*DMODEL*D3];
__device__ __half g_wa_hi[(size_t)NLAYER*DMODEL*DMODEL], g_wa_lo[(size_t)NLAYER*DMODEL*DMODEL];
__device__ __half g_wf_hi[(size_t)NLAYER*DMODEL*FFDIM],  g_wf_lo[(size_t)NLAYER*DMODEL*FFDIM];
__device__ __half g_wp_hi[(size_t)NLAYER*FFDIM*DMODEL],  g_wp_lo[(size_t)NLAYER*FFDIM*DMODEL];
__device__ __half g_we_hi[(size_t)VOCAB*DMODEL],         g_we_lo[(size_t)VOCAB*DMODEL];

__device__ __forceinline__ uint32_t smem_u32(const void* p){
    uint32_t a;
    asm("{ .reg .u64 t; cvta.to.shared.u64 t, %1; cvt.u32.u64 %0, t; }" : "=r"(a) : "l"(p));
    return a;
}
#define LDSM4(r0,r1,r2,r3,a) asm volatile("ldmatrix.sync.aligned.m8n8.x4.shared.b16 {%0,%1,%2,%3},[%4];":"=r"(r0),"=r"(r1),"=r"(r2),"=r"(r3):"r"(a))
#define MMA_BF16(c,a,b) asm volatile( \
    "mma.sync.aligned.m16n8k16.row.col.f32.bf16.bf16.f32 {%0,%1,%2,%3},{%4,%5,%6,%7},{%8,%9},{%0,%1,%2,%3};" \
    :"+f"((c)[0]),"+f"((c)[1]),"+f"((c)[2]),"+f"((c)[3]) \
    :"r"((a)[0]),"r"((a)[1]),"r"((a)[2]),"r"((a)[3]),"r"((b)[0]),"r"((b)[1]))
#define MMA_F16(c,a,b) asm volatile( \
    "mma.sync.aligned.m16n8k16.row.col.f32.f16.f16.f32 {%0,%1,%2,%3},{%4,%5,%6,%7},{%8,%9},{%0,%1,%2,%3};" \
    :"+f"((c)[0]),"+f"((c)[1]),"+f"((c)[2]),"+f"((c)[3]) \
    :"r"((a)[0]),"r"((a)[1]),"r"((a)[2]),"r"((a)[3]),"r"((b)[0]),"r"((b)[1]))
#define CPASYNC16(sa,gp) asm volatile("cp.async.cg.shared.global [%0],[%1],16;"::"r"(sa),"l"(gp))
#define CPCOMMIT() asm volatile("cp.async.commit_group;":::"memory")
#define CPWAIT0()  asm volatile("cp.async.wait_group 0;":::"memory")

__device__ __forceinline__ float gelu_f(float x){
    float x3=x*x*x;
    return 0.5f*x*(1.f+tanhf(0.7978845608028654f*(x+0.044715f*x3)));
}
__device__ __forceinline__ void split2(float v, __nv_bfloat16&h, __nv_bfloat16&l){
    h=__float2bfloat16(v); l=__float2bfloat16(v-__bfloat162float(h));
}
__device__ __forceinline__ void split2h(float v, __half&h, __half&l){
    h=__float2half(v); l=__float2half(v-__half2float(h));
}
__device__ __forceinline__ uint32_t pack2(__nv_bfloat16 a, __nv_bfloat16 b){
    return ((uint32_t)__bfloat16_as_ushort(b)<<16)|__bfloat16_as_ushort(a);
}
__device__ __forceinline__ uint32_t pack2h(__half a, __half b){
    return ((uint32_t)__half_as_ushort(b)<<16)|__half_as_ushort(a);
}

__global__ __launch_bounds__(256) void embed_kernel(
    const int* __restrict__ idx, const float* __restrict__ wte,
    const float* __restrict__ wpe, float* __restrict__ x)
{
    int i=blockIdx.x*256+threadIdx.x, tok=i>>8, c=i&255, t=tok&(SEQ-1);
    int id=idx[tok];
    float4 a=((const float4*)(wte+(size_t)id*DMODEL))[c];
    float4 p=((const float4*)(wpe+(size_t)t*DMODEL))[c];
    a.x+=p.x; a.y+=p.y; a.z+=p.z; a.w+=p.w;
    ((float4*)x)[i]=a;
}

__global__ __launch_bounds__(256) void ln_kernel(
    const float* __restrict__ x, const float* __restrict__ w, const float* __restrict__ b,
    __half* __restrict__ oh)
{
    int row=blockIdx.x, tid=threadIdx.x;
    float4 v=((const float4*)(x+(size_t)row*DMODEL))[tid];
    float s=v.x+v.y+v.z+v.w, sq=v.x*v.x+v.y*v.y+v.z*v.z+v.w*v.w;
    #pragma unroll
    for(int o=16;o>0;o>>=1){ s+=__shfl_xor_sync(~0u,s,o); sq+=__shfl_xor_sync(~0u,sq,o); }
    __shared__ float ss[8],sqs[8];
    if((tid&31)==0){ ss[tid>>5]=s; sqs[tid>>5]=sq; }
    __syncthreads();
    float st=0,sqt=0;
    #pragma unroll
    for(int i=0;i<8;i++){ st+=ss[i]; sqt+=sqs[i]; }
    float mean=st*(1.f/DMODEL), var=sqt*(1.f/DMODEL)-mean*mean, inv=rsqrtf(var+1e-5f);
    float4 wv=((const float4*)w)[tid], bv=((const float4*)b)[tid];
    float o0=(v.x-mean)*inv*wv.x+bv.x, o1=(v.y-mean)*inv*wv.y+bv.y;
    float o2=(v.z-mean)*inv*wv.z+bv.z, o3=(v.w-mean)*inv*wv.w+bv.w;
    size_t base=(size_t)row*DMODEL+tid*4;
    *(uint2*)(oh+base)=make_uint2(
        pack2h(__float2half(o0),__float2half(o1)),
        pack2h(__float2half(o2),__float2half(o3)));
}

__global__ void wsplit_t(const float* __restrict__ W, __half* __restrict__ hi,
                         __half* __restrict__ lo, int K, int N)
{
    __shared__ float t[32][33];
    int l=blockIdx.z;
    const float* Wl=W+(size_t)l*K*N;
    __half* hil=hi+(size_t)l*K*N;
    __half* lol=lo+(size_t)l*K*N;
    int n0=blockIdx.x*32, k0=blockIdx.y*32, tx=threadIdx.x, ty=threadIdx.y;
    #pragma unroll
    for(int i=0;i<4;i++) t[ty+8*i][tx]=Wl[(size_t)(k0+ty+8*i)*N+n0+tx];
    __syncthreads();
    #pragma unroll
    for(int i=0;i<4;i++){
        float v=t[tx][ty+8*i];
        __half h,lw; split2h(v,h,lw);
        size_t o=(size_t)(n0+ty+8*i)*K+k0+tx;
        hil[o]=h; lol[o]=lw;
    }
}

__global__ __launch_bounds__(256) void wte_split(
    const float* __restrict__ w, __half* __restrict__ hi, __half* __restrict__ lo)
{
    size_t base=(size_t)blockIdx.x*DMODEL+threadIdx.x*4;
    float4 v=*(const float4*)(w+base);
    __half h,l;
    split2h(v.x,h,l); hi[base]=h;   lo[base]=l;
    split2h(v.y,h,l); hi[base+1]=h; lo[base+1]=l;
    split2h(v.z,h,l); hi[base+2]=h; lo[base+2]=l;
    split2h(v.w,h,l); hi[base+3]=h; lo[base+3]=l;
}

// ---- fp16x2 GEMM: C = A(fp16) * (Bhi+Blo)(fp16 pair)^T, 2 MMA passes ----
// grid (M/128, Ntiles) bm fastest. A slab stride 40, B slab stride 72.
#define GSTA  40
#define GSTB  72
#define ASLABB (128*GSTA*2)
#define BSLABB (128*GSTB*2)
#define GSMEM3 (2*ASLABB+2*BSLABB)
__global__ __launch_bounds__(256) void gemm_mma(
    const __half* __restrict__ A,
    const __half* __restrict__ Bhi, const __half* __restrict__ Blo,
    const float* __restrict__ bias, const float* __restrict__ res,
    float* __restrict__ Cf, __half* __restrict__ Ch,
    int N, int K, int act)
{
    extern __shared__ __half sm2[];
    const uint32_t smA = smem_u32(sm2);
    const uint32_t smB = smA + 2*ASLABB;
    const int tid=threadIdx.x, wid=tid>>5, lane=tid&31;
    const int bm=blockIdx.x*128, bn=blockIdx.y*128;
    const int wm=(wid&3)*32, wn=(wid>>2)*64;
    const int row2=tid>>2, ch=tid&3;

    float acc[2][8][4];
    #pragma unroll
    for(int i=0;i<2;i++)
        #pragma unroll
        for(int j=0;j<8;j++)
            #pragma unroll
            for(int k=0;k<4;k++) acc[i][j][k]=0.f;

    const uint32_t a_base = smA + (uint32_t)(((wm+(lane&15))*GSTA + (lane>>4)*8)*2);
    const uint32_t b4_base = smB + (uint32_t)(((wn+(lane&7)+((lane>>4)&1)*8)*GSTB + ((lane>>3)&1)*8)*2);
    const int KS = K>>5;

    auto load_stage=[&](int c,int buf){
        const size_t gk=(size_t)c*32 + ch*8;
        #pragma unroll
        for(int hf=0;hf<2;hf++){
            int r=row2+hf*64;
            uint32_t sa = smA + buf*ASLABB + (uint32_t)((r*GSTA+ch*8)*2);
            CPASYNC16(sa, A+(size_t)(bm+r)*K+gk);
            int gn=bn+r; size_t gs=(gn<N)?(size_t)gn:0;
            uint32_t sb = smB + buf*BSLABB + (uint32_t)((r*GSTB+ch*8)*2);
            CPASYNC16(sb,    Bhi+gs*K+gk);
            CPASYNC16(sb+64, Blo+gs*K+gk);
        }
    };

    load_stage(0,0); CPCOMMIT(); CPWAIT0();
    __syncthreads();

    for(int c=0;c<KS;c++){
        const int buf=c&1;
        if(c+1<KS){ load_stage(c+1,buf^1); CPCOMMIT(); }
        const uint32_t ab=a_base+buf*ASLABB, bb=b4_base+buf*BSLABB;
        #pragma unroll
        for(int ks=0;ks<2;ks++){
            uint32_t Ah[2][4],Bh[8][2],Bl[8][2];
            #pragma unroll
            for(int mt=0;mt<2;mt++){
                uint32_t ad=ab+mt*(16*GSTA*2)+ks*32;
                LDSM4(Ah[mt][0],Ah[mt][1],Ah[mt][2],Ah[mt][3], ad);
            }
            #pragma unroll
            for(int np=0;np<4;np++){
                uint32_t bd=bb+np*(16*GSTB*2)+ks*32;
                LDSM4(Bh[2*np][0],Bh[2*np][1],Bh[2*np+1][0],Bh[2*np+1][1], bd);
                LDSM4(Bl[2*np][0],Bl[2*np][1],Bl[2*np+1][0],Bl[2*np+1][1], bd+64);
            }
            #pragma unroll
            for(int mt=0;mt<2;mt++)
                #pragma unroll
                for(int nt=0;nt<8;nt++)
                    MMA_F16(acc[mt][nt], Ah[mt], Bh[nt]);
            #pragma unroll
            for(int mt=0;mt<2;mt++)
                #pragma unroll
                for(int nt=0;nt<8;nt++)
                    MMA_F16(acc[mt][nt], Ah[mt], Bl[nt]);
        }
        if(c+1<KS) CPWAIT0();
        __syncthreads();
    }

    const int g=lane>>2, ct=lane&3;
    #pragma unroll
    for(int mt=0;mt<2;mt++){
        #pragma unroll
        for(int nt=0;nt<8;nt++){
            int r0=bm+wm+mt*16+g, r1=r0+8;
            int col=bn+wn+nt*8+ct*2;
            float c0=acc[mt][nt][0], c1=acc[mt][nt][1];
            float c2=acc[mt][nt][2], c3=acc[mt][nt][3];
            if(act==3){
                if(col<N)   Cf[(size_t)r0*N+col]=c0;
                if(col+1<N) Cf[(size_t)r0*N+col+1]=c1;
                if(col<N)   Cf[(size_t)r1*N+col]=c2;
                if(col+1<N) Cf[(size_t)r1*N+col+1]=c3;
            } else {
                float b0=bias[col], b1=bias[col+1];
                c0+=b0; c1+=b1; c2+=b0; c3+=b1;
                if(act==1){
                    float2 q0=*(const float2*)(res+(size_t)r0*N+col);
                    float2 q1=*(const float2*)(res+(size_t)r1*N+col);
                    c0+=q0.x; c1+=q0.y; c2+=q1.x; c3+=q1.y;
                    *(float2*)(Cf+(size_t)r0*N+col)=make_float2(c0,c1);
                    *(float2*)(Cf+(size_t)r1*N+col)=make_float2(c2,c3);
                } else if(act==0){
                    *(float2*)(Cf+(size_t)r0*N+col)=make_float2(c0,c1);
                    *(float2*)(Cf+(size_t)r1*N+col)=make_float2(c2,c3);
                } else { // gelu -> fp16
                    c0=gelu_f(c0); c1=gelu_f(c1); c2=gelu_f(c2); c3=gelu_f(c3);
                    *(uint32_t*)(Ch+(size_t)r0*N+col)=pack2h(__float2half(c0),__float2half(c1));
                    *(uint32_t*)(Ch+(size_t)r1*N+col)=pack2h(__float2half(c2),__float2half(c3));
                }
            }
        }
    }
}

// ---- tensor-core flash attention (bf16x3 internal, fp16 output) ----------
#define AT_STR 72
#define AT_TILE (64*AT_STR)
#define AT_SMEM (6*AT_TILE*2)
__global__ __launch_bounds__(128) void attn_tc(
    const float* __restrict__ qkv, __half* __restrict__ y)
{
    extern __shared__ __nv_bfloat16 sm[];
    __nv_bfloat16 *Qh=sm, *Kh=sm+2*AT_TILE, *Vh=sm+4*AT_TILE;
    const int qb=blockIdx.x, h=blockIdx.y, b=blockIdx.z;
    const int tid=threadIdx.x, wid=tid>>5, lane=tid&31;
    const int q0=qb*64;
    const float* base=qkv+(size_t)b*SEQ*D3;
    const uint32_t dLO = AT_TILE*2;

    #pragma unroll
    for(int i=0;i<8;i++){
        int idx=tid+128*i, r=idx>>4, c=(idx&15)*4;
        float4 v=*(const float4*)(base+(size_t)(q0+r)*D3+h*HDIM+c);
        float f[4]={v.x*0.125f,v.y*0.125f,v.z*0.125f,v.w*0.125f};
        #pragma unroll
        for(int j=0;j<4;j++){
            __nv_bfloat16 hh,ll; split2(f[j],hh,ll);
            Qh[r*AT_STR+c+j]=hh; Qh[AT_TILE+r*AT_STR+c+j]=ll;
        }
    }

    const int g=lane>>2, ct=lane&3;
    float o[8][4];
    #pragma unroll
    for(int nt=0;nt<8;nt++){ o[nt][0]=0.f;o[nt][1]=0.f;o[nt][2]=0.f;o[nt][3]=0.f; }
    float m0=-1e30f,m1=-1e30f,l0=0.f,l1=0.f;

    const uint32_t qa  = smem_u32(Qh) + (uint32_t)(((wid*16+(lane&15))*AT_STR + (lane>>4)*8)*2);
    const uint32_t kb4 = smem_u32(Kh) + (uint32_t)((((lane&7)+((lane>>4)&1)*8)*AT_STR + ((lane>>3)&1)*8)*2);
    const uint32_t vb4 = smem_u32(Vh) + (uint32_t)((((lane&7)+((lane>>4)&1)*8)*AT_STR + ((lane>>3)&1)*8)*2);

    for(int kt=0;kt<=qb;kt++){
        __syncthreads();
        const int ks0=kt*64;
        #pragma unroll
        for(int i=0;i<8;i++){
            int idx=tid+128*i, r=idx>>4, c=(idx&15)*4;
            float4 kv=*(const float4*)(base+(size_t)(ks0+r)*D3+DMODEL+h*HDIM+c);
            float4 vv=*(const float4*)(base+(size_t)(ks0+r)*D3+2*DMODEL+h*HDIM+c);
            float kf[4]={kv.x,kv.y,kv.z,kv.w}, vf[4]={vv.x,vv.y,vv.z,vv.w};
            #pragma unroll
            for(int j=0;j<4;j++){
                __nv_bfloat16 hh,ll;
                split2(kf[j],hh,ll);
                Kh[r*AT_STR+c+j]=hh; Kh[AT_TILE+r*AT_STR+c+j]=ll;
                split2(vf[j],hh,ll);
                Vh[(c+j)*AT_STR+r]=hh; Vh[AT_TILE+(c+j)*AT_STR+r]=ll;
            }
        }
        __syncthreads();

        float S[8][4];
        #pragma unroll
        for(int nt=0;nt<8;nt++){ S[nt][0]=0.f;S[nt][1]=0.f;S[nt][2]=0.f;S[nt][3]=0.f; }
        #pragma unroll
        for(int ks=0;ks<4;ks++){
            uint32_t Aq[4],Alq[4],KhF[8][2],KlF[8][2];
            LDSM4(Aq[0],Aq[1],Aq[2],Aq[3],   qa + ks*32);
            LDSM4(Alq[0],Alq[1],Alq[2],Alq[3], qa + dLO + ks*32);
            #pragma unroll
            for(int np=0;np<4;np++){
                uint32_t kd = kb4 + np*(16*AT_STR*2) + ks*32;
                LDSM4(KhF[2*np][0],KhF[2*np][1],KhF[2*np+1][0],KhF[2*np+1][1], kd);
                LDSM4(KlF[2*np][0],KlF[2*np][1],KlF[2*np+1][0],KlF[2*np+1][1], kd+dLO);
            }
            #pragma unroll
            for(int nt=0;nt<8;nt++) MMA_BF16(S[nt], Aq, KhF[nt]);
            #pragma unroll
            for(int nt=0;nt<8;nt++) MMA_BF16(S[nt], Aq, KlF[nt]);
            #pragma unroll
            for(int nt=0;nt<8;nt++) MMA_BF16(S[nt], Alq, KhF[nt]);
        }
        if(kt==qb){
            const int r0=q0+wid*16+g, r1=r0+8;
            #pragma unroll
            for(int nt=0;nt<8;nt++){
                int c0=ks0+nt*8+ct*2;
                if(c0>r0)   S[nt][0]=-1e30f;
                if(c0+1>r0) S[nt][1]=-1e30f;
                if(c0>r1)   S[nt][2]=-1e30f;
                if(c0+1>r1) S[nt][3]=-1e30f;
            }
        }
        float rm0=-1e30f, rm1=-1e30f;
        #pragma unroll
        for(int nt=0;nt<8;nt++){
            rm0=fmaxf(rm0,fmaxf(S[nt][0],S[nt][1]));
            rm1=fmaxf(rm1,fmaxf(S[nt][2],S[nt][3]));
        }
        rm0=fmaxf(rm0,__shfl_xor_sync(~0u,rm0,1)); rm0=fmaxf(rm0,__shfl_xor_sync(~0u,rm0,2));
        rm1=fmaxf(rm1,__shfl_xor_sync(~0u,rm1,1)); rm1=fmaxf(rm1,__shfl_xor_sync(~0u,rm1,2));
        float mn0=fmaxf(m0,rm0), mn1=fmaxf(m1,rm1);
        float al0=__expf(m0-mn0), al1=__expf(m1-mn1);
        m0=mn0; m1=mn1;
        float rs0=0.f, rs1=0.f;
        uint32_t ph[4][4], pl[4][4];
        #pragma unroll
        for(int j=0;j<8;j++){
            float p0=__expf(S[j][0]-mn0), p1=__expf(S[j][1]-mn0);
            float p2=__expf(S[j][2]-mn1), p3=__expf(S[j][3]-mn1);
            rs0+=p0+p1; rs1+=p2+p3;
            __nv_bfloat16 h0,h1,h2,h3,q0b,q1b,q2b,q3b;
            split2(p0,h0,q0b); split2(p1,h1,q1b); split2(p2,h2,q2b); split2(p3,h3,q3b);
            ph[j>>1][(j&1)*2]  =pack2(h0,h1);
            ph[j>>1][(j&1)*2+1]=pack2(h2,h3);
            pl[j>>1][(j&1)*2]  =pack2(q0b,q1b);
            pl[j>>1][(j&1)*2+1]=pack2(q2b,q3b);
        }
        rs0+=__shfl_xor_sync(~0u,rs0,1); rs0+=__shfl_xor_sync(~0u,rs0,2);
        rs1+=__shfl_xor_sync(~0u,rs1,1); rs1+=__shfl_xor_sync(~0u,rs1,2);
        l0=l0*al0+rs0; l1=l1*al1+rs1;
        #pragma unroll
        for(int nt=0;nt<8;nt++){
            o[nt][0]*=al0; o[nt][1]*=al0; o[nt][2]*=al1; o[nt][3]*=al1;
        }
        #pragma unroll
        for(int kk=0;kk<4;kk++){
            uint32_t VhF[8][2],VlF[8][2];
            #pragma unroll
            for(int np=0;np<4;np++){
                uint32_t vd = vb4 + np*(16*AT_STR*2) + kk*32;
                LDSM4(VhF[2*np][0],VhF[2*np][1],VhF[2*np+1][0],VhF[2*np+1][1], vd);
                LDSM4(VlF[2*np][0],VlF[2*np][1],VlF[2*np+1][0],VlF[2*np+1][1], vd+dLO);
            }
            #pragma unroll
            for(int nt=0;nt<8;nt++) MMA_BF16(o[nt], ph[kk], VhF[nt]);
            #pragma unroll
            for(int nt=0;nt<8;nt++) MMA_BF16(o[nt], ph[kk], VlF[nt]);
            #pragma unroll
            for(int nt=0;nt<8;nt++) MMA_BF16(o[nt], pl[kk], VhF[nt]);
        }
    }
    const float i0=1.f/l0, i1=1.f/l1;
    const size_t r0=(size_t)(b*SEQ+q0+wid*16+g), r1=r0+8;
    #pragma unroll
    for(int nt=0;nt<8;nt++){
        int col=h*HDIM+nt*8+ct*2;
        *(uint32_t*)(y+r0*DMODEL+col)=pack2h(__float2half(o[nt][0]*i0),__float2half(o[nt][1]*i0));
        *(uint32_t*)(y+r1*DMODEL+col)=pack2h(__float2half(o[nt][2]*i1),__float2half(o[nt][3]*i1));
    }
}

extern "C" void kernel_launch(void* const* d_in, const int* in_sizes, int n_in,
                              void* d_out, int out_size)
{
    (void)in_sizes;(void)n_in;(void)out_size;
    const int*   idx   =(const int*)  d_in[0];
    const float* wte   =(const float*)d_in[1];
    const float* wpe   =(const float*)d_in[2];
    const float* ln1_w =(const float*)d_in[3];
    const float* ln1_b =(const float*)d_in[4];
    const float* aw    =(const float*)d_in[5];
    const float* ab    =(const float*)d_in[6];
    const float* pw    =(const float*)d_in[7];
    const float* pb    =(const float*)d_in[8];
    const float* ln2_w =(const float*)d_in[9];
    const float* ln2_b =(const float*)d_in[10];
    const float* fw    =(const float*)d_in[11];
    const float* fb    =(const float*)d_in[12];
    const float* ow    =(const float*)d_in[13];
    const float* ob    =(const float*)d_in[14];
    const float* lnf_w =(const float*)d_in[15];
    const float* lnf_b =(const float*)d_in[16];
    float* out=(float*)d_out;

    cudaFuncSetAttribute(attn_tc,  cudaFuncAttributeMaxDynamicSharedMemorySize, AT_SMEM);
    cudaFuncSetAttribute(gemm_mma, cudaFuncAttributeMaxDynamicSharedMemorySize, GSMEM3);

    float *x,*qkv;
    __half *h,*y,*ff;
    __half *wqh,*wql,*wah,*wal,*wfh,*wfl,*wph,*wpl,*weh,*wel;
    cudaGetSymbolAddress((void**)&x,g_x);    cudaGetSymbolAddress((void**)&qkv,g_qkv);
    cudaGetSymbolAddress((void**)&h,g_h);    cudaGetSymbolAddress((void**)&y,g_y);
    cudaGetSymbolAddress((void**)&ff,g_ff);
    cudaGetSymbolAddress((void**)&wqh,g_wq_hi); cudaGetSymbolAddress((void**)&wql,g_wq_lo);
    cudaGetSymbolAddress((void**)&wah,g_wa_hi); cudaGetSymbolAddress((void**)&wal,g_wa_lo);
    cudaGetSymbolAddress((void**)&wfh,g_wf_hi); cudaGetSymbolAddress((void**)&wfl,g_wf_lo);
    cudaGetSymbolAddress((void**)&wph,g_wp_hi); cudaGetSymbolAddress((void**)&wpl,g_wp_lo);
    cudaGetSymbolAddress((void**)&weh,g_we_hi); cudaGetSymbolAddress((void**)&wel,g_we_lo);

    dim3 wb(32,8);
    wsplit_t<<<dim3(D3/32,   DMODEL/32, NLAYER), wb>>>(aw, wqh, wql, DMODEL, D3);
    wsplit_t<<<dim3(DMODEL/32,DMODEL/32,NLAYER), wb>>>(pw, wah, wal, DMODEL, DMODEL);
    wsplit_t<<<dim3(FFDIM/32, DMODEL/32,NLAYER), wb>>>(fw, wfh, wfl, DMODEL, FFDIM);
    wsplit_t<<<dim3(DMODEL/32,FFDIM/32, NLAYER), wb>>>(ow, wph, wpl, FFDIM, DMODEL);
    wte_split<<<VOCAB,256>>>(wte, weh, wel);

    embed_kernel<<<BTOK*DMODEL/1024,256>>>(idx, wte, wpe, x);

    for(int l=0;l<NLAYER;l++){
        ln_kernel<<<BTOK,256>>>(x, ln1_w+(size_t)l*DMODEL, ln1_b+(size_t)l*DMODEL, h);
        gemm_mma<<<dim3(BTOK/128,D3/128),256,GSMEM3>>>(
            h, wqh+(size_t)l*DMODEL*D3, wql+(size_t)l*DMODEL*D3,
            ab+(size_t)l*D3, nullptr, qkv, nullptr, D3, DMODEL, 0);
        attn_tc<<<dim3(SEQ/64,NHEAD,BATCH),128,AT_SMEM>>>(qkv, y);
        gemm_mma<<<dim3(BTOK/128,DMODEL/128),256,GSMEM3>>>(
            y, wah+(size_t)l*DMODEL*DMODEL, wal+(size_t)l*DMODEL*DMODEL,
            pb+(size_t)l*DMODEL, x, x, nullptr, DMODEL, DMODEL, 1);
        ln_kernel<<<BTOK,256>>>(x, ln2_w+(size_t)l*DMODEL, ln2_b+(size_t)l*DMODEL, h);
        gemm_mma<<<dim3(BTOK/128,FFDIM/128),256,GSMEM3>>>(
            h, wfh+(size_t)l*DMODEL*FFDIM, wfl+(size_t)l*DMODEL*FFDIM,
            fb+(size_t)l*FFDIM, nullptr, nullptr, ff, FFDIM, DMODEL, 2);
        gemm_mma<<<dim3(BTOK/128,DMODEL/128),256,GSMEM3>>>(
            ff, wph+(size_t)l*FFDIM*DMODEL, wpl+(size_t)l*FFDIM*DMODEL,
            ob+(size_t)l*DMODEL, x, x, nullptr, DMODEL, FFDIM, 1);
    }
    ln_kernel<<<BTOK,256>>>(x, lnf_w, lnf_b, h);
    gemm_mma<<<dim3(BTOK/128,(VOCAB+127)/128),256,GSMEM3>>>(
        h, weh, wel, nullptr, nullptr, out, nullptr, VOCAB, DMODEL, 3);
}

// round 12
// speedup vs baseline: 3.5538x; 1.0646x over previous
#include <cuda_runtime.h>
#include <cuda_fp16.h>
#include <math.h>
#include <stdint.h>

#define NLAYER 24
#define NHEAD  16
#define DMODEL 1024
#define HDIM   64
#define VOCAB  50257
#define BATCH  2
#define SEQ    1024
#define BTOK   (BATCH*SEQ)
#define FFDIM  4096
#define D3     (3*DMODEL)

__device__ float g_x  [BTOK*DMODEL];
__device__ __half g_qkv[BTOK*D3];
__device__ __half g_h [BTOK*DMODEL];
__device__ __half g_y [BTOK*DMODEL];
__device__ __half g_ff[BTOK*FFDIM];
__device__ __half g_wq_hi[(size_t)NLAYER*DMODEL*D3],     g_wq_lo[(size_t)NLAYER*DMODEL*D3];
__device__ __half g_wa_hi[(size_t)NLAYER*DMODEL*DMODEL], g_wa_lo[(size_t)NLAYER*DMODEL*DMODEL];
__device__ __half g_wf_hi[(size_t)NLAYER*DMODEL*FFDIM],  g_wf_lo[(size_t)NLAYER*DMODEL*FFDIM];
__device__ __half g_wp_hi[(size_t)NLAYER*FFDIM*DMODEL],  g_wp_lo[(size_t)NLAYER*FFDIM*DMODEL];
__device__ __half g_we_hi[(size_t)VOCAB*DMODEL],         g_we_lo[(size_t)VOCAB*DMODEL];

__device__ __forceinline__ uint32_t smem_u32(const void* p){
    uint32_t a;
    asm("{ .reg .u64 t; cvta.to.shared.u64 t, %1; cvt.u32.u64 %0, t; }" : "=r"(a) : "l"(p));
    return a;
}
#define LDSM4(r0,r1,r2,r3,a) asm volatile("ldmatrix.sync.aligned.m8n8.x4.shared.b16 {%0,%1,%2,%3},[%4];":"=r"(r0),"=r"(r1),"=r"(r2),"=r"(r3):"r"(a))
#define MMA_F16(c,a,b) asm volatile( \
    "mma.sync.aligned.m16n8k16.row.col.f32.f16.f16.f32 {%0,%1,%2,%3},{%4,%5,%6,%7},{%8,%9},{%0,%1,%2,%3};" \
    :"+f"((c)[0]),"+f"((c)[1]),"+f"((c)[2]),"+f"((c)[3]) \
    :"r"((a)[0]),"r"((a)[1]),"r"((a)[2]),"r"((a)[3]),"r"((b)[0]),"r"((b)[1]))
#define CPASYNC16(sa,gp) asm volatile("cp.async.cg.shared.global [%0],[%1],16;"::"r"(sa),"l"(gp))
#define CPCOMMIT() asm volatile("cp.async.commit_group;":::"memory")
#define CPWAIT0()  asm volatile("cp.async.wait_group 0;":::"memory")

__device__ __forceinline__ float gelu_f(float x){
    float x3=x*x*x;
    return 0.5f*x*(1.f+tanhf(0.7978845608028654f*(x+0.044715f*x3)));
}
__device__ __forceinline__ void split2h(float v, __half&h, __half&l){
    h=__float2half(v); l=__float2half(v-__half2float(h));
}
__device__ __forceinline__ uint32_t pack2h(__half a, __half b){
    return ((uint32_t)__half_as_ushort(b)<<16)|__half_as_ushort(a);
}

__global__ __launch_bounds__(256) void embed_kernel(
    const int* __restrict__ idx, const float* __restrict__ wte,
    const float* __restrict__ wpe, float* __restrict__ x)
{
    int i=blockIdx.x*256+threadIdx.x, tok=i>>8, c=i&255, t=tok&(SEQ-1);
    int id=idx[tok];
    float4 a=((const float4*)(wte+(size_t)id*DMODEL))[c];
    float4 p=((const float4*)(wpe+(size_t)t*DMODEL))[c];
    a.x+=p.x; a.y+=p.y; a.z+=p.z; a.w+=p.w;
    ((float4*)x)[i]=a;
}

__global__ __launch_bounds__(256) void ln_kernel(
    const float* __restrict__ x, const float* __restrict__ w, const float* __restrict__ b,
    __half* __restrict__ oh)
{
    int row=blockIdx.x, tid=threadIdx.x;
    float4 v=((const float4*)(x+(size_t)row*DMODEL))[tid];
    float s=v.x+v.y+v.z+v.w, sq=v.x*v.x+v.y*v.y+v.z*v.z+v.w*v.w;
    #pragma unroll
    for(int o=16;o>0;o>>=1){ s+=__shfl_xor_sync(~0u,s,o); sq+=__shfl_xor_sync(~0u,sq,o); }
    __shared__ float ss[8],sqs[8];
    if((tid&31)==0){ ss[tid>>5]=s; sqs[tid>>5]=sq; }
    __syncthreads();
    float st=0,sqt=0;
    #pragma unroll
    for(int i=0;i<8;i++){ st+=ss[i]; sqt+=sqs[i]; }
    float mean=st*(1.f/DMODEL), var=sqt*(1.f/DMODEL)-mean*mean, inv=rsqrtf(var+1e-5f);
    float4 wv=((const float4*)w)[tid], bv=((const float4*)b)[tid];
    float o0=(v.x-mean)*inv*wv.x+bv.x, o1=(v.y-mean)*inv*wv.y+bv.y;
    float o2=(v.z-mean)*inv*wv.z+bv.z, o3=(v.w-mean)*inv*wv.w+bv.w;
    size_t base=(size_t)row*DMODEL+tid*4;
    *(uint2*)(oh+base)=make_uint2(
        pack2h(__float2half(o0),__float2half(o1)),
        pack2h(__float2half(o2),__float2half(o3)));
}

__global__ void wsplit_t(const float* __restrict__ W, __half* __restrict__ hi,
                         __half* __restrict__ lo, int K, int N)
{
    __shared__ float t[32][33];
    int l=blockIdx.z;
    const float* Wl=W+(size_t)l*K*N;
    __half* hil=hi+(size_t)l*K*N;
    __half* lol=lo+(size_t)l*K*N;
    int n0=blockIdx.x*32, k0=blockIdx.y*32, tx=threadIdx.x, ty=threadIdx.y;
    #pragma unroll
    for(int i=0;i<4;i++) t[ty+8*i][tx]=Wl[(size_t)(k0+ty+8*i)*N+n0+tx];
    __syncthreads();
    #pragma unroll
    for(int i=0;i<4;i++){
        float v=t[tx][ty+8*i];
        __half h,lw; split2h(v,h,lw);
        size_t o=(size_t)(n0+ty+8*i)*K+k0+tx;
        hil[o]=h; lol[o]=lw;
    }
}

__global__ __launch_bounds__(256) void wte_split(
    const float* __restrict__ w, __half* __restrict__ hi, __half* __restrict__ lo)
{
    size_t base=(size_t)blockIdx.x*DMODEL+threadIdx.x*4;
    float4 v=*(const float4*)(w+base);
    __half h,l;
    split2h(v.x,h,l); hi[base]=h;   lo[base]=l;
    split2h(v.y,h,l); hi[base+1]=h; lo[base+1]=l;
    split2h(v.z,h,l); hi[base+2]=h; lo[base+2]=l;
    split2h(v.w,h,l); hi[base+3]=h; lo[base+3]=l;
}

// ---- fp16x2 GEMM: C = A(fp16) * (Bhi+Blo)(fp16 pair)^T, 2 MMA passes ----
// act 0: bias->f32  1: bias+res->f32  2: bias+gelu->fp16  3: plain guarded f32
// act 4: bias->fp16 with 0.125 scale on cols<DMODEL (qkv output)
#define GSTA  40
#define GSTB  72
#define ASLABB (128*GSTA*2)
#define BSLABB (128*GSTB*2)
#define GSMEM3 (2*ASLABB+2*BSLABB)
__global__ __launch_bounds__(256) void gemm_mma(
    const __half* __restrict__ A,
    const __half* __restrict__ Bhi, const __half* __restrict__ Blo,
    const float* __restrict__ bias, const float* __restrict__ res,
    float* __restrict__ Cf, __half* __restrict__ Ch,
    int N, int K, int act)
{
    extern __shared__ __half sm2[];
    const uint32_t smA = smem_u32(sm2);
    const uint32_t smB = smA + 2*ASLABB;
    const int tid=threadIdx.x, wid=tid>>5, lane=tid&31;
    const int bm=blockIdx.x*128, bn=blockIdx.y*128;
    const int wm=(wid&3)*32, wn=(wid>>2)*64;
    const int row2=tid>>2, ch=tid&3;

    float acc[2][8][4];
    #pragma unroll
    for(int i=0;i<2;i++)
        #pragma unroll
        for(int j=0;j<8;j++)
            #pragma unroll
            for(int k=0;k<4;k++) acc[i][j][k]=0.f;

    const uint32_t a_base = smA + (uint32_t)(((wm+(lane&15))*GSTA + (lane>>4)*8)*2);
    const uint32_t b4_base = smB + (uint32_t)(((wn+(lane&7)+((lane>>4)&1)*8)*GSTB + ((lane>>3)&1)*8)*2);
    const int KS = K>>5;

    auto load_stage=[&](int c,int buf){
        const size_t gk=(size_t)c*32 + ch*8;
        #pragma unroll
        for(int hf=0;hf<2;hf++){
            int r=row2+hf*64;
            uint32_t sa = smA + buf*ASLABB + (uint32_t)((r*GSTA+ch*8)*2);
            CPASYNC16(sa, A+(size_t)(bm+r)*K+gk);
            int gn=bn+r; size_t gs=(gn<N)?(size_t)gn:0;
            uint32_t sb = smB + buf*BSLABB + (uint32_t)((r*GSTB+ch*8)*2);
            CPASYNC16(sb,    Bhi+gs*K+gk);
            CPASYNC16(sb+64, Blo+gs*K+gk);
        }
    };

    load_stage(0,0); CPCOMMIT(); CPWAIT0();
    __syncthreads();

    for(int c=0;c<KS;c++){
        const int buf=c&1;
        if(c+1<KS){ load_stage(c+1,buf^1); CPCOMMIT(); }
        const uint32_t ab=a_base+buf*ASLABB, bb=b4_base+buf*BSLABB;
        #pragma unroll
        for(int ks=0;ks<2;ks++){
            uint32_t Ah[2][4],Bh[8][2],Bl[8][2];
            #pragma unroll
            for(int mt=0;mt<2;mt++){
                uint32_t ad=ab+mt*(16*GSTA*2)+ks*32;
                LDSM4(Ah[mt][0],Ah[mt][1],Ah[mt][2],Ah[mt][3], ad);
            }
            #pragma unroll
            for(int np=0;np<4;np++){
                uint32_t bd=bb+np*(16*GSTB*2)+ks*32;
                LDSM4(Bh[2*np][0],Bh[2*np][1],Bh[2*np+1][0],Bh[2*np+1][1], bd);
                LDSM4(Bl[2*np][0],Bl[2*np][1],Bl[2*np+1][0],Bl[2*np+1][1], bd+64);
            }
            #pragma unroll
            for(int mt=0;mt<2;mt++)
                #pragma unroll
                for(int nt=0;nt<8;nt++)
                    MMA_F16(acc[mt][nt], Ah[mt], Bh[nt]);
            #pragma unroll
            for(int mt=0;mt<2;mt++)
                #pragma unroll
                for(int nt=0;nt<8;nt++)
                    MMA_F16(acc[mt][nt], Ah[mt], Bl[nt]);
        }
        if(c+1<KS) CPWAIT0();
        __syncthreads();
    }

    const int g=lane>>2, ct=lane&3;
    #pragma unroll
    for(int mt=0;mt<2;mt++){
        #pragma unroll
        for(int nt=0;nt<8;nt++){
            int r0=bm+wm+mt*16+g, r1=r0+8;
            int col=bn+wn+nt*8+ct*2;
            float c0=acc[mt][nt][0], c1=acc[mt][nt][1];
            float c2=acc[mt][nt][2], c3=acc[mt][nt][3];
            if(act==3){
                if(col<N)   Cf[(size_t)r0*N+col]=c0;
                if(col+1<N) Cf[(size_t)r0*N+col+1]=c1;
                if(col<N)   Cf[(size_t)r1*N+col]=c2;
                if(col+1<N) Cf[(size_t)r1*N+col+1]=c3;
            } else {
                float b0=bias[col], b1=bias[col+1];
                c0+=b0; c1+=b1; c2+=b0; c3+=b1;
                if(act==1){
                    float2 q0=*(const float2*)(res+(size_t)r0*N+col);
                    float2 q1=*(const float2*)(res+(size_t)r1*N+col);
                    c0+=q0.x; c1+=q0.y; c2+=q1.x; c3+=q1.y;
                    *(float2*)(Cf+(size_t)r0*N+col)=make_float2(c0,c1);
                    *(float2*)(Cf+(size_t)r1*N+col)=make_float2(c2,c3);
                } else if(act==0){
                    *(float2*)(Cf+(size_t)r0*N+col)=make_float2(c0,c1);
                    *(float2*)(Cf+(size_t)r1*N+col)=make_float2(c2,c3);
                } else if(act==4){
                    float sc=(col<DMODEL)?0.125f:1.f;
                    *(uint32_t*)(Ch+(size_t)r0*N+col)=pack2h(__float2half(c0*sc),__float2half(c1*sc));
                    *(uint32_t*)(Ch+(size_t)r1*N+col)=pack2h(__float2half(c2*sc),__float2half(c3*sc));
                } else { // act==2 gelu -> fp16
                    c0=gelu_f(c0); c1=gelu_f(c1); c2=gelu_f(c2); c3=gelu_f(c3);
                    *(uint32_t*)(Ch+(size_t)r0*N+col)=pack2h(__float2half(c0),__float2half(c1));
                    *(uint32_t*)(Ch+(size_t)r1*N+col)=pack2h(__float2half(c2),__float2half(c3));
                }
            }
        }
    }
}

// ---- fp16 single-pass tensor-core flash attention ------------------------
// qkv is fp16 with Q pre-scaled. Q,K copied; V transposed during staging.
#define AT_STR 72
#define AT_TILE (64*AT_STR)
#define AT_SMEM (3*AT_TILE*2)
__global__ __launch_bounds__(128) void attn_tc(
    const __half* __restrict__ qkv, __half* __restrict__ y)
{
    extern __shared__ __half sma[];
    __half *Qs=sma, *Ks=sma+AT_TILE, *Vt=sma+2*AT_TILE;
    const int qb=blockIdx.x, h=blockIdx.y, b=blockIdx.z;
    const int tid=threadIdx.x, wid=tid>>5, lane=tid&31;
    const int q0=qb*64;
    const __half* base=qkv+(size_t)b*SEQ*D3;

    // stage Q (64 rows x 64 halves)
    #pragma unroll
    for(int i=0;i<4;i++){
        int idx=tid+128*i, r=idx>>3, ch=idx&7;
        uint4 v=*(const uint4*)(base+(size_t)(q0+r)*D3+h*HDIM+ch*8);
        *(uint4*)(Qs+r*AT_STR+ch*8)=v;
    }

    const int g=lane>>2, ct=lane&3;
    float o[8][4];
    #pragma unroll
    for(int nt=0;nt<8;nt++){ o[nt][0]=0.f;o[nt][1]=0.f;o[nt][2]=0.f;o[nt][3]=0.f; }
    float m0=-1e30f,m1=-1e30f,l0=0.f,l1=0.f;

    const uint32_t qa  = smem_u32(Qs) + (uint32_t)(((wid*16+(lane&15))*AT_STR + (lane>>4)*8)*2);
    const uint32_t kb4 = smem_u32(Ks) + (uint32_t)((((lane&7)+((lane>>4)&1)*8)*AT_STR + ((lane>>3)&1)*8)*2);
    const uint32_t vb4 = smem_u32(Vt) + (uint32_t)((((lane&7)+((lane>>4)&1)*8)*AT_STR + ((lane>>3)&1)*8)*2);

    for(int kt=0;kt<=qb;kt++){
        __syncthreads();
        const int ks0=kt*64;
        #pragma unroll
        for(int i=0;i<4;i++){   // K copy
            int idx=tid+128*i, r=idx>>3, ch=idx&7;
            uint4 v=*(const uint4*)(base+(size_t)(ks0+r)*D3+DMODEL+h*HDIM+ch*8);
            *(uint4*)(Ks+r*AT_STR+ch*8)=v;
        }
        #pragma unroll
        for(int i=0;i<8;i++){   // V transpose
            int idx=tid+128*i, r=idx>>4, c=(idx&15)*4;
            uint2 v=*(const uint2*)(base+(size_t)(ks0+r)*D3+2*DMODEL+h*HDIM+c);
            const __half* pv=(const __half*)&v;
            Vt[(c+0)*AT_STR+r]=pv[0]; Vt[(c+1)*AT_STR+r]=pv[1];
            Vt[(c+2)*AT_STR+r]=pv[2]; Vt[(c+3)*AT_STR+r]=pv[3];
        }
        __syncthreads();

        float S[8][4];
        #pragma unroll
        for(int nt=0;nt<8;nt++){ S[nt][0]=0.f;S[nt][1]=0.f;S[nt][2]=0.f;S[nt][3]=0.f; }
        #pragma unroll
        for(int ks=0;ks<4;ks++){
            uint32_t Aq[4],KF[8][2];
            LDSM4(Aq[0],Aq[1],Aq[2],Aq[3], qa + ks*32);
            #pragma unroll
            for(int np=0;np<4;np++){
                uint32_t kd = kb4 + np*(16*AT_STR*2) + ks*32;
                LDSM4(KF[2*np][0],KF[2*np][1],KF[2*np+1][0],KF[2*np+1][1], kd);
            }
            #pragma unroll
            for(int nt=0;nt<8;nt++) MMA_F16(S[nt], Aq, KF[nt]);
        }
        if(kt==qb){
            const int r0=q0+wid*16+g, r1=r0+8;
            #pragma unroll
            for(int nt=0;nt<8;nt++){
                int c0=ks0+nt*8+ct*2;
                if(c0>r0)   S[nt][0]=-1e30f;
                if(c0+1>r0) S[nt][1]=-1e30f;
                if(c0>r1)   S[nt][2]=-1e30f;
                if(c0+1>r1) S[nt][3]=-1e30f;
            }
        }
        float rm0=-1e30f, rm1=-1e30f;
        #pragma unroll
        for(int nt=0;nt<8;nt++){
            rm0=fmaxf(rm0,fmaxf(S[nt][0],S[nt][1]));
            rm1=fmaxf(rm1,fmaxf(S[nt][2],S[nt][3]));
        }
        rm0=fmaxf(rm0,__shfl_xor_sync(~0u,rm0,1)); rm0=fmaxf(rm0,__shfl_xor_sync(~0u,rm0,2));
        rm1=fmaxf(rm1,__shfl_xor_sync(~0u,rm1,1)); rm1=fmaxf(rm1,__shfl_xor_sync(~0u,rm1,2));
        float mn0=fmaxf(m0,rm0), mn1=fmaxf(m1,rm1);
        float al0=__expf(m0-mn0), al1=__expf(m1-mn1);
        m0=mn0; m1=mn1;
        float rs0=0.f, rs1=0.f;
        uint32_t ph[4][4];
        #pragma unroll
        for(int j=0;j<8;j++){
            float p0=__expf(S[j][0]-mn0), p1=__expf(S[j][1]-mn0);
            float p2=__expf(S[j][2]-mn1), p3=__expf(S[j][3]-mn1);
            rs0+=p0+p1; rs1+=p2+p3;
            ph[j>>1][(j&1)*2]  =pack2h(__float2half(p0),__float2half(p1));
            ph[j>>1][(j&1)*2+1]=pack2h(__float2half(p2),__float2half(p3));
        }
        rs0+=__shfl_xor_sync(~0u,rs0,1); rs0+=__shfl_xor_sync(~0u,rs0,2);
        rs1+=__shfl_xor_sync(~0u,rs1,1); rs1+=__shfl_xor_sync(~0u,rs1,2);
        l0=l0*al0+rs0; l1=l1*al1+rs1;
        #pragma unroll
        for(int nt=0;nt<8;nt++){
            o[nt][0]*=al0; o[nt][1]*=al0; o[nt][2]*=al1; o[nt][3]*=al1;
        }
        #pragma unroll
        for(int kk=0;kk<4;kk++){
            uint32_t VF[8][2];
            #pragma unroll
            for(int np=0;np<4;np++){
                uint32_t vd = vb4 + np*(16*AT_STR*2) + kk*32;
                LDSM4(VF[2*np][0],VF[2*np][1],VF[2*np+1][0],VF[2*np+1][1], vd);
            }
            #pragma unroll
            for(int nt=0;nt<8;nt++) MMA_F16(o[nt], ph[kk], VF[nt]);
        }
    }
    const float i0=1.f/l0, i1=1.f/l1;
    const size_t r0=(size_t)(b*SEQ+q0+wid*16+g), r1=r0+8;
    #pragma unroll
    for(int nt=0;nt<8;nt++){
        int col=h*HDIM+nt*8+ct*2;
        *(uint32_t*)(y+r0*DMODEL+col)=pack2h(__float2half(o[nt][0]*i0),__float2half(o[nt][1]*i0));
        *(uint32_t*)(y+r1*DMODEL+col)=pack2h(__float2half(o[nt][2]*i1),__float2half(o[nt][3]*i1));
    }
}

extern "C" void kernel_launch(void* const* d_in, const int* in_sizes, int n_in,
                              void* d_out, int out_size)
{
    (void)in_sizes;(void)n_in;(void)out_size;
    const int*   idx   =(const int*)  d_in[0];
    const float* wte   =(const float*)d_in[1];
    const float* wpe   =(const float*)d_in[2];
    const float* ln1_w =(const float*)d_in[3];
    const float* ln1_b =(const float*)d_in[4];
    const float* aw    =(const float*)d_in[5];
    const float* ab    =(const float*)d_in[6];
    const float* pw    =(const float*)d_in[7];
    const float* pb    =(const float*)d_in[8];
    const float* ln2_w =(const float*)d_in[9];
    const float* ln2_b =(const float*)d_in[10];
    const float* fw    =(const float*)d_in[11];
    const float* fb    =(const float*)d_in[12];
    const float* ow    =(const float*)d_in[13];
    const float* ob    =(const float*)d_in[14];
    const float* lnf_w =(const float*)d_in[15];
    const float* lnf_b =(const float*)d_in[16];
    float* out=(float*)d_out;

    cudaFuncSetAttribute(attn_tc,  cudaFuncAttributeMaxDynamicSharedMemorySize, AT_SMEM);
    cudaFuncSetAttribute(gemm_mma, cudaFuncAttributeMaxDynamicSharedMemorySize, GSMEM3);

    float *x;
    __half *qkv,*h,*y,*ff;
    __half *wqh,*wql,*wah,*wal,*wfh,*wfl,*wph,*wpl,*weh,*wel;
    cudaGetSymbolAddress((void**)&x,g_x);    cudaGetSymbolAddress((void**)&qkv,g_qkv);
    cudaGetSymbolAddress((void**)&h,g_h);    cudaGetSymbolAddress((void**)&y,g_y);
    cudaGetSymbolAddress((void**)&ff,g_ff);
    cudaGetSymbolAddress((void**)&wqh,g_wq_hi); cudaGetSymbolAddress((void**)&wql,g_wq_lo);
    cudaGetSymbolAddress((void**)&wah,g_wa_hi); cudaGetSymbolAddress((void**)&wal,g_wa_lo);
    cudaGetSymbolAddress((void**)&wfh,g_wf_hi); cudaGetSymbolAddress((void**)&wfl,g_wf_lo);
    cudaGetSymbolAddress((void**)&wph,g_wp_hi); cudaGetSymbolAddress((void**)&wpl,g_wp_lo);
    cudaGetSymbolAddress((void**)&weh,g_we_hi); cudaGetSymbolAddress((void**)&wel,g_we_lo);

    dim3 wb(32,8);
    wsplit_t<<<dim3(D3/32,   DMODEL/32, NLAYER), wb>>>(aw, wqh, wql, DMODEL, D3);
    wsplit_t<<<dim3(DMODEL/32,DMODEL/32,NLAYER), wb>>>(pw, wah, wal, DMODEL, DMODEL);
    wsplit_t<<<dim3(FFDIM/32, DMODEL/32,NLAYER), wb>>>(fw, wfh, wfl, DMODEL, FFDIM);
    wsplit_t<<<dim3(DMODEL/32,FFDIM/32, NLAYER), wb>>>(ow, wph, wpl, FFDIM, DMODEL);
    wte_split<<<VOCAB,256>>>(wte, weh, wel);

    embed_kernel<<<BTOK*DMODEL/1024,256>>>(idx, wte, wpe, x);

    for(int l=0;l<NLAYER;l++){
        ln_kernel<<<BTOK,256>>>(x, ln1_w+(size_t)l*DMODEL, ln1_b+(size_t)l*DMODEL, h);
        gemm_mma<<<dim3(BTOK/128,D3/128),256,GSMEM3>>>(
            h, wqh+(size_t)l*DMODEL*D3, wql+(size_t)l*DMODEL*D3,
            ab+(size_t)l*D3, nullptr, nullptr, qkv, D3, DMODEL, 4);
        attn_tc<<<dim3(SEQ/64,NHEAD,BATCH),128,AT_SMEM>>>(qkv, y);
        gemm_mma<<<dim3(BTOK/128,DMODEL/128),256,GSMEM3>>>(
            y, wah+(size_t)l*DMODEL*DMODEL, wal+(size_t)l*DMODEL*DMODEL,
            pb+(size_t)l*DMODEL, x, x, nullptr, DMODEL, DMODEL, 1);
        ln_kernel<<<BTOK,256>>>(x, ln2_w+(size_t)l*DMODEL, ln2_b+(size_t)l*DMODEL, h);
        gemm_mma<<<dim3(BTOK/128,FFDIM/128),256,GSMEM3>>>(
            h, wfh+(size_t)l*DMODEL*FFDIM, wfl+(size_t)l*DMODEL*FFDIM,
            fb+(size_t)l*FFDIM, nullptr, nullptr, ff, FFDIM, DMODEL, 2);
        gemm_mma<<<dim3(BTOK/128,DMODEL/128),256,GSMEM3>>>(
            ff, wph+(size_t)l*FFDIM*DMODEL, wpl+(size_t)l*FFDIM*DMODEL,
            ob+(size_t)l*DMODEL, x, x, nullptr, DMODEL, FFDIM, 1);
    }
    ln_kernel<<<BTOK,256>>>(x, lnf_w, lnf_b, h);
    gemm_mma<<<dim3(BTOK/128,(VOCAB+127)/128),256,GSMEM3>>>(
        h, weh, wel, nullptr, nullptr, out, nullptr, VOCAB, DMODEL, 3);
}

// round 13
// speedup vs baseline: 4.0511x; 1.1399x over previous
#include <cuda_runtime.h>
#include <cuda_fp16.h>
#include <math.h>
#include <stdint.h>

#define NLAYER 24
#define NHEAD  16
#define DMODEL 1024
#define HDIM   64
#define VOCAB  50257
#define BATCH  2
#define SEQ    1024
#define BTOK   (BATCH*SEQ)
#define FFDIM  4096
#define D3     (3*DMODEL)

__device__ float g_x  [BTOK*DMODEL];
__device__ __half g_qkv[BTOK*D3];
__device__ __half g_h [BTOK*DMODEL];
__device__ __half g_y [BTOK*DMODEL];
__device__ __half g_ff[BTOK*FFDIM];
__device__ __half g_wq_hi[(size_t)NLAYER*DMODEL*D3],     g_wq_lo[(size_t)NLAYER*DMODEL*D3];
__device__ __half g_wa_hi[(size_t)NLAYER*DMODEL*DMODEL], g_wa_lo[(size_t)NLAYER*DMODEL*DMODEL];
__device__ __half g_wf_hi[(size_t)NLAYER*DMODEL*FFDIM],  g_wf_lo[(size_t)NLAYER*DMODEL*FFDIM];
__device__ __half g_wp_hi[(size_t)NLAYER*FFDIM*DMODEL],  g_wp_lo[(size_t)NLAYER*FFDIM*DMODEL];
__device__ __half g_we_hi[(size_t)VOCAB*DMODEL],         g_we_lo[(size_t)VOCAB*DMODEL];

__device__ __forceinline__ uint32_t smem_u32(const void* p){
    uint32_t a;
    asm("{ .reg .u64 t; cvta.to.shared.u64 t, %1; cvt.u32.u64 %0, t; }" : "=r"(a) : "l"(p));
    return a;
}
#define LDSM4(r0,r1,r2,r3,a) asm volatile("ldmatrix.sync.aligned.m8n8.x4.shared.b16 {%0,%1,%2,%3},[%4];":"=r"(r0),"=r"(r1),"=r"(r2),"=r"(r3):"r"(a))
#define MMA_F16(c,a,b) asm volatile( \
    "mma.sync.aligned.m16n8k16.row.col.f32.f16.f16.f32 {%0,%1,%2,%3},{%4,%5,%6,%7},{%8,%9},{%0,%1,%2,%3};" \
    :"+f"((c)[0]),"+f"((c)[1]),"+f"((c)[2]),"+f"((c)[3]) \
    :"r"((a)[0]),"r"((a)[1]),"r"((a)[2]),"r"((a)[3]),"r"((b)[0]),"r"((b)[1]))
#define CPASYNC16(sa,gp) asm volatile("cp.async.cg.shared.global [%0],[%1],16;"::"r"(sa),"l"(gp))
#define CPCOMMIT() asm volatile("cp.async.commit_group;":::"memory")
#define CPWAIT0()  asm volatile("cp.async.wait_group 0;":::"memory")

__device__ __forceinline__ float gelu_f(float x){
    float x3=x*x*x;
    return 0.5f*x*(1.f+tanhf(0.7978845608028654f*(x+0.044715f*x3)));
}
__device__ __forceinline__ void split2h(float v, __half&h, __half&l){
    h=__float2half(v); l=__float2half(v-__half2float(h));
}
__device__ __forceinline__ uint32_t pack2h(__half a, __half b){
    return ((uint32_t)__half_as_ushort(b)<<16)|__half_as_ushort(a);
}

__global__ __launch_bounds__(256) void embed_kernel(
    const int* __restrict__ idx, const float* __restrict__ wte,
    const float* __restrict__ wpe, float* __restrict__ x)
{
    int i=blockIdx.x*256+threadIdx.x, tok=i>>8, c=i&255, t=tok&(SEQ-1);
    int id=idx[tok];
    float4 a=((const float4*)(wte+(size_t)id*DMODEL))[c];
    float4 p=((const float4*)(wpe+(size_t)t*DMODEL))[c];
    a.x+=p.x; a.y+=p.y; a.z+=p.z; a.w+=p.w;
    ((float4*)x)[i]=a;
}

__global__ __launch_bounds__(256) void ln_kernel(
    const float* __restrict__ x, const float* __restrict__ w, const float* __restrict__ b,
    __half* __restrict__ oh)
{
    int row=blockIdx.x, tid=threadIdx.x;
    float4 v=((const float4*)(x+(size_t)row*DMODEL))[tid];
    float s=v.x+v.y+v.z+v.w, sq=v.x*v.x+v.y*v.y+v.z*v.z+v.w*v.w;
    #pragma unroll
    for(int o=16;o>0;o>>=1){ s+=__shfl_xor_sync(~0u,s,o); sq+=__shfl_xor_sync(~0u,sq,o); }
    __shared__ float ss[8],sqs[8];
    if((tid&31)==0){ ss[tid>>5]=s; sqs[tid>>5]=sq; }
    __syncthreads();
    float st=0,sqt=0;
    #pragma unroll
    for(int i=0;i<8;i++){ st+=ss[i]; sqt+=sqs[i]; }
    float mean=st*(1.f/DMODEL), var=sqt*(1.f/DMODEL)-mean*mean, inv=rsqrtf(var+1e-5f);
    float4 wv=((const float4*)w)[tid], bv=((const float4*)b)[tid];
    float o0=(v.x-mean)*inv*wv.x+bv.x, o1=(v.y-mean)*inv*wv.y+bv.y;
    float o2=(v.z-mean)*inv*wv.z+bv.z, o3=(v.w-mean)*inv*wv.w+bv.w;
    size_t base=(size_t)row*DMODEL+tid*4;
    *(uint2*)(oh+base)=make_uint2(
        pack2h(__float2half(o0),__float2half(o1)),
        pack2h(__float2half(o2),__float2half(o3)));
}

__global__ void wsplit_t(const float* __restrict__ W, __half* __restrict__ hi,
                         __half* __restrict__ lo, int K, int N)
{
    __shared__ float t[32][33];
    int l=blockIdx.z;
    const float* Wl=W+(size_t)l*K*N;
    __half* hil=hi+(size_t)l*K*N;
    __half* lol=lo+(size_t)l*K*N;
    int n0=blockIdx.x*32, k0=blockIdx.y*32, tx=threadIdx.x, ty=threadIdx.y;
    #pragma unroll
    for(int i=0;i<4;i++) t[ty+8*i][tx]=Wl[(size_t)(k0+ty+8*i)*N+n0+tx];
    __syncthreads();
    #pragma unroll
    for(int i=0;i<4;i++){
        float v=t[tx][ty+8*i];
        __half h,lw; split2h(v,h,lw);
        size_t o=(size_t)(n0+ty+8*i)*K+k0+tx;
        hil[o]=h; lol[o]=lw;
    }
}

__global__ __launch_bounds__(256) void wte_split(
    const float* __restrict__ w, __half* __restrict__ hi, __half* __restrict__ lo)
{
    size_t base=(size_t)blockIdx.x*DMODEL+threadIdx.x*4;
    float4 v=*(const float4*)(w+base);
    __half h,l;
    split2h(v.x,h,l); hi[base]=h;   lo[base]=l;
    split2h(v.y,h,l); hi[base+1]=h; lo[base+1]=l;
    split2h(v.z,h,l); hi[base+2]=h; lo[base+2]=l;
    split2h(v.w,h,l); hi[base+3]=h; lo[base+3]=l;
}

// ---- fp16 GEMM: C = A(fp16) * (Bhi[+Blo])(fp16)^T, 1 or 2 MMA passes ----
// Blo==nullptr -> single pass. occupancy 2 CTAs/SM.
// act 0: bias->f32  1: bias+res->f32  2: bias+gelu->fp16  3: plain guarded f32
// act 4: bias->fp16 with 0.125 scale on cols<DMODEL (qkv output)
#define GSTA  40
#define GSTB  72
#define ASLABB (128*GSTA*2)
#define BSLABB (128*GSTB*2)
#define GSMEM3 (2*ASLABB+2*BSLABB)
__global__ __launch_bounds__(256,2) void gemm_mma(
    const __half* __restrict__ A,
    const __half* __restrict__ Bhi, const __half* __restrict__ Blo,
    const float* __restrict__ bias, const float* __restrict__ res,
    float* __restrict__ Cf, __half* __restrict__ Ch,
    int N, int K, int act)
{
    extern __shared__ __half sm2[];
    const uint32_t smA = smem_u32(sm2);
    const uint32_t smB = smA + 2*ASLABB;
    const int tid=threadIdx.x, wid=tid>>5, lane=tid&31;
    const int bm=blockIdx.x*128, bn=blockIdx.y*128;
    const int wm=(wid&3)*32, wn=(wid>>2)*64;
    const int row2=tid>>2, ch=tid&3;
    const bool twop = (Blo!=nullptr);

    float acc[2][8][4];
    #pragma unroll
    for(int i=0;i<2;i++)
        #pragma unroll
        for(int j=0;j<8;j++)
            #pragma unroll
            for(int k=0;k<4;k++) acc[i][j][k]=0.f;

    const uint32_t a_base = smA + (uint32_t)(((wm+(lane&15))*GSTA + (lane>>4)*8)*2);
    const uint32_t b4_base = smB + (uint32_t)(((wn+(lane&7)+((lane>>4)&1)*8)*GSTB + ((lane>>3)&1)*8)*2);
    const int KS = K>>5;

    auto load_stage=[&](int c,int buf){
        const size_t gk=(size_t)c*32 + ch*8;
        #pragma unroll
        for(int hf=0;hf<2;hf++){
            int r=row2+hf*64;
            uint32_t sa = smA + buf*ASLABB + (uint32_t)((r*GSTA+ch*8)*2);
            CPASYNC16(sa, A+(size_t)(bm+r)*K+gk);
            int gn=bn+r; size_t gs=(gn<N)?(size_t)gn:0;
            uint32_t sb = smB + buf*BSLABB + (uint32_t)((r*GSTB+ch*8)*2);
            CPASYNC16(sb, Bhi+gs*K+gk);
            if(twop) CPASYNC16(sb+64, Blo+gs*K+gk);
        }
    };

    load_stage(0,0); CPCOMMIT(); CPWAIT0();
    __syncthreads();

    for(int c=0;c<KS;c++){
        const int buf=c&1;
        if(c+1<KS){ load_stage(c+1,buf^1); CPCOMMIT(); }
        const uint32_t ab=a_base+buf*ASLABB, bb=b4_base+buf*BSLABB;
        #pragma unroll
        for(int ks=0;ks<2;ks++){
            uint32_t Ah[2][4],Bh[8][2];
            #pragma unroll
            for(int mt=0;mt<2;mt++){
                uint32_t ad=ab+mt*(16*GSTA*2)+ks*32;
                LDSM4(Ah[mt][0],Ah[mt][1],Ah[mt][2],Ah[mt][3], ad);
            }
            #pragma unroll
            for(int np=0;np<4;np++){
                uint32_t bd=bb+np*(16*GSTB*2)+ks*32;
                LDSM4(Bh[2*np][0],Bh[2*np][1],Bh[2*np+1][0],Bh[2*np+1][1], bd);
            }
            #pragma unroll
            for(int mt=0;mt<2;mt++)
                #pragma unroll
                for(int nt=0;nt<8;nt++)
                    MMA_F16(acc[mt][nt], Ah[mt], Bh[nt]);
            if(twop){
                uint32_t Bl[8][2];
                #pragma unroll
                for(int np=0;np<4;np++){
                    uint32_t bd=bb+np*(16*GSTB*2)+ks*32;
                    LDSM4(Bl[2*np][0],Bl[2*np][1],Bl[2*np+1][0],Bl[2*np+1][1], bd+64);
                }
                #pragma unroll
                for(int mt=0;mt<2;mt++)
                    #pragma unroll
                    for(int nt=0;nt<8;nt++)
                        MMA_F16(acc[mt][nt], Ah[mt], Bl[nt]);
            }
        }
        if(c+1<KS) CPWAIT0();
        __syncthreads();
    }

    const int g=lane>>2, ct=lane&3;
    #pragma unroll
    for(int mt=0;mt<2;mt++){
        #pragma unroll
        for(int nt=0;nt<8;nt++){
            int r0=bm+wm+mt*16+g, r1=r0+8;
            int col=bn+wn+nt*8+ct*2;
            float c0=acc[mt][nt][0], c1=acc[mt][nt][1];
            float c2=acc[mt][nt][2], c3=acc[mt][nt][3];
            if(act==3){
                if(col<N)   Cf[(size_t)r0*N+col]=c0;
                if(col+1<N) Cf[(size_t)r0*N+col+1]=c1;
                if(col<N)   Cf[(size_t)r1*N+col]=c2;
                if(col+1<N) Cf[(size_t)r1*N+col+1]=c3;
            } else {
                float b0=bias[col], b1=bias[col+1];
                c0+=b0; c1+=b1; c2+=b0; c3+=b1;
                if(act==1){
                    float2 q0=*(const float2*)(res+(size_t)r0*N+col);
                    float2 q1=*(const float2*)(res+(size_t)r1*N+col);
                    c0+=q0.x; c1+=q0.y; c2+=q1.x; c3+=q1.y;
                    *(float2*)(Cf+(size_t)r0*N+col)=make_float2(c0,c1);
                    *(float2*)(Cf+(size_t)r1*N+col)=make_float2(c2,c3);
                } else if(act==0){
                    *(float2*)(Cf+(size_t)r0*N+col)=make_float2(c0,c1);
                    *(float2*)(Cf+(size_t)r1*N+col)=make_float2(c2,c3);
                } else if(act==4){
                    float sc=(col<DMODEL)?0.125f:1.f;
                    *(uint32_t*)(Ch+(size_t)r0*N+col)=pack2h(__float2half(c0*sc),__float2half(c1*sc));
                    *(uint32_t*)(Ch+(size_t)r1*N+col)=pack2h(__float2half(c2*sc),__float2half(c3*sc));
                } else { // act==2 gelu -> fp16
                    c0=gelu_f(c0); c1=gelu_f(c1); c2=gelu_f(c2); c3=gelu_f(c3);
                    *(uint32_t*)(Ch+(size_t)r0*N+col)=pack2h(__float2half(c0),__float2half(c1));
                    *(uint32_t*)(Ch+(size_t)r1*N+col)=pack2h(__float2half(c2),__float2half(c3));
                }
            }
        }
    }
}

// ---- fp16 single-pass tensor-core flash attention ------------------------
#define AT_STR 72
#define AT_TILE (64*AT_STR)
#define AT_SMEM (3*AT_TILE*2)
__global__ __launch_bounds__(128) void attn_tc(
    const __half* __restrict__ qkv, __half* __restrict__ y)
{
    extern __shared__ __half sma[];
    __half *Qs=sma, *Ks=sma+AT_TILE, *Vt=sma+2*AT_TILE;
    const int qb=blockIdx.x, h=blockIdx.y, b=blockIdx.z;
    const int tid=threadIdx.x, wid=tid>>5, lane=tid&31;
    const int q0=qb*64;
    const __half* base=qkv+(size_t)b*SEQ*D3;

    #pragma unroll
    for(int i=0;i<4;i++){
        int idx=tid+128*i, r=idx>>3, ch=idx&7;
        uint4 v=*(const uint4*)(base+(size_t)(q0+r)*D3+h*HDIM+ch*8);
        *(uint4*)(Qs+r*AT_STR+ch*8)=v;
    }

    const int g=lane>>2, ct=lane&3;
    float o[8][4];
    #pragma unroll
    for(int nt=0;nt<8;nt++){ o[nt][0]=0.f;o[nt][1]=0.f;o[nt][2]=0.f;o[nt][3]=0.f; }
    float m0=-1e30f,m1=-1e30f,l0=0.f,l1=0.f;

    const uint32_t qa  = smem_u32(Qs) + (uint32_t)(((wid*16+(lane&15))*AT_STR + (lane>>4)*8)*2);
    const uint32_t kb4 = smem_u32(Ks) + (uint32_t)((((lane&7)+((lane>>4)&1)*8)*AT_STR + ((lane>>3)&1)*8)*2);
    const uint32_t vb4 = smem_u32(Vt) + (uint32_t)((((lane&7)+((lane>>4)&1)*8)*AT_STR + ((lane>>3)&1)*8)*2);

    for(int kt=0;kt<=qb;kt++){
        __syncthreads();
        const int ks0=kt*64;
        #pragma unroll
        for(int i=0;i<4;i++){
            int idx=tid+128*i, r=idx>>3, ch=idx&7;
            uint4 v=*(const uint4*)(base+(size_t)(ks0+r)*D3+DMODEL+h*HDIM+ch*8);
            *(uint4*)(Ks+r*AT_STR+ch*8)=v;
        }
        #pragma unroll
        for(int i=0;i<8;i++){
            int idx=tid+128*i, r=idx>>4, c=(idx&15)*4;
            uint2 v=*(const uint2*)(base+(size_t)(ks0+r)*D3+2*DMODEL+h*HDIM+c);
            const __half* pv=(const __half*)&v;
            Vt[(c+0)*AT_STR+r]=pv[0]; Vt[(c+1)*AT_STR+r]=pv[1];
            Vt[(c+2)*AT_STR+r]=pv[2]; Vt[(c+3)*AT_STR+r]=pv[3];
        }
        __syncthreads();

        float S[8][4];
        #pragma unroll
        for(int nt=0;nt<8;nt++){ S[nt][0]=0.f;S[nt][1]=0.f;S[nt][2]=0.f;S[nt][3]=0.f; }
        #pragma unroll
        for(int ks=0;ks<4;ks++){
            uint32_t Aq[4],KF[8][2];
            LDSM4(Aq[0],Aq[1],Aq[2],Aq[3], qa + ks*32);
            #pragma unroll
            for(int np=0;np<4;np++){
                uint32_t kd = kb4 + np*(16*AT_STR*2) + ks*32;
                LDSM4(KF[2*np][0],KF[2*np][1],KF[2*np+1][0],KF[2*np+1][1], kd);
            }
            #pragma unroll
            for(int nt=0;nt<8;nt++) MMA_F16(S[nt], Aq, KF[nt]);
        }
        if(kt==qb){
            const int r0=q0+wid*16+g, r1=r0+8;
            #pragma unroll
            for(int nt=0;nt<8;nt++){
                int c0=ks0+nt*8+ct*2;
                if(c0>r0)   S[nt][0]=-1e30f;
                if(c0+1>r0) S[nt][1]=-1e30f;
                if(c0>r1)   S[nt][2]=-1e30f;
                if(c0+1>r1) S[nt][3]=-1e30f;
            }
        }
        float rm0=-1e30f, rm1=-1e30f;
        #pragma unroll
        for(int nt=0;nt<8;nt++){
            rm0=fmaxf(rm0,fmaxf(S[nt][0],S[nt][1]));
            rm1=fmaxf(rm1,fmaxf(S[nt][2],S[nt][3]));
        }
        rm0=fmaxf(rm0,__shfl_xor_sync(~0u,rm0,1)); rm0=fmaxf(rm0,__shfl_xor_sync(~0u,rm0,2));
        rm1=fmaxf(rm1,__shfl_xor_sync(~0u,rm1,1)); rm1=fmaxf(rm1,__shfl_xor_sync(~0u,rm1,2));
        float mn0=fmaxf(m0,rm0), mn1=fmaxf(m1,rm1);
        float al0=__expf(m0-mn0), al1=__expf(m1-mn1);
        m0=mn0; m1=mn1;
        float rs0=0.f, rs1=0.f;
        uint32_t ph[4][4];
        #pragma unroll
        for(int j=0;j<8;j++){
            float p0=__expf(S[j][0]-mn0), p1=__expf(S[j][1]-mn0);
            float p2=__expf(S[j][2]-mn1), p3=__expf(S[j][3]-mn1);
            rs0+=p0+p1; rs1+=p2+p3;
            ph[j>>1][(j&1)*2]  =pack2h(__float2half(p0),__float2half(p1));
            ph[j>>1][(j&1)*2+1]=pack2h(__float2half(p2),__float2half(p3));
        }
        rs0+=__shfl_xor_sync(~0u,rs0,1); rs0+=__shfl_xor_sync(~0u,rs0,2);
        rs1+=__shfl_xor_sync(~0u,rs1,1); rs1+=__shfl_xor_sync(~0u,rs1,2);
        l0=l0*al0+rs0; l1=l1*al1+rs1;
        #pragma unroll
        for(int nt=0;nt<8;nt++){
            o[nt][0]*=al0; o[nt][1]*=al0; o[nt][2]*=al1; o[nt][3]*=al1;
        }
        #pragma unroll
        for(int kk=0;kk<4;kk++){
            uint32_t VF[8][2];
            #pragma unroll
            for(int np=0;np<4;np++){
                uint32_t vd = vb4 + np*(16*AT_STR*2) + kk*32;
                LDSM4(VF[2*np][0],VF[2*np][1],VF[2*np+1][0],VF[2*np+1][1], vd);
            }
            #pragma unroll
            for(int nt=0;nt<8;nt++) MMA_F16(o[nt], ph[kk], VF[nt]);
        }
    }
    const float i0=1.f/l0, i1=1.f/l1;
    const size_t r0=(size_t)(b*SEQ+q0+wid*16+g), r1=r0+8;
    #pragma unroll
    for(int nt=0;nt<8;nt++){
        int col=h*HDIM+nt*8+ct*2;
        *(uint32_t*)(y+r0*DMODEL+col)=pack2h(__float2half(o[nt][0]*i0),__float2half(o[nt][1]*i0));
        *(uint32_t*)(y+r1*DMODEL+col)=pack2h(__float2half(o[nt][2]*i1),__float2half(o[nt][3]*i1));
    }
}

extern "C" void kernel_launch(void* const* d_in, const int* in_sizes, int n_in,
                              void* d_out, int out_size)
{
    (void)in_sizes;(void)n_in;(void)out_size;
    const int*   idx   =(const int*)  d_in[0];
    const float* wte   =(const float*)d_in[1];
    const float* wpe   =(const float*)d_in[2];
    const float* ln1_w =(const float*)d_in[3];
    const float* ln1_b =(const float*)d_in[4];
    const float* aw    =(const float*)d_in[5];
    const float* ab    =(const float*)d_in[6];
    const float* pw    =(const float*)d_in[7];
    const float* pb    =(const float*)d_in[8];
    const float* ln2_w =(const float*)d_in[9];
    const float* ln2_b =(const float*)d_in[10];
    const float* fw    =(const float*)d_in[11];
    const float* fb    =(const float*)d_in[12];
    const float* ow    =(const float*)d_in[13];
    const float* ob    =(const float*)d_in[14];
    const float* lnf_w =(const float*)d_in[15];
    const float* lnf_b =(const float*)d_in[16];
    float* out=(float*)d_out;

    cudaFuncSetAttribute(attn_tc,  cudaFuncAttributeMaxDynamicSharedMemorySize, AT_SMEM);
    cudaFuncSetAttribute(gemm_mma, cudaFuncAttributeMaxDynamicSharedMemorySize, GSMEM3);

    float *x;
    __half *qkv,*h,*y,*ff;
    __half *wqh,*wql,*wah,*wal,*wfh,*wfl,*wph,*wpl,*weh,*wel;
    cudaGetSymbolAddress((void**)&x,g_x);    cudaGetSymbolAddress((void**)&qkv,g_qkv);
    cudaGetSymbolAddress((void**)&h,g_h);    cudaGetSymbolAddress((void**)&y,g_y);
    cudaGetSymbolAddress((void**)&ff,g_ff);
    cudaGetSymbolAddress((void**)&wqh,g_wq_hi); cudaGetSymbolAddress((void**)&wql,g_wq_lo);
    cudaGetSymbolAddress((void**)&wah,g_wa_hi); cudaGetSymbolAddress((void**)&wal,g_wa_lo);
    cudaGetSymbolAddress((void**)&wfh,g_wf_hi); cudaGetSymbolAddress((void**)&wfl,g_wf_lo);
    cudaGetSymbolAddress((void**)&wph,g_wp_hi); cudaGetSymbolAddress((void**)&wpl,g_wp_lo);
    cudaGetSymbolAddress((void**)&weh,g_we_hi); cudaGetSymbolAddress((void**)&wel,g_we_lo);

    dim3 wb(32,8);
    wsplit_t<<<dim3(D3/32,   DMODEL/32, NLAYER), wb>>>(aw, wqh, wql, DMODEL, D3);
    wsplit_t<<<dim3(DMODEL/32,DMODEL/32,NLAYER), wb>>>(pw, wah, wal, DMODEL, DMODEL);
    wsplit_t<<<dim3(FFDIM/32, DMODEL/32,NLAYER), wb>>>(fw, wfh, wfl, DMODEL, FFDIM);
    wsplit_t<<<dim3(DMODEL/32,FFDIM/32, NLAYER), wb>>>(ow, wph, wpl, FFDIM, DMODEL);
    wte_split<<<VOCAB,256>>>(wte, weh, wel);

    embed_kernel<<<BTOK*DMODEL/1024,256>>>(idx, wte, wpe, x);

    for(int l=0;l<NLAYER;l++){
        ln_kernel<<<BTOK,256>>>(x, ln1_w+(size_t)l*DMODEL, ln1_b+(size_t)l*DMODEL, h);
        gemm_mma<<<dim3(BTOK/128,D3/128),256,GSMEM3>>>(
            h, wqh+(size_t)l*DMODEL*D3, wql+(size_t)l*DMODEL*D3,
            ab+(size_t)l*D3, nullptr, nullptr, qkv, D3, DMODEL, 4);
        attn_tc<<<dim3(SEQ/64,NHEAD,BATCH),128,AT_SMEM>>>(qkv, y);
        gemm_mma<<<dim3(BTOK/128,DMODEL/128),256,GSMEM3>>>(
            y, wah+(size_t)l*DMODEL*DMODEL, wal+(size_t)l*DMODEL*DMODEL,
            pb+(size_t)l*DMODEL, x, x, nullptr, DMODEL, DMODEL, 1);
        ln_kernel<<<BTOK,256>>>(x, ln2_w+(size_t)l*DMODEL, ln2_b+(size_t)l*DMODEL, h);
        gemm_mma<<<dim3(BTOK/128,FFDIM/128),256,GSMEM3>>>(
            h, wfh+(size_t)l*DMODEL*FFDIM, wfl+(size_t)l*DMODEL*FFDIM,
            fb+(size_t)l*FFDIM, nullptr, nullptr, ff, FFDIM, DMODEL, 2);
        gemm_mma<<<dim3(BTOK/128,DMODEL/128),256,GSMEM3>>>(
            ff, wph+(size_t)l*FFDIM*DMODEL, wpl+(size_t)l*FFDIM*DMODEL,
            ob+(size_t)l*DMODEL, x, x, nullptr, DMODEL, FFDIM, 1);
    }
    ln_kernel<<<BTOK,256>>>(x, lnf_w, lnf_b, h);
    // LM head: single-pass fp16 (Blo = nullptr)
    gemm_mma<<<dim3(BTOK/128,(VOCAB+127)/128),256,GSMEM3>>>(
        h, weh, nullptr, nullptr, nullptr, out, nullptr, VOCAB, DMODEL, 3);
}

// round 15
// speedup vs baseline: 5.5625x; 1.3731x over previous
#include <cuda_runtime.h>
#include <cuda_fp16.h>
#include <math.h>
#include <stdint.h>

#define NLAYER 24
#define NHEAD  16
#define DMODEL 1024
#define HDIM   64
#define VOCAB  50257
#define BATCH  2
#define SEQ    1024
#define BTOK   (BATCH*SEQ)
#define FFDIM  4096
#define D3     (3*DMODEL)

__device__ float g_x  [BTOK*DMODEL];
__device__ __half g_qkv[BTOK*D3];
__device__ __half g_h [BTOK*DMODEL];
__device__ __half g_y [BTOK*DMODEL];
__device__ __half g_ff[BTOK*FFDIM];
__device__ __half g_wq[(size_t)NLAYER*DMODEL*D3];
__device__ __half g_wa[(size_t)NLAYER*DMODEL*DMODEL];
__device__ __half g_wf[(size_t)NLAYER*DMODEL*FFDIM];
__device__ __half g_wp[(size_t)NLAYER*FFDIM*DMODEL];
__device__ __half g_we[(size_t)VOCAB*DMODEL];

__device__ __forceinline__ uint32_t smem_u32(const void* p){
    uint32_t a;
    asm("{ .reg .u64 t; cvta.to.shared.u64 t, %1; cvt.u32.u64 %0, t; }" : "=r"(a) : "l"(p));
    return a;
}
#define LDSM4(r0,r1,r2,r3,a) asm volatile("ldmatrix.sync.aligned.m8n8.x4.shared.b16 {%0,%1,%2,%3},[%4];":"=r"(r0),"=r"(r1),"=r"(r2),"=r"(r3):"r"(a))
#define MMA_F16(c,a,b) asm volatile( \
    "mma.sync.aligned.m16n8k16.row.col.f32.f16.f16.f32 {%0,%1,%2,%3},{%4,%5,%6,%7},{%8,%9},{%0,%1,%2,%3};" \
    :"+f"((c)[0]),"+f"((c)[1]),"+f"((c)[2]),"+f"((c)[3]) \
    :"r"((a)[0]),"r"((a)[1]),"r"((a)[2]),"r"((a)[3]),"r"((b)[0]),"r"((b)[1]))
#define CPASYNC16(sa,gp) asm volatile("cp.async.cg.shared.global [%0],[%1],16;"::"r"(sa),"l"(gp))
#define CPCOMMIT() asm volatile("cp.async.commit_group;":::"memory")
#define CPWAIT0()  asm volatile("cp.async.wait_group 0;":::"memory")

__device__ __forceinline__ float gelu_f(float x){
    float x3=x*x*x;
    return 0.5f*x*(1.f+tanhf(0.7978845608028654f*(x+0.044715f*x3)));
}
__device__ __forceinline__ uint32_t pack2h(__half a, __half b){
    return ((uint32_t)__half_as_ushort(b)<<16)|__half_as_ushort(a);
}

__global__ __launch_bounds__(256) void embed_kernel(
    const int* __restrict__ idx, const float* __restrict__ wte,
    const float* __restrict__ wpe, float* __restrict__ x)
{
    int i=blockIdx.x*256+threadIdx.x, tok=i>>8, c=i&255, t=tok&(SEQ-1);
    int id=idx[tok];
    float4 a=((const float4*)(wte+(size_t)id*DMODEL))[c];
    float4 p=((const float4*)(wpe+(size_t)t*DMODEL))[c];
    a.x+=p.x; a.y+=p.y; a.z+=p.z; a.w+=p.w;
    ((float4*)x)[i]=a;
}

__global__ __launch_bounds__(256) void ln_kernel(
    const float* __restrict__ x, const float* __restrict__ w, const float* __restrict__ b,
    __half* __restrict__ oh)
{
    int row=blockIdx.x, tid=threadIdx.x;
    float4 v=((const float4*)(x+(size_t)row*DMODEL))[tid];
    float s=v.x+v.y+v.z+v.w, sq=v.x*v.x+v.y*v.y+v.z*v.z+v.w*v.w;
    #pragma unroll
    for(int o=16;o>0;o>>=1){ s+=__shfl_xor_sync(~0u,s,o); sq+=__shfl_xor_sync(~0u,sq,o); }
    __shared__ float ss[8],sqs[8];
    if((tid&31)==0){ ss[tid>>5]=s; sqs[tid>>5]=sq; }
    __syncthreads();
    float st=0,sqt=0;
    #pragma unroll
    for(int i=0;i<8;i++){ st+=ss[i]; sqt+=sqs[i]; }
    float mean=st*(1.f/DMODEL), var=sqt*(1.f/DMODEL)-mean*mean, inv=rsqrtf(var+1e-5f);
    float4 wv=((const float4*)w)[tid], bv=((const float4*)b)[tid];
    float o0=(v.x-mean)*inv*wv.x+bv.x, o1=(v.y-mean)*inv*wv.y+bv.y;
    float o2=(v.z-mean)*inv*wv.z+bv.z, o3=(v.w-mean)*inv*wv.w+bv.w;
    size_t base=(size_t)row*DMODEL+tid*4;
    *(uint2*)(oh+base)=make_uint2(
        pack2h(__float2half(o0),__float2half(o1)),
        pack2h(__float2half(o2),__float2half(o3)));
}

// W[K][N] (layer l) -> fp16 [N][K]
__global__ void wconv_t(const float* __restrict__ W, __half* __restrict__ O, int K, int N)
{
    __shared__ float t[32][33];
    int l=blockIdx.z;
    const float* Wl=W+(size_t)l*K*N;
    __half* Ol=O+(size_t)l*K*N;
    int n0=blockIdx.x*32, k0=blockIdx.y*32, tx=threadIdx.x, ty=threadIdx.y;
    #pragma unroll
    for(int i=0;i<4;i++) t[ty+8*i][tx]=Wl[(size_t)(k0+ty+8*i)*N+n0+tx];
    __syncthreads();
    #pragma unroll
    for(int i=0;i<4;i++)
        Ol[(size_t)(n0+ty+8*i)*K+k0+tx]=__float2half(t[tx][ty+8*i]);
}

__global__ __launch_bounds__(256) void wte_conv(
    const float* __restrict__ w, __half* __restrict__ o)
{
    size_t base=(size_t)blockIdx.x*DMODEL+threadIdx.x*4;
    float4 v=*(const float4*)(w+base);
    *(uint2*)(o+base)=make_uint2(
        pack2h(__float2half(v.x),__float2half(v.y)),
        pack2h(__float2half(v.z),__float2half(v.w)));
}

// ---- single-pass fp16 GEMM: C = A * B^T, both fp16 ----------------------
// act 0: bias->f32  1: bias+res->f32  2: bias+gelu->fp16  3: plain guarded f32
// act 4: bias->fp16 with 0.125 scale on cols<DMODEL (qkv output)
#define GST   40
#define SLABB (128*GST*2)
#define GSMEM4 (4*SLABB)
__global__ __launch_bounds__(256,2) void gemm_mma(
    const __half* __restrict__ A, const __half* __restrict__ B,
    const float* __restrict__ bias, const float* __restrict__ res,
    float* __restrict__ Cf, __half* __restrict__ Ch,
    int N, int K, int act)
{
    extern __shared__ __half sm2[];
    const uint32_t smA = smem_u32(sm2);
    const uint32_t smB = smA + 2*SLABB;
    const int tid=threadIdx.x, wid=tid>>5, lane=tid&31;
    const int bm=blockIdx.x*128, bn=blockIdx.y*128;
    const int wm=(wid&3)*32, wn=(wid>>2)*64;
    const int row2=tid>>2, ch=tid&3;

    float acc[2][8][4];
    #pragma unroll
    for(int i=0;i<2;i++)
        #pragma unroll
        for(int j=0;j<8;j++)
            #pragma unroll
            for(int k=0;k<4;k++) acc[i][j][k]=0.f;

    const uint32_t a_base  = smA + (uint32_t)(((wm+(lane&15))*GST + (lane>>4)*8)*2);
    const uint32_t b4_base = smB + (uint32_t)(((wn+(lane&7)+((lane>>4)&1)*8)*GST + ((lane>>3)&1)*8)*2);
    const int KS = K>>5;

    auto load_stage=[&](int c,int buf){
        const size_t gk=(size_t)c*32 + ch*8;
        #pragma unroll
        for(int hf=0;hf<2;hf++){
            int r=row2+hf*64;
            uint32_t sa = smA + buf*SLABB + (uint32_t)((r*GST+ch*8)*2);
            CPASYNC16(sa, A+(size_t)(bm+r)*K+gk);
            int gn=bn+r; size_t gs=(gn<N)?(size_t)gn:0;
            uint32_t sb = smB + buf*SLABB + (uint32_t)((r*GST+ch*8)*2);
            CPASYNC16(sb, B+gs*K+gk);
        }
    };

    load_stage(0,0); CPCOMMIT(); CPWAIT0();
    __syncthreads();

    for(int c=0;c<KS;c++){
        const int buf=c&1;
        if(c+1<KS){ load_stage(c+1,buf^1); CPCOMMIT(); }
        const uint32_t ab=a_base+buf*SLABB, bb=b4_base+buf*SLABB;
        #pragma unroll
        for(int ks=0;ks<2;ks++){
            uint32_t Ah[2][4],Bh[8][2];
            #pragma unroll
            for(int mt=0;mt<2;mt++){
                uint32_t ad=ab+mt*(16*GST*2)+ks*32;
                LDSM4(Ah[mt][0],Ah[mt][1],Ah[mt][2],Ah[mt][3], ad);
            }
            #pragma unroll
            for(int np=0;np<4;np++){
                uint32_t bd=bb+np*(16*GST*2)+ks*32;
                LDSM4(Bh[2*np][0],Bh[2*np][1],Bh[2*np+1][0],Bh[2*np+1][1], bd);
            }
            #pragma unroll
            for(int mt=0;mt<2;mt++)
                #pragma unroll
                for(int nt=0;nt<8;nt++)
                    MMA_F16(acc[mt][nt], Ah[mt], Bh[nt]);
        }
        if(c+1<KS) CPWAIT0();
        __syncthreads();
    }

    const int g=lane>>2, ct=lane&3;
    #pragma unroll
    for(int mt=0;mt<2;mt++){
        #pragma unroll
        for(int nt=0;nt<8;nt++){
            int r0=bm+wm+mt*16+g, r1=r0+8;
            int col=bn+wn+nt*8+ct*2;
            float c0=acc[mt][nt][0], c1=acc[mt][nt][1];
            float c2=acc[mt][nt][2], c3=acc[mt][nt][3];
            if(act==3){
                if(col<N)   Cf[(size_t)r0*N+col]=c0;
                if(col+1<N) Cf[(size_t)r0*N+col+1]=c1;
                if(col<N)   Cf[(size_t)r1*N+col]=c2;
                if(col+1<N) Cf[(size_t)r1*N+col+1]=c3;
            } else {
                float b0=bias[col], b1=bias[col+1];
                c0+=b0; c1+=b1; c2+=b0; c3+=b1;
                if(act==1){
                    float2 q0=*(const float2*)(res+(size_t)r0*N+col);
                    float2 q1=*(const float2*)(res+(size_t)r1*N+col);
                    c0+=q0.x; c1+=q0.y; c2+=q1.x; c3+=q1.y;
                    *(float2*)(Cf+(size_t)r0*N+col)=make_float2(c0,c1);
                    *(float2*)(Cf+(size_t)r1*N+col)=make_float2(c2,c3);
                } else if(act==0){
                    *(float2*)(Cf+(size_t)r0*N+col)=make_float2(c0,c1);
                    *(float2*)(Cf+(size_t)r1*N+col)=make_float2(c2,c3);
                } else if(act==4){
                    float sc=(col<DMODEL)?0.125f:1.f;
                    *(uint32_t*)(Ch+(size_t)r0*N+col)=pack2h(__float2half(c0*sc),__float2half(c1*sc));
                    *(uint32_t*)(Ch+(size_t)r1*N+col)=pack2h(__float2half(c2*sc),__float2half(c3*sc));
                } else { // act==2 gelu -> fp16
                    c0=gelu_f(c0); c1=gelu_f(c1); c2=gelu_f(c2); c3=gelu_f(c3);
                    *(uint32_t*)(Ch+(size_t)r0*N+col)=pack2h(__float2half(c0),__float2half(c1));
                    *(uint32_t*)(Ch+(size_t)r1*N+col)=pack2h(__float2half(c2),__float2half(c3));
                }
            }
        }
    }
}

// ---- fp16 single-pass tensor-core flash attention ------------------------
#define AT_STR 72
#define AT_TILE (64*AT_STR)
#define AT_SMEM (3*AT_TILE*2)
__global__ __launch_bounds__(128) void attn_tc(
    const __half* __restrict__ qkv, __half* __restrict__ y)
{
    extern __shared__ __half sma[];
    __half *Qs=sma, *Ks=sma+AT_TILE, *Vt=sma+2*AT_TILE;
    const int qb=blockIdx.x, h=blockIdx.y, b=blockIdx.z;
    const int tid=threadIdx.x, wid=tid>>5, lane=tid&31;
    const int q0=qb*64;
    const __half* base=qkv+(size_t)b*SEQ*D3;

    #pragma unroll
    for(int i=0;i<4;i++){
        int idx=tid+128*i, r=idx>>3, ch=idx&7;
        uint4 v=*(const uint4*)(base+(size_t)(q0+r)*D3+h*HDIM+ch*8);
        *(uint4*)(Qs+r*AT_STR+ch*8)=v;
    }

    const int g=lane>>2, ct=lane&3;
    float o[8][4];
    #pragma unroll
    for(int nt=0;nt<8;nt++){ o[nt][0]=0.f;o[nt][1]=0.f;o[nt][2]=0.f;o[nt][3]=0.f; }
    float m0=-1e30f,m1=-1e30f,l0=0.f,l1=0.f;

    const uint32_t qa  = smem_u32(Qs) + (uint32_t)(((wid*16+(lane&15))*AT_STR + (lane>>4)*8)*2);
    const uint32_t kb4 = smem_u32(Ks) + (uint32_t)((((lane&7)+((lane>>4)&1)*8)*AT_STR + ((lane>>3)&1)*8)*2);
    const uint32_t vb4 = smem_u32(Vt) + (uint32_t)((((lane&7)+((lane>>4)&1)*8)*AT_STR + ((lane>>3)&1)*8)*2);

    for(int kt=0;kt<=qb;kt++){
        __syncthreads();
        const int ks0=kt*64;
        #pragma unroll
        for(int i=0;i<4;i++){
            int idx=tid+128*i, r=idx>>3, ch=idx&7;
            uint4 v=*(const uint4*)(base+(size_t)(ks0+r)*D3+DMODEL+h*HDIM+ch*8);
            *(uint4*)(Ks+r*AT_STR+ch*8)=v;
        }
        #pragma unroll
        for(int i=0;i<8;i++){
            int idx=tid+128*i, r=idx>>4, c=(idx&15)*4;
            uint2 v=*(const uint2*)(base+(size_t)(ks0+r)*D3+2*DMODEL+h*HDIM+c);
            const __half* pv=(const __half*)&v;
            Vt[(c+0)*AT_STR+r]=pv[0]; Vt[(c+1)*AT_STR+r]=pv[1];
            Vt[(c+2)*AT_STR+r]=pv[2]; Vt[(c+3)*AT_STR+r]=pv[3];
        }
        __syncthreads();

        float S[8][4];
        #pragma unroll
        for(int nt=0;nt<8;nt++){ S[nt][0]=0.f;S[nt][1]=0.f;S[nt][2]=0.f;S[nt][3]=0.f; }
        #pragma unroll
        for(int ks=0;ks<4;ks++){
            uint32_t Aq[4],KF[8][2];
            LDSM4(Aq[0],Aq[1],Aq[2],Aq[3], qa + ks*32);
            #pragma unroll
            for(int np=0;np<4;np++){
                uint32_t kd = kb4 + np*(16*AT_STR*2) + ks*32;
                LDSM4(KF[2*np][0],KF[2*np][1],KF[2*np+1][0],KF[2*np+1][1], kd);
            }
            #pragma unroll
            for(int nt=0;nt<8;nt++) MMA_F16(S[nt], Aq, KF[nt]);
        }
        if(kt==qb){
            const int r0=q0+wid*16+g, r1=r0+8;
            #pragma unroll
            for(int nt=0;nt<8;nt++){
                int c0=ks0+nt*8+ct*2;
                if(c0>r0)   S[nt][0]=-1e30f;
                if(c0+1>r0) S[nt][1]=-1e30f;
                if(c0>r1)   S[nt][2]=-1e30f;
                if(c0+1>r1) S[nt][3]=-1e30f;
            }
        }
        float rm0=-1e30f, rm1=-1e30f;
        #pragma unroll
        for(int nt=0;nt<8;nt++){
            rm0=fmaxf(rm0,fmaxf(S[nt][0],S[nt][1]));
            rm1=fmaxf(rm1,fmaxf(S[nt][2],S[nt][3]));
        }
        rm0=fmaxf(rm0,__shfl_xor_sync(~0u,rm0,1)); rm0=fmaxf(rm0,__shfl_xor_sync(~0u,rm0,2));
        rm1=fmaxf(rm1,__shfl_xor_sync(~0u,rm1,1)); rm1=fmaxf(rm1,__shfl_xor_sync(~0u,rm1,2));
        float mn0=fmaxf(m0,rm0), mn1=fmaxf(m1,rm1);
        float al0=__expf(m0-mn0), al1=__expf(m1-mn1);
        m0=mn0; m1=mn1;
        float rs0=0.f, rs1=0.f;
        uint32_t ph[4][4];
        #pragma unroll
        for(int j=0;j<8;j++){
            float p0=__expf(S[j][0]-mn0), p1=__expf(S[j][1]-mn0);
            float p2=__expf(S[j][2]-mn1), p3=__expf(S[j][3]-mn1);
            rs0+=p0+p1; rs1+=p2+p3;
            ph[j>>1][(j&1)*2]  =pack2h(__float2half(p0),__float2half(p1));
            ph[j>>1][(j&1)*2+1]=pack2h(__float2half(p2),__float2half(p3));
        }
        rs0+=__shfl_xor_sync(~0u,rs0,1); rs0+=__shfl_xor_sync(~0u,rs0,2);
        rs1+=__shfl_xor_sync(~0u,rs1,1); rs1+=__shfl_xor_sync(~0u,rs1,2);
        l0=l0*al0+rs0; l1=l1*al1+rs1;
        #pragma unroll
        for(int nt=0;nt<8;nt++){
            o[nt][0]*=al0; o[nt][1]*=al0; o[nt][2]*=al1; o[nt][3]*=al1;
        }
        #pragma unroll
        for(int kk=0;kk<4;kk++){
            uint32_t VF[8][2];
            #pragma unroll
            for(int np=0;np<4;np++){
                uint32_t vd = vb4 + np*(16*AT_STR*2) + kk*32;
                LDSM4(VF[2*np][0],VF[2*np][1],VF[2*np+1][0],VF[2*np+1][1], vd);
            }
            #pragma unroll
            for(int nt=0;nt<8;nt++) MMA_F16(o[nt], ph[kk], VF[nt]);
        }
    }
    const float i0=1.f/l0, i1=1.f/l1;
    const size_t r0=(size_t)(b*SEQ+q0+wid*16+g), r1=r0+8;
    #pragma unroll
    for(int nt=0;nt<8;nt++){
        int col=h*HDIM+nt*8+ct*2;
        *(uint32_t*)(y+r0*DMODEL+col)=pack2h(__float2half(o[nt][0]*i0),__float2half(o[nt][1]*i0));
        *(uint32_t*)(y+r1*DMODEL+col)=pack2h(__float2half(o[nt][2]*i1),__float2half(o[nt][3]*i1));
    }
}

extern "C" void kernel_launch(void* const* d_in, const int* in_sizes, int n_in,
                              void* d_out, int out_size)
{
    (void)in_sizes;(void)n_in;(void)out_size;
    const int*   idx   =(const int*)  d_in[0];
    const float* wte   =(const float*)d_in[1];
    const float* wpe   =(const float*)d_in[2];
    const float* ln1_w =(const float*)d_in[3];
    const float* ln1_b =(const float*)d_in[4];
    const float* aw    =(const float*)d_in[5];
    const float* ab    =(const float*)d_in[6];
    const float* pw    =(const float*)d_in[7];
    const float* pb    =(const float*)d_in[8];
    const float* ln2_w =(const float*)d_in[9];
    const float* ln2_b =(const float*)d_in[10];
    const float* fw    =(const float*)d_in[11];
    const float* fb    =(const float*)d_in[12];
    const float* ow    =(const float*)d_in[13];
    const float* ob    =(const float*)d_in[14];
    const float* lnf_w =(const float*)d_in[15];
    const float* lnf_b =(const float*)d_in[16];
    float* out=(float*)d_out;

    cudaFuncSetAttribute(attn_tc,  cudaFuncAttributeMaxDynamicSharedMemorySize, AT_SMEM);
    cudaFuncSetAttribute(gemm_mma, cudaFuncAttributeMaxDynamicSharedMemorySize, GSMEM4);

    float *x;
    __half *qkv,*h,*y,*ff;
    __half *wq,*wa,*wf,*wp,*we;
    cudaGetSymbolAddress((void**)&x,g_x);    cudaGetSymbolAddress((void**)&qkv,g_qkv);
    cudaGetSymbolAddress((void**)&h,g_h);    cudaGetSymbolAddress((void**)&y,g_y);
    cudaGetSymbolAddress((void**)&ff,g_ff);
    cudaGetSymbolAddress((void**)&wq,g_wq);  cudaGetSymbolAddress((void**)&wa,g_wa);
    cudaGetSymbolAddress((void**)&wf,g_wf);  cudaGetSymbolAddress((void**)&wp,g_wp);
    cudaGetSymbolAddress((void**)&we,g_we);

    dim3 wb(32,8);
    wconv_t<<<dim3(D3/32,   DMODEL/32, NLAYER), wb>>>(aw, wq, DMODEL, D3);
    wconv_t<<<dim3(DMODEL/32,DMODEL/32,NLAYER), wb>>>(pw, wa, DMODEL, DMODEL);
    wconv_t<<<dim3(FFDIM/32, DMODEL/32,NLAYER), wb>>>(fw, wf, DMODEL, FFDIM);
    wconv_t<<<dim3(DMODEL/32,FFDIM/32, NLAYER), wb>>>(ow, wp, FFDIM, DMODEL);
    wte_conv<<<VOCAB,256>>>(wte, we);

    embed_kernel<<<BTOK*DMODEL/1024,256>>>(idx, wte, wpe, x);

    for(int l=0;l<NLAYER;l++){
        ln_kernel<<<BTOK,256>>>(x, ln1_w+(size_t)l*DMODEL, ln1_b+(size_t)l*DMODEL, h);
        gemm_mma<<<dim3(BTOK/128,D3/128),256,GSMEM4>>>(
            h, wq+(size_t)l*DMODEL*D3,
            ab+(size_t)l*D3, nullptr, nullptr, qkv, D3, DMODEL, 4);
        attn_tc<<<dim3(SEQ/64,NHEAD,BATCH),128,AT_SMEM>>>(qkv, y);
        gemm_mma<<<dim3(BTOK/128,DMODEL/128),256,GSMEM4>>>(
            y, wa+(size_t)l*DMODEL*DMODEL,
            pb+(size_t)l*DMODEL, x, x, nullptr, DMODEL, DMODEL, 1);
        ln_kernel<<<BTOK,256>>>(x, ln2_w+(size_t)l*DMODEL, ln2_b+(size_t)l*DMODEL, h);
        gemm_mma<<<dim3(BTOK/128,FFDIM/128),256,GSMEM4>>>(
            h, wf+(size_t)l*DMODEL*FFDIM,
            fb+(size_t)l*FFDIM, nullptr, nullptr, ff, FFDIM, DMODEL, 2);
        gemm_mma<<<dim3(BTOK/128,DMODEL/128),256,GSMEM4>>>(
            ff, wp+(size_t)l*FFDIM*DMODEL,
            ob+(size_t)l*DMODEL, x, x, nullptr, DMODEL, FFDIM, 1);
    }
    ln_kernel<<<BTOK,256>>>(x, lnf_w, lnf_b, h);
    gemm_mma<<<dim3(BTOK/128,(VOCAB+127)/128),256,GSMEM4>>>(
        h, we, nullptr, nullptr, out, nullptr, VOCAB, DMODEL, 3);
}